// round 6
// baseline (speedup 1.0000x reference)
#include <cuda_runtime.h>
#include <cuda_bf16.h>
#include <mma.h>
#include <cstdint>

using namespace nvcuda;

#define N_NODES 100000
#define N_EDGES 1600000
#define T_STEPS 12

// ----------------- static device scratch -----------------
__device__ float g_agg[(size_t)N_NODES * 128];
__device__ float g_h0 [(size_t)N_NODES * 128];
__device__ float g_h1 [(size_t)N_NODES * 128];
__device__ float g_hA [(size_t)N_NODES * 128];
__device__ float g_hB [(size_t)N_NODES * 128];
__device__ float g_zc [(size_t)N_NODES * 64];
__device__ float g_Wc0t[128 * 128];   // [N=128, K=128] = [Wn0 | Ws0]^T  (K-major)
__device__ float g_Wc1t[128 * 256];   // [N=128, K=256] = [Wn1 | Ws1]^T
__device__ float g_Wqt [512 * 256];   // [N=512 gate-quads, K=256]
__device__ float g_cW1t[64 * 128];    // [N=64, K=128]
__device__ float g_bq [512];
__device__ int   g_cnt   [N_NODES];
__device__ int   g_rowptr[N_NODES + 1];
__device__ int   g_cur   [N_NODES];
__device__ int   g_colidx[N_EDGES];

__device__ __forceinline__ float sigf(float x) { return 1.f / (1.f + expf(-x)); }

// store float4 as tf32-truncated floats (RN)
__device__ __forceinline__ void sts4_tf32(float* p, float4 v) {
    uint32_t r0, r1, r2, r3;
    asm("cvt.rn.tf32.f32 %0, %1;" : "=r"(r0) : "f"(v.x));
    asm("cvt.rn.tf32.f32 %0, %1;" : "=r"(r1) : "f"(v.y));
    asm("cvt.rn.tf32.f32 %0, %1;" : "=r"(r2) : "f"(v.z));
    asm("cvt.rn.tf32.f32 %0, %1;" : "=r"(r3) : "f"(v.w));
    *(uint4*)p = make_uint4(r0, r1, r2, r3);
}

// ----------------- wmma tf32 GEMM, double-buffered, fused epilogues -----------------
// D[row, jbase+c] = epi( A1[row,:K1]@Bt[jbase+c,:K1]^T + A2[row,:K2]@Bt[...,K1:]^T )
// Bt is [Ntot x Ktot] K-major. K consumed in chunks of 32, ping-pong smem buffers.
// EPI 0: bias+LayerNorm+ReLU            (BM=128, BN=128, out stride 128)
// EPI 1: bias+LayerNorm+ReLU+residual   (BM=128, BN=128)
// EPI 2: GRU gate-quad update           (BM=128, BN=128, grid.y=4, res=h_prev)
// EPI 3: bias+ReLU                      (BM=128, BN=64, out stride 64)
template <int BM, int BN, int WR, int WC, int EPI>
__global__ void __launch_bounds__(256) k_wmma(
    const float* __restrict__ A1, int K1,
    const float* __restrict__ A2, int K2,
    const float* __restrict__ Bt, int Ktot,
    const float* __restrict__ bias,
    const float* __restrict__ gamma, const float* __restrict__ beta,
    const float* __restrict__ res,
    float* __restrict__ out, int n)
{
    constexpr int LDA = 40;            // 160B rows (32B-aligned fragment ptrs)
    constexpr int LDB = 40;
    constexpr int LDC = BN + 8;
    constexpr int ASZ = BM * LDA;      // floats per A buffer
    constexpr int BSZ = BN * LDB;
    constexpr int MI = BM / WR / 16;   // row frags per warp
    constexpr int NI = BN / WC / 16;   // col frags per warp
    constexpr int AIT = BM * 8 / 256;  // float4 stage iters (A)
    constexpr int BIT = BN * 8 / 256;  // float4 stage iters (B)
    extern __shared__ __align__(32) float smem[];
    float* Cs = smem;

    const int tid = threadIdx.x;
    const int wid = tid >> 5;
    const int wr = wid / WC, wc = wid % WC;
    const int row0 = blockIdx.x * BM;
    const int jbase = blockIdx.y * BN;

    wmma::fragment<wmma::accumulator, 16, 16, 8, float> acc[MI][NI];
#pragma unroll
    for (int mi = 0; mi < MI; mi++)
#pragma unroll
        for (int ni = 0; ni < NI; ni++) wmma::fill_fragment(acc[mi][ni], 0.f);

    const int nc = Ktot / 32;
    float4 pa[AIT], pb[BIT];

    auto ldg_chunk = [&](int c) {
        int kg = c * 32;
        const float* Asrc; int Kph, koff;
        if (kg < K1) { Asrc = A1; Kph = K1; koff = kg; }
        else         { Asrc = A2; Kph = K2; koff = kg - K1; }
#pragma unroll
        for (int it = 0; it < AIT; it++) {
            int idx = it * 256 + tid;
            int r = idx >> 3, q = idx & 7;
            int grow = row0 + r;
            pa[it] = (grow < n) ? *(const float4*)(Asrc + (size_t)grow * Kph + koff + q * 4)
                                : make_float4(0.f, 0.f, 0.f, 0.f);
        }
#pragma unroll
        for (int it = 0; it < BIT; it++) {
            int idx = it * 256 + tid;
            int r = idx >> 3, q = idx & 7;
            pb[it] = *(const float4*)(Bt + (size_t)(jbase + r) * Ktot + kg + q * 4);
        }
    };
    auto sts_chunk = [&](int s) {
        float* As = smem + s * ASZ;
        float* Bs = smem + 2 * ASZ + s * BSZ;
#pragma unroll
        for (int it = 0; it < AIT; it++) {
            int idx = it * 256 + tid;
            int r = idx >> 3, q = idx & 7;
            sts4_tf32(&As[r * LDA + q * 4], pa[it]);
        }
#pragma unroll
        for (int it = 0; it < BIT; it++) {
            int idx = it * 256 + tid;
            int r = idx >> 3, q = idx & 7;
            sts4_tf32(&Bs[r * LDB + q * 4], pb[it]);
        }
    };

    // prologue: stage chunk 0 into buffer 0
    ldg_chunk(0);
    sts_chunk(0);
    __syncthreads();

    for (int c = 0; c < nc; c++) {
        int s = c & 1;
        if (c + 1 < nc) ldg_chunk(c + 1);       // global loads overlap MMAs below
        const float* As = smem + s * ASZ;
        const float* Bs = smem + 2 * ASZ + s * BSZ;
#pragma unroll
        for (int ks = 0; ks < 4; ks++) {
            wmma::fragment<wmma::matrix_a, 16, 16, 8, wmma::precision::tf32, wmma::row_major> af[MI];
            wmma::fragment<wmma::matrix_b, 16, 16, 8, wmma::precision::tf32, wmma::col_major> bf[NI];
#pragma unroll
            for (int mi = 0; mi < MI; mi++)
                wmma::load_matrix_sync(af[mi], As + (wr * (BM / WR) + mi * 16) * LDA + ks * 8, LDA);
#pragma unroll
            for (int ni = 0; ni < NI; ni++)
                wmma::load_matrix_sync(bf[ni], Bs + (wc * (BN / WC) + ni * 16) * LDB + ks * 8, LDB);
#pragma unroll
            for (int mi = 0; mi < MI; mi++)
#pragma unroll
                for (int ni = 0; ni < NI; ni++)
                    wmma::mma_sync(acc[mi][ni], af[mi], bf[ni], acc[mi][ni]);
        }
        if (c + 1 < nc) sts_chunk(s ^ 1);
        __syncthreads();
    }

    // spill accumulators to smem C tile
#pragma unroll
    for (int mi = 0; mi < MI; mi++)
#pragma unroll
        for (int ni = 0; ni < NI; ni++)
            wmma::store_matrix_sync(Cs + (wr * (BM / WR) + mi * 16) * LDC + wc * (BN / WC) + ni * 16,
                                    acc[mi][ni], LDC, wmma::mem_row_major);
    __syncthreads();

    // ------------- epilogues (2 threads per row) -------------
    const int r = tid >> 1, seg = tid & 1;
    const int grow = row0 + r;

    if constexpr (EPI == 0 || EPI == 1) {
        // pass 1: stats over this thread's 64 cols, combine with partner lane
        float sum = 0.f, sq = 0.f;
#pragma unroll
        for (int q = 0; q < 16; q++) {
            int cc = seg * 64 + q * 4;
            float4 c4 = *(float4*)&Cs[r * LDC + cc];
            c4.x += __ldg(&bias[cc + 0]); c4.y += __ldg(&bias[cc + 1]);
            c4.z += __ldg(&bias[cc + 2]); c4.w += __ldg(&bias[cc + 3]);
            sum += (c4.x + c4.y) + (c4.z + c4.w);
            sq += c4.x * c4.x + c4.y * c4.y + c4.z * c4.z + c4.w * c4.w;
        }
        sum += __shfl_xor_sync(0xffffffffu, sum, 1);
        sq  += __shfl_xor_sync(0xffffffffu, sq, 1);
        float mean = sum * (1.f / 128.f);
        float var = sq * (1.f / 128.f) - mean * mean;
        float rs = rsqrtf(var + 1e-5f);
        if (grow < n) {
#pragma unroll
            for (int q = 0; q < 16; q++) {
                int cc = seg * 64 + q * 4;
                float4 c4 = *(float4*)&Cs[r * LDC + cc];
                float4 o;
                o.x = fmaxf((c4.x + __ldg(&bias[cc + 0]) - mean) * rs * __ldg(&gamma[cc + 0]) + __ldg(&beta[cc + 0]), 0.f);
                o.y = fmaxf((c4.y + __ldg(&bias[cc + 1]) - mean) * rs * __ldg(&gamma[cc + 1]) + __ldg(&beta[cc + 1]), 0.f);
                o.z = fmaxf((c4.z + __ldg(&bias[cc + 2]) - mean) * rs * __ldg(&gamma[cc + 2]) + __ldg(&beta[cc + 2]), 0.f);
                o.w = fmaxf((c4.w + __ldg(&bias[cc + 3]) - mean) * rs * __ldg(&gamma[cc + 3]) + __ldg(&beta[cc + 3]), 0.f);
                if (EPI == 1) {
                    float4 rv = *(const float4*)(res + (size_t)grow * 128 + cc);
                    o.x += rv.x; o.y += rv.y; o.z += rv.z; o.w += rv.w;
                }
                *(float4*)(out + (size_t)grow * 128 + cc) = o;
            }
        }
    } else if constexpr (EPI == 2) {
        // GRU gate quads: each thread -> 64 gemm cols = 16 quads = 16 h cols
        if (grow < n) {
            int j0 = (jbase >> 2) + seg * 16;
#pragma unroll
            for (int g4 = 0; g4 < 4; g4++) {
                float4 hp = *(const float4*)(res + (size_t)grow * 128 + j0 + g4 * 4);
                float hpv[4] = {hp.x, hp.y, hp.z, hp.w};
                float hv[4];
#pragma unroll
                for (int q = 0; q < 4; q++) {
                    int lc = seg * 64 + (g4 * 4 + q) * 4;
                    int gcol = jbase + lc;
                    float cr = Cs[r * LDC + lc + 0] + __ldg(&bias[gcol + 0]);
                    float cz = Cs[r * LDC + lc + 1] + __ldg(&bias[gcol + 1]);
                    float ci = Cs[r * LDC + lc + 2] + __ldg(&bias[gcol + 2]);
                    float ch = Cs[r * LDC + lc + 3] + __ldg(&bias[gcol + 3]);
                    float rg = sigf(cr);
                    float z = sigf(cz);
                    float ng = tanhf(ci + rg * ch);
                    hv[q] = (1.f - z) * ng + z * hpv[q];
                }
                *(float4*)(out + (size_t)grow * 128 + j0 + g4 * 4) =
                    make_float4(hv[0], hv[1], hv[2], hv[3]);
            }
        }
    } else {  // EPI == 3: bias+relu, BN=64, out stride 64
        if (grow < n) {
#pragma unroll
            for (int q = 0; q < 8; q++) {
                int cc = seg * 32 + q * 4;
                float4 c4 = *(float4*)&Cs[r * LDC + cc];
                float4 o;
                o.x = fmaxf(c4.x + __ldg(&bias[cc + 0]), 0.f);
                o.y = fmaxf(c4.y + __ldg(&bias[cc + 1]), 0.f);
                o.z = fmaxf(c4.z + __ldg(&bias[cc + 2]), 0.f);
                o.w = fmaxf(c4.w + __ldg(&bias[cc + 3]), 0.f);
                *(float4*)(out + (size_t)grow * 64 + cc) = o;
            }
        }
    }
}

// ----------------- CSR build + misc -----------------
__global__ void k_zero_f4(float4* p, int c4) {
    int i = blockIdx.x * blockDim.x + threadIdx.x;
    if (i < c4) p[i] = make_float4(0.f, 0.f, 0.f, 0.f);
}
__global__ void k_zero_i(int* p, int c) {
    int i = blockIdx.x * blockDim.x + threadIdx.x;
    if (i < c) p[i] = 0;
}
__global__ void k_hist(const int* __restrict__ dst, int e, int* __restrict__ cnt) {
    int i = blockIdx.x * blockDim.x + threadIdx.x;
    if (i < e) atomicAdd(&cnt[dst[i]], 1);
}
__global__ void k_copy_i(const int* __restrict__ a, int* __restrict__ b, int c) {
    int i = blockIdx.x * blockDim.x + threadIdx.x;
    if (i < c) b[i] = a[i];
}
__global__ void k_fill(const int* __restrict__ src, const int* __restrict__ dst, int e,
                       int* __restrict__ cur, int* __restrict__ colidx) {
    int i = blockIdx.x * blockDim.x + threadIdx.x;
    if (i < e) {
        int p = atomicAdd(&cur[dst[i]], 1);
        colidx[p] = src[i];
    }
}
__global__ void k_sortseg(const int* __restrict__ rp, int* __restrict__ ci, int n) {
    int v = blockIdx.x * blockDim.x + threadIdx.x;
    if (v >= n) return;
    int s = rp[v], e = rp[v + 1];
    for (int i = s + 1; i < e; i++) {
        int key = ci[i];
        int j = i - 1;
        while (j >= s && ci[j] > key) { ci[j + 1] = ci[j]; j--; }
        ci[j + 1] = key;
    }
}
__global__ void k_scan(const int* __restrict__ cnt, int* __restrict__ rowptr, int n) {
    __shared__ int wsums[32];
    __shared__ int s_carry;
    int tid = threadIdx.x;
    int lane = tid & 31, wid = tid >> 5;
    if (tid == 0) s_carry = 0;
    __syncthreads();
    for (int base = 0; base < n; base += 1024) {
        int i = base + tid;
        int v = (i < n) ? cnt[i] : 0;
        int x = v;
#pragma unroll
        for (int o = 1; o < 32; o <<= 1) {
            int t = __shfl_up_sync(0xffffffffu, x, o);
            if (lane >= o) x += t;
        }
        if (lane == 31) wsums[wid] = x;
        __syncthreads();
        if (tid < 32) {
            int s = wsums[tid];
#pragma unroll
            for (int o = 1; o < 32; o <<= 1) {
                int t = __shfl_up_sync(0xffffffffu, s, o);
                if (tid >= o) s += t;
            }
            wsums[tid] = s;
        }
        __syncthreads();
        int incl = x + ((wid > 0) ? wsums[wid - 1] : 0);
        int excl = s_carry + incl - v;
        if (i < n) rowptr[i] = excl;
        int blocktot = wsums[31];
        __syncthreads();
        if (tid == 0) s_carry += blocktot;
        __syncthreads();
    }
    if (tid == 0) rowptr[n] = s_carry;
}

// ----------------- weight pre-transpose kernels -----------------
__global__ void k_prep_c0(const float* __restrict__ Wn, const float* __restrict__ Ws,
                          float* __restrict__ o) {
    int idx = blockIdx.x * blockDim.x + threadIdx.x;
    if (idx >= 128 * 128) return;
    int nn = idx >> 7, k = idx & 127;
    o[idx] = (k < 64) ? Wn[k * 128 + nn] : Ws[(k - 64) * 128 + nn];
}
__global__ void k_prep_c1(const float* __restrict__ Wn, const float* __restrict__ Ws,
                          float* __restrict__ o) {
    int idx = blockIdx.x * blockDim.x + threadIdx.x;
    if (idx >= 128 * 256) return;
    int nn = idx >> 8, k = idx & 255;
    o[idx] = (k < 128) ? Wn[k * 128 + nn] : Ws[(k - 128) * 128 + nn];
}
__global__ void k_prep_qt(const float* __restrict__ Wih, const float* __restrict__ Whh,
                          const float* __restrict__ bih, const float* __restrict__ bhh,
                          float* __restrict__ o, float* __restrict__ bq) {
    int idx = blockIdx.x * blockDim.x + threadIdx.x;
    if (idx >= 512 * 256) return;
    int c = idx >> 8, k = idx & 255;
    int j = c >> 2, g = c & 3;
    float w = 0.f;
    if (k < 128) {
        if (g == 0)      w = Wih[j * 128 + k];
        else if (g == 1) w = Wih[(128 + j) * 128 + k];
        else if (g == 2) w = Wih[(256 + j) * 128 + k];
    } else {
        int kk = k - 128;
        if (g == 0)      w = Whh[j * 128 + kk];
        else if (g == 1) w = Whh[(128 + j) * 128 + kk];
        else if (g == 3) w = Whh[(256 + j) * 128 + kk];
    }
    o[idx] = w;
    if (idx < 512) {
        int jj = idx >> 2, gg = idx & 3;
        bq[idx] = (gg == 0) ? bih[jj] + bhh[jj]
                : (gg == 1) ? bih[128 + jj] + bhh[128 + jj]
                : (gg == 2) ? bih[256 + jj]
                            : bhh[256 + jj];
    }
}
__global__ void k_prep_cls(const float* __restrict__ W, float* __restrict__ o) {
    int idx = blockIdx.x * blockDim.x + threadIdx.x;
    if (idx >= 64 * 128) return;
    int oo = idx >> 7, k = idx & 127;
    o[idx] = W[k * 64 + oo];
}

// ----------------- mean aggregation (warp per node) -----------------
__global__ void __launch_bounds__(256) k_agg64(const float* __restrict__ x, float* __restrict__ out,
                                               const int* __restrict__ rp, const int* __restrict__ ci, int n) {
    int w = (blockIdx.x * blockDim.x + threadIdx.x) >> 5;
    if (w >= n) return;
    int lane = threadIdx.x & 31;
    int s0 = rp[w], s1 = rp[w + 1];
    float ax = 0.f, ay = 0.f;
    int e = s0;
    for (; e + 4 <= s1; e += 4) {
        int i0 = ci[e], i1 = ci[e + 1], i2 = ci[e + 2], i3 = ci[e + 3];
        float2 v0 = *(const float2*)(x + (size_t)i0 * 64 + lane * 2);
        float2 v1 = *(const float2*)(x + (size_t)i1 * 64 + lane * 2);
        float2 v2 = *(const float2*)(x + (size_t)i2 * 64 + lane * 2);
        float2 v3 = *(const float2*)(x + (size_t)i3 * 64 + lane * 2);
        ax += (v0.x + v1.x) + (v2.x + v3.x);
        ay += (v0.y + v1.y) + (v2.y + v3.y);
    }
    for (; e < s1; e++) {
        int i0 = ci[e];
        float2 v0 = *(const float2*)(x + (size_t)i0 * 64 + lane * 2);
        ax += v0.x; ay += v0.y;
    }
    int d = s1 - s0; if (d < 1) d = 1;
    float inv = 1.f / (float)d;
    *(float2*)(out + (size_t)w * 64 + lane * 2) = make_float2(ax * inv, ay * inv);
}
__global__ void __launch_bounds__(256) k_agg128(const float* __restrict__ x, float* __restrict__ out,
                                                const int* __restrict__ rp, const int* __restrict__ ci, int n) {
    int w = (blockIdx.x * blockDim.x + threadIdx.x) >> 5;
    if (w >= n) return;
    int lane = threadIdx.x & 31;
    int s0 = rp[w], s1 = rp[w + 1];
    float4 acc = make_float4(0.f, 0.f, 0.f, 0.f);
    int e = s0;
    for (; e + 4 <= s1; e += 4) {
        int i0 = ci[e], i1 = ci[e + 1], i2 = ci[e + 2], i3 = ci[e + 3];
        float4 v0 = *(const float4*)(x + (size_t)i0 * 128 + lane * 4);
        float4 v1 = *(const float4*)(x + (size_t)i1 * 128 + lane * 4);
        float4 v2 = *(const float4*)(x + (size_t)i2 * 128 + lane * 4);
        float4 v3 = *(const float4*)(x + (size_t)i3 * 128 + lane * 4);
        acc.x += (v0.x + v1.x) + (v2.x + v3.x);
        acc.y += (v0.y + v1.y) + (v2.y + v3.y);
        acc.z += (v0.z + v1.z) + (v2.z + v3.z);
        acc.w += (v0.w + v1.w) + (v2.w + v3.w);
    }
    for (; e < s1; e++) {
        int i0 = ci[e];
        float4 v0 = *(const float4*)(x + (size_t)i0 * 128 + lane * 4);
        acc.x += v0.x; acc.y += v0.y; acc.z += v0.z; acc.w += v0.w;
    }
    int d = s1 - s0; if (d < 1) d = 1;
    float inv = 1.f / (float)d;
    *(float4*)(out + (size_t)w * 128 + lane * 4) =
        make_float4(acc.x * inv, acc.y * inv, acc.z * inv, acc.w * inv);
}

// final logits: warp per row, zc[64] @ W2[64,2] + b2
__global__ void __launch_bounds__(256) k_logits(const float* __restrict__ zc,
                                                const float* __restrict__ W2,
                                                const float* __restrict__ b2,
                                                float* __restrict__ out, int n) {
    int w = (blockIdx.x * blockDim.x + threadIdx.x) >> 5;
    if (w >= n) return;
    int lane = threadIdx.x & 31;
    float z0 = zc[(size_t)w * 64 + lane];
    float z1 = zc[(size_t)w * 64 + 32 + lane];
    float a0 = z0 * W2[lane * 2 + 0] + z1 * W2[(lane + 32) * 2 + 0];
    float a1 = z0 * W2[lane * 2 + 1] + z1 * W2[(lane + 32) * 2 + 1];
#pragma unroll
    for (int o = 16; o > 0; o >>= 1) {
        a0 += __shfl_xor_sync(0xffffffffu, a0, o);
        a1 += __shfl_xor_sync(0xffffffffu, a1, o);
    }
    if (lane == 0) {
        out[(size_t)w * 2 + 0] = a0 + b2[0];
        out[(size_t)w * 2 + 1] = a1 + b2[1];
    }
}

// ----------------- host launch -----------------
extern "C" void kernel_launch(void* const* d_in, const int* in_sizes, int n_in,
                              void* d_out, int out_size) {
    const int N = N_NODES, E = N_EDGES;

    const float* x_seq = nullptr;
    const int* eidx = nullptr;
    const float* Wt[18];
    int wi = 0;
    for (int i = 0; i < n_in; i++) {
        if (in_sizes[i] == 2 * E) eidx = (const int*)d_in[i];
        else if (in_sizes[i] == T_STEPS * N * 64) x_seq = (const float*)d_in[i];
        else if (wi < 18) Wt[wi++] = (const float*)d_in[i];
    }
    const float *Wn0 = Wt[0], *Ws0 = Wt[1], *b0 = Wt[2], *g0 = Wt[3], *be0 = Wt[4];
    const float *Wn1 = Wt[5], *Ws1 = Wt[6], *b1 = Wt[7], *g1 = Wt[8], *be1 = Wt[9];
    const float *gWih = Wt[10], *gWhh = Wt[11], *gbih = Wt[12], *gbhh = Wt[13];
    const float *cW1 = Wt[14], *cb1 = Wt[15], *cW2 = Wt[16], *cb2 = Wt[17];

    float *agg, *h0, *h1, *hA, *hB, *zc, *Wc0t, *Wc1t, *Wqt, *cW1t, *bq;
    int *cnt, *rp, *cur, *ci;
    cudaGetSymbolAddress((void**)&agg, g_agg);
    cudaGetSymbolAddress((void**)&h0, g_h0);
    cudaGetSymbolAddress((void**)&h1, g_h1);
    cudaGetSymbolAddress((void**)&hA, g_hA);
    cudaGetSymbolAddress((void**)&hB, g_hB);
    cudaGetSymbolAddress((void**)&zc, g_zc);
    cudaGetSymbolAddress((void**)&Wc0t, g_Wc0t);
    cudaGetSymbolAddress((void**)&Wc1t, g_Wc1t);
    cudaGetSymbolAddress((void**)&Wqt, g_Wqt);
    cudaGetSymbolAddress((void**)&cW1t, g_cW1t);
    cudaGetSymbolAddress((void**)&bq, g_bq);
    cudaGetSymbolAddress((void**)&cnt, g_cnt);
    cudaGetSymbolAddress((void**)&rp, g_rowptr);
    cudaGetSymbolAddress((void**)&cur, g_cur);
    cudaGetSymbolAddress((void**)&ci, g_colidx);

    const int* src = eidx;
    const int* dst = eidx + E;

    // dynamic smem: max(double-buffered stage, epilogue C tile), in bytes
    // EPI0/1/2 (BM=128,BN=128): stage = 2*(128*40 + 128*40)*4 = 81920 ; Cs = 128*136*4 = 69632
    // EPI3     (BM=128,BN=64):  stage = 2*(128*40 + 64*40)*4  = 61440 ; Cs = 128*72*4  = 36864
    const int SM_A = 81920;
    const int SM_B = 61440;
    cudaFuncSetAttribute((const void*)k_wmma<128, 128, 4, 2, 0>, cudaFuncAttributeMaxDynamicSharedMemorySize, SM_A);
    cudaFuncSetAttribute((const void*)k_wmma<128, 128, 4, 2, 1>, cudaFuncAttributeMaxDynamicSharedMemorySize, SM_A);
    cudaFuncSetAttribute((const void*)k_wmma<128, 128, 4, 2, 2>, cudaFuncAttributeMaxDynamicSharedMemorySize, SM_A);
    cudaFuncSetAttribute((const void*)k_wmma<128, 64, 4, 2, 3>,  cudaFuncAttributeMaxDynamicSharedMemorySize, SM_B);

    // ---- build CSR (deterministic after per-segment sort) ----
    k_zero_i<<<(N + 255) / 256, 256>>>(cnt, N);
    k_hist<<<(E + 255) / 256, 256>>>(dst, E, cnt);
    k_scan<<<1, 1024>>>(cnt, rp, N);
    k_copy_i<<<(N + 255) / 256, 256>>>(rp, cur, N);
    k_fill<<<(E + 255) / 256, 256>>>(src, dst, E, cur, ci);
    k_sortseg<<<(N + 255) / 256, 256>>>(rp, ci, N);

    // ---- init GRU state + pre-transposed weights ----
    k_zero_f4<<<(N * 128 / 4 + 255) / 256, 256>>>((float4*)hA, N * 128 / 4);
    k_prep_c0<<<(128 * 128 + 255) / 256, 256>>>(Wn0, Ws0, Wc0t);
    k_prep_c1<<<(128 * 256 + 255) / 256, 256>>>(Wn1, Ws1, Wc1t);
    k_prep_qt<<<(512 * 256 + 255) / 256, 256>>>(gWih, gWhh, gbih, gbhh, Wqt, bq);
    k_prep_cls<<<(64 * 128 + 255) / 256, 256>>>(cW1, cW1t);

    const int GRID = (N + 127) / 128;   // 782
    const int AGG_GRID = (N + 7) / 8;

    float* hprev = hA;
    float* hnext = hB;
    for (int t = 0; t < T_STEPS; t++) {
        const float* xt = x_seq + (size_t)t * N * 64;
        // SAGE layer 0: LN+ReLU
        k_agg64<<<AGG_GRID, 256>>>(xt, agg, rp, ci, N);
        k_wmma<128, 128, 4, 2, 0><<<dim3(GRID, 1), 256, SM_A>>>(
            agg, 64, xt, 64, Wc0t, 128, b0, g0, be0, nullptr, h0, N);
        // SAGE layer 1: LN+ReLU + residual(h0)
        k_agg128<<<AGG_GRID, 256>>>(h0, agg, rp, ci, N);
        k_wmma<128, 128, 4, 2, 1><<<dim3(GRID, 1), 256, SM_A>>>(
            agg, 128, h0, 128, Wc1t, 256, b1, g1, be1, h0, h1, N);
        // GRU step (gate-quad epilogue), Ntot=512 in 4 col-blocks
        k_wmma<128, 128, 4, 2, 2><<<dim3(GRID, 4), 256, SM_A>>>(
            h1, 128, hprev, 128, Wqt, 256, bq, nullptr, nullptr, hprev, hnext, N);
        float* tmp = hprev; hprev = hnext; hnext = tmp;
    }
    // classifier
    k_wmma<128, 64, 4, 2, 3><<<dim3(GRID, 1), 256, SM_B>>>(
        hprev, 128, nullptr, 0, cW1t, 128, cb1, nullptr, nullptr, nullptr, zc, N);
    k_logits<<<AGG_GRID, 256>>>(zc, cW2, cb2, (float*)d_out, N);
}

// round 7
// speedup vs baseline: 1.1820x; 1.1820x over previous
#include <cuda_runtime.h>
#include <cuda_bf16.h>
#include <mma.h>
#include <cstdint>

using namespace nvcuda;

#define N_NODES 100000
#define N_EDGES 1600000
#define T_STEPS 12

// ----------------- static device scratch -----------------
__device__ float g_agg[(size_t)N_NODES * 128];
__device__ float g_h0 [(size_t)N_NODES * 128];
__device__ float g_h1 [(size_t)N_NODES * 128];
__device__ float g_hA [(size_t)N_NODES * 128];
__device__ float g_hB [(size_t)N_NODES * 128];
__device__ float g_zc [(size_t)N_NODES * 64];
__device__ float g_Wc0t[128 * 128];   // [N=128, K=128] = [Wn0 | Ws0]^T  (K-major)
__device__ float g_Wc1t[128 * 256];   // [N=128, K=256] = [Wn1 | Ws1]^T
__device__ float g_Wqt [512 * 256];   // [N=512 gate-quads, K=256]
__device__ float g_cW1t[64 * 128];    // [N=64, K=128]
__device__ float g_bq [512];
__device__ int   g_cnt   [N_NODES];
__device__ int   g_rowptr[N_NODES + 1];
__device__ int   g_cur   [N_NODES];
__device__ int   g_colidx[N_EDGES];

__device__ __forceinline__ float sigf(float x) { return 1.f / (1.f + expf(-x)); }

// store float4 as tf32-truncated floats (RN)
__device__ __forceinline__ void sts4_tf32(float* p, float4 v) {
    uint32_t r0, r1, r2, r3;
    asm("cvt.rn.tf32.f32 %0, %1;" : "=r"(r0) : "f"(v.x));
    asm("cvt.rn.tf32.f32 %0, %1;" : "=r"(r1) : "f"(v.y));
    asm("cvt.rn.tf32.f32 %0, %1;" : "=r"(r2) : "f"(v.z));
    asm("cvt.rn.tf32.f32 %0, %1;" : "=r"(r3) : "f"(v.w));
    *(uint4*)p = make_uint4(r0, r1, r2, r3);
}

// ----------------- wmma tf32 GEMM, pipelined, fused epilogues -----------------
// D[row, jbase+c] = epi( A1[row,:K1]@Bt[jbase+c,:K1]^T + A2[row,:K2]@Bt[...,K1:]^T )
// Bt is [Ntot x Ktot] K-major. K in chunks of 32, ping-pong smem buffers;
// next chunk's LDGs issued before this chunk's MMAs (latency overlap).
// EPI 0: bias+LayerNorm+ReLU            (BM=64, BN=128, out stride 128)
// EPI 1: bias+LayerNorm+ReLU+residual   (BM=64, BN=128)
// EPI 2: GRU gate-quad update           (BM=64, BN=128, grid.y=4, res=h_prev)
// EPI 3: bias+ReLU                      (BM=128, BN=64, out stride 64)
template <int BM, int BN, int WR, int WC, int EPI>
__global__ void __launch_bounds__(256) k_wmma(
    const float* __restrict__ A1, int K1,
    const float* __restrict__ A2, int K2,
    const float* __restrict__ Bt, int Ktot,
    const float* __restrict__ bias,
    const float* __restrict__ gamma, const float* __restrict__ beta,
    const float* __restrict__ res,
    float* __restrict__ out, int n)
{
    constexpr int LDA = 40;            // 160B rows (32B-aligned fragment ptrs)
    constexpr int LDB = 40;
    constexpr int LDC = BN + 8;
    constexpr int ASZ = BM * LDA;
    constexpr int BSZ = BN * LDB;
    constexpr int MI = BM / WR / 16;   // 2
    constexpr int NI = BN / WC / 16;   // 2
    constexpr int AIT = BM * 8 / 256;  // float4 stage iters (A)
    constexpr int BIT = BN * 8 / 256;  // float4 stage iters (B)
    extern __shared__ __align__(32) float smem[];
    float* Cs = smem;

    const int tid = threadIdx.x;
    const int wid = tid >> 5;
    const int wr = wid / WC, wc = wid % WC;
    const int row0 = blockIdx.x * BM;
    const int jbase = blockIdx.y * BN;

    wmma::fragment<wmma::accumulator, 16, 16, 8, float> acc[MI][NI];
#pragma unroll
    for (int mi = 0; mi < MI; mi++)
#pragma unroll
        for (int ni = 0; ni < NI; ni++) wmma::fill_fragment(acc[mi][ni], 0.f);

    const int nc = Ktot / 32;
    float4 pa[AIT], pb[BIT];

    auto ldg_chunk = [&](int c) {
        int kg = c * 32;
        const float* Asrc; int Kph, koff;
        if (kg < K1) { Asrc = A1; Kph = K1; koff = kg; }
        else         { Asrc = A2; Kph = K2; koff = kg - K1; }
#pragma unroll
        for (int it = 0; it < AIT; it++) {
            int idx = it * 256 + tid;
            int r = idx >> 3, q = idx & 7;
            int grow = row0 + r;
            pa[it] = (grow < n) ? *(const float4*)(Asrc + (size_t)grow * Kph + koff + q * 4)
                                : make_float4(0.f, 0.f, 0.f, 0.f);
        }
#pragma unroll
        for (int it = 0; it < BIT; it++) {
            int idx = it * 256 + tid;
            int r = idx >> 3, q = idx & 7;
            pb[it] = *(const float4*)(Bt + (size_t)(jbase + r) * Ktot + kg + q * 4);
        }
    };
    auto sts_chunk = [&](int s) {
        float* As = smem + s * ASZ;
        float* Bs = smem + 2 * ASZ + s * BSZ;
#pragma unroll
        for (int it = 0; it < AIT; it++) {
            int idx = it * 256 + tid;
            int r = idx >> 3, q = idx & 7;
            sts4_tf32(&As[r * LDA + q * 4], pa[it]);
        }
#pragma unroll
        for (int it = 0; it < BIT; it++) {
            int idx = it * 256 + tid;
            int r = idx >> 3, q = idx & 7;
            sts4_tf32(&Bs[r * LDB + q * 4], pb[it]);
        }
    };

    // prologue: stage chunk 0 into buffer 0
    ldg_chunk(0);
    sts_chunk(0);
    __syncthreads();

    for (int c = 0; c < nc; c++) {
        int s = c & 1;
        if (c + 1 < nc) ldg_chunk(c + 1);   // LDGs in flight while MMAs run
        const float* As = smem + s * ASZ;
        const float* Bs = smem + 2 * ASZ + s * BSZ;
#pragma unroll
        for (int ks = 0; ks < 4; ks++) {
            wmma::fragment<wmma::matrix_a, 16, 16, 8, wmma::precision::tf32, wmma::row_major> af[MI];
            wmma::fragment<wmma::matrix_b, 16, 16, 8, wmma::precision::tf32, wmma::col_major> bf[NI];
#pragma unroll
            for (int mi = 0; mi < MI; mi++)
                wmma::load_matrix_sync(af[mi], As + (wr * (BM / WR) + mi * 16) * LDA + ks * 8, LDA);
#pragma unroll
            for (int ni = 0; ni < NI; ni++)
                wmma::load_matrix_sync(bf[ni], Bs + (wc * (BN / WC) + ni * 16) * LDB + ks * 8, LDB);
#pragma unroll
            for (int mi = 0; mi < MI; mi++)
#pragma unroll
                for (int ni = 0; ni < NI; ni++)
                    wmma::mma_sync(acc[mi][ni], af[mi], bf[ni], acc[mi][ni]);
        }
        if (c + 1 < nc) sts_chunk(s ^ 1);
        __syncthreads();
    }

    // spill accumulators to smem C tile
#pragma unroll
    for (int mi = 0; mi < MI; mi++)
#pragma unroll
        for (int ni = 0; ni < NI; ni++)
            wmma::store_matrix_sync(Cs + (wr * (BM / WR) + mi * 16) * LDC + wc * (BN / WC) + ni * 16,
                                    acc[mi][ni], LDC, wmma::mem_row_major);
    __syncthreads();

    // ------------- epilogues (identical numerics to the 10.1ms version) -------------
    if constexpr (EPI == 0 || EPI == 1) {
        // 4 threads per row, 32 cols each; LN over 128 cols
        int r = tid >> 2, seg = tid & 3;
        int grow = row0 + r;
        float v[32];
        float sum = 0.f, sq = 0.f;
#pragma unroll
        for (int q = 0; q < 8; q++) {
            float4 c4 = *(float4*)&Cs[r * LDC + seg * 32 + q * 4];
            float b0v = __ldg(&bias[seg * 32 + q * 4 + 0]);
            float b1v = __ldg(&bias[seg * 32 + q * 4 + 1]);
            float b2v = __ldg(&bias[seg * 32 + q * 4 + 2]);
            float b3v = __ldg(&bias[seg * 32 + q * 4 + 3]);
            v[q * 4 + 0] = c4.x + b0v; v[q * 4 + 1] = c4.y + b1v;
            v[q * 4 + 2] = c4.z + b2v; v[q * 4 + 3] = c4.w + b3v;
#pragma unroll
            for (int u = 0; u < 4; u++) { sum += v[q * 4 + u]; sq += v[q * 4 + u] * v[q * 4 + u]; }
        }
        sum += __shfl_xor_sync(0xffffffffu, sum, 1);
        sq  += __shfl_xor_sync(0xffffffffu, sq, 1);
        sum += __shfl_xor_sync(0xffffffffu, sum, 2);
        sq  += __shfl_xor_sync(0xffffffffu, sq, 2);
        float mean = sum * (1.f / 128.f);
        float var = sq * (1.f / 128.f) - mean * mean;
        float rs = rsqrtf(var + 1e-5f);
        if (grow < n) {
#pragma unroll
            for (int q = 0; q < 8; q++) {
                int cc = seg * 32 + q * 4;
                float4 o;
                o.x = fmaxf((v[q * 4 + 0] - mean) * rs * __ldg(&gamma[cc + 0]) + __ldg(&beta[cc + 0]), 0.f);
                o.y = fmaxf((v[q * 4 + 1] - mean) * rs * __ldg(&gamma[cc + 1]) + __ldg(&beta[cc + 1]), 0.f);
                o.z = fmaxf((v[q * 4 + 2] - mean) * rs * __ldg(&gamma[cc + 2]) + __ldg(&beta[cc + 2]), 0.f);
                o.w = fmaxf((v[q * 4 + 3] - mean) * rs * __ldg(&gamma[cc + 3]) + __ldg(&beta[cc + 3]), 0.f);
                if (EPI == 1) {
                    float4 rv = *(const float4*)(res + (size_t)grow * 128 + cc);
                    o.x += rv.x; o.y += rv.y; o.z += rv.z; o.w += rv.w;
                }
                *(float4*)(out + (size_t)grow * 128 + cc) = o;
            }
        }
    } else if constexpr (EPI == 2) {
        // GRU gate quads: 128 gemm cols -> 32 h cols; 4 threads/row, 8 quads each
        int r = tid >> 2, seg = tid & 3;
        int grow = row0 + r;
        if (grow < n) {
            int lc0 = seg * 32;
            float hv[8];
#pragma unroll
            for (int q = 0; q < 8; q++) {
                int lc = lc0 + q * 4;
                int gcol = jbase + lc;
                float cr = Cs[r * LDC + lc + 0] + __ldg(&bias[gcol + 0]);
                float cz = Cs[r * LDC + lc + 1] + __ldg(&bias[gcol + 1]);
                float ci = Cs[r * LDC + lc + 2] + __ldg(&bias[gcol + 2]);
                float ch = Cs[r * LDC + lc + 3] + __ldg(&bias[gcol + 3]);
                float rg = sigf(cr);
                float z = sigf(cz);
                float ng = tanhf(ci + rg * ch);
                float hp = res[(size_t)grow * 128 + ((jbase + lc0) >> 2) + q];
                hv[q] = (1.f - z) * ng + z * hp;
            }
            int j0 = ((jbase + lc0) >> 2);
            *(float4*)(out + (size_t)grow * 128 + j0) = make_float4(hv[0], hv[1], hv[2], hv[3]);
            *(float4*)(out + (size_t)grow * 128 + j0 + 4) = make_float4(hv[4], hv[5], hv[6], hv[7]);
        }
    } else {  // EPI == 3: bias+relu, BN=64, out stride 64
        int r = tid >> 1, seg = tid & 1;
        int grow = row0 + r;
        if (grow < n) {
#pragma unroll
            for (int q = 0; q < 8; q++) {
                int cc = seg * 32 + q * 4;
                float4 c4 = *(float4*)&Cs[r * LDC + cc];
                float4 o;
                o.x = fmaxf(c4.x + __ldg(&bias[cc + 0]), 0.f);
                o.y = fmaxf(c4.y + __ldg(&bias[cc + 1]), 0.f);
                o.z = fmaxf(c4.z + __ldg(&bias[cc + 2]), 0.f);
                o.w = fmaxf(c4.w + __ldg(&bias[cc + 3]), 0.f);
                *(float4*)(out + (size_t)grow * 64 + cc) = o;
            }
        }
    }
}

// ----------------- CSR build + misc -----------------
__global__ void k_zero_f4(float4* p, int c4) {
    int i = blockIdx.x * blockDim.x + threadIdx.x;
    if (i < c4) p[i] = make_float4(0.f, 0.f, 0.f, 0.f);
}
__global__ void k_zero_i(int* p, int c) {
    int i = blockIdx.x * blockDim.x + threadIdx.x;
    if (i < c) p[i] = 0;
}
__global__ void k_hist(const int* __restrict__ dst, int e, int* __restrict__ cnt) {
    int i = blockIdx.x * blockDim.x + threadIdx.x;
    if (i < e) atomicAdd(&cnt[dst[i]], 1);
}
__global__ void k_copy_i(const int* __restrict__ a, int* __restrict__ b, int c) {
    int i = blockIdx.x * blockDim.x + threadIdx.x;
    if (i < c) b[i] = a[i];
}
__global__ void k_fill(const int* __restrict__ src, const int* __restrict__ dst, int e,
                       int* __restrict__ cur, int* __restrict__ colidx) {
    int i = blockIdx.x * blockDim.x + threadIdx.x;
    if (i < e) {
        int p = atomicAdd(&cur[dst[i]], 1);
        colidx[p] = src[i];
    }
}
__global__ void k_sortseg(const int* __restrict__ rp, int* __restrict__ ci, int n) {
    int v = blockIdx.x * blockDim.x + threadIdx.x;
    if (v >= n) return;
    int s = rp[v], e = rp[v + 1];
    for (int i = s + 1; i < e; i++) {
        int key = ci[i];
        int j = i - 1;
        while (j >= s && ci[j] > key) { ci[j + 1] = ci[j]; j--; }
        ci[j + 1] = key;
    }
}
__global__ void k_scan(const int* __restrict__ cnt, int* __restrict__ rowptr, int n) {
    __shared__ int wsums[32];
    __shared__ int s_carry;
    int tid = threadIdx.x;
    int lane = tid & 31, wid = tid >> 5;
    if (tid == 0) s_carry = 0;
    __syncthreads();
    for (int base = 0; base < n; base += 1024) {
        int i = base + tid;
        int v = (i < n) ? cnt[i] : 0;
        int x = v;
#pragma unroll
        for (int o = 1; o < 32; o <<= 1) {
            int t = __shfl_up_sync(0xffffffffu, x, o);
            if (lane >= o) x += t;
        }
        if (lane == 31) wsums[wid] = x;
        __syncthreads();
        if (tid < 32) {
            int s = wsums[tid];
#pragma unroll
            for (int o = 1; o < 32; o <<= 1) {
                int t = __shfl_up_sync(0xffffffffu, s, o);
                if (tid >= o) s += t;
            }
            wsums[tid] = s;
        }
        __syncthreads();
        int incl = x + ((wid > 0) ? wsums[wid - 1] : 0);
        int excl = s_carry + incl - v;
        if (i < n) rowptr[i] = excl;
        int blocktot = wsums[31];
        __syncthreads();
        if (tid == 0) s_carry += blocktot;
        __syncthreads();
    }
    if (tid == 0) rowptr[n] = s_carry;
}

// ----------------- weight pre-transpose kernels -----------------
__global__ void k_prep_c0(const float* __restrict__ Wn, const float* __restrict__ Ws,
                          float* __restrict__ o) {
    int idx = blockIdx.x * blockDim.x + threadIdx.x;
    if (idx >= 128 * 128) return;
    int nn = idx >> 7, k = idx & 127;
    o[idx] = (k < 64) ? Wn[k * 128 + nn] : Ws[(k - 64) * 128 + nn];
}
__global__ void k_prep_c1(const float* __restrict__ Wn, const float* __restrict__ Ws,
                          float* __restrict__ o) {
    int idx = blockIdx.x * blockDim.x + threadIdx.x;
    if (idx >= 128 * 256) return;
    int nn = idx >> 8, k = idx & 255;
    o[idx] = (k < 128) ? Wn[k * 128 + nn] : Ws[(k - 128) * 128 + nn];
}
__global__ void k_prep_qt(const float* __restrict__ Wih, const float* __restrict__ Whh,
                          const float* __restrict__ bih, const float* __restrict__ bhh,
                          float* __restrict__ o, float* __restrict__ bq) {
    int idx = blockIdx.x * blockDim.x + threadIdx.x;
    if (idx >= 512 * 256) return;
    int c = idx >> 8, k = idx & 255;
    int j = c >> 2, g = c & 3;
    float w = 0.f;
    if (k < 128) {
        if (g == 0)      w = Wih[j * 128 + k];
        else if (g == 1) w = Wih[(128 + j) * 128 + k];
        else if (g == 2) w = Wih[(256 + j) * 128 + k];
    } else {
        int kk = k - 128;
        if (g == 0)      w = Whh[j * 128 + kk];
        else if (g == 1) w = Whh[(128 + j) * 128 + kk];
        else if (g == 3) w = Whh[(256 + j) * 128 + kk];
    }
    o[idx] = w;
    if (idx < 512) {
        int jj = idx >> 2, gg = idx & 3;
        bq[idx] = (gg == 0) ? bih[jj] + bhh[jj]
                : (gg == 1) ? bih[128 + jj] + bhh[128 + jj]
                : (gg == 2) ? bih[256 + jj]
                            : bhh[256 + jj];
    }
}
__global__ void k_prep_cls(const float* __restrict__ W, float* __restrict__ o) {
    int idx = blockIdx.x * blockDim.x + threadIdx.x;
    if (idx >= 64 * 128) return;
    int oo = idx >> 7, k = idx & 127;
    o[idx] = W[k * 64 + oo];
}

// ----------------- mean aggregation (warp per node) -----------------
__global__ void __launch_bounds__(256) k_agg64(const float* __restrict__ x, float* __restrict__ out,
                                               const int* __restrict__ rp, const int* __restrict__ ci, int n) {
    int w = (blockIdx.x * blockDim.x + threadIdx.x) >> 5;
    if (w >= n) return;
    int lane = threadIdx.x & 31;
    int s0 = rp[w], s1 = rp[w + 1];
    float ax = 0.f, ay = 0.f;
    int e = s0;
    for (; e + 4 <= s1; e += 4) {
        int i0 = ci[e], i1 = ci[e + 1], i2 = ci[e + 2], i3 = ci[e + 3];
        float2 v0 = *(const float2*)(x + (size_t)i0 * 64 + lane * 2);
        float2 v1 = *(const float2*)(x + (size_t)i1 * 64 + lane * 2);
        float2 v2 = *(const float2*)(x + (size_t)i2 * 64 + lane * 2);
        float2 v3 = *(const float2*)(x + (size_t)i3 * 64 + lane * 2);
        ax += (v0.x + v1.x) + (v2.x + v3.x);
        ay += (v0.y + v1.y) + (v2.y + v3.y);
    }
    for (; e < s1; e++) {
        int i0 = ci[e];
        float2 v0 = *(const float2*)(x + (size_t)i0 * 64 + lane * 2);
        ax += v0.x; ay += v0.y;
    }
    int d = s1 - s0; if (d < 1) d = 1;
    float inv = 1.f / (float)d;
    *(float2*)(out + (size_t)w * 64 + lane * 2) = make_float2(ax * inv, ay * inv);
}
__global__ void __launch_bounds__(256) k_agg128(const float* __restrict__ x, float* __restrict__ out,
                                                const int* __restrict__ rp, const int* __restrict__ ci, int n) {
    int w = (blockIdx.x * blockDim.x + threadIdx.x) >> 5;
    if (w >= n) return;
    int lane = threadIdx.x & 31;
    int s0 = rp[w], s1 = rp[w + 1];
    float4 acc = make_float4(0.f, 0.f, 0.f, 0.f);
    int e = s0;
    for (; e + 4 <= s1; e += 4) {
        int i0 = ci[e], i1 = ci[e + 1], i2 = ci[e + 2], i3 = ci[e + 3];
        float4 v0 = *(const float4*)(x + (size_t)i0 * 128 + lane * 4);
        float4 v1 = *(const float4*)(x + (size_t)i1 * 128 + lane * 4);
        float4 v2 = *(const float4*)(x + (size_t)i2 * 128 + lane * 4);
        float4 v3 = *(const float4*)(x + (size_t)i3 * 128 + lane * 4);
        acc.x += (v0.x + v1.x) + (v2.x + v3.x);
        acc.y += (v0.y + v1.y) + (v2.y + v3.y);
        acc.z += (v0.z + v1.z) + (v2.z + v3.z);
        acc.w += (v0.w + v1.w) + (v2.w + v3.w);
    }
    for (; e < s1; e++) {
        int i0 = ci[e];
        float4 v0 = *(const float4*)(x + (size_t)i0 * 128 + lane * 4);
        acc.x += v0.x; acc.y += v0.y; acc.z += v0.z; acc.w += v0.w;
    }
    int d = s1 - s0; if (d < 1) d = 1;
    float inv = 1.f / (float)d;
    *(float4*)(out + (size_t)w * 128 + lane * 4) =
        make_float4(acc.x * inv, acc.y * inv, acc.z * inv, acc.w * inv);
}

// final logits: warp per row, zc[64] @ W2[64,2] + b2
__global__ void __launch_bounds__(256) k_logits(const float* __restrict__ zc,
                                                const float* __restrict__ W2,
                                                const float* __restrict__ b2,
                                                float* __restrict__ out, int n) {
    int w = (blockIdx.x * blockDim.x + threadIdx.x) >> 5;
    if (w >= n) return;
    int lane = threadIdx.x & 31;
    float z0 = zc[(size_t)w * 64 + lane];
    float z1 = zc[(size_t)w * 64 + 32 + lane];
    float a0 = z0 * W2[lane * 2 + 0] + z1 * W2[(lane + 32) * 2 + 0];
    float a1 = z0 * W2[lane * 2 + 1] + z1 * W2[(lane + 32) * 2 + 1];
#pragma unroll
    for (int o = 16; o > 0; o >>= 1) {
        a0 += __shfl_xor_sync(0xffffffffu, a0, o);
        a1 += __shfl_xor_sync(0xffffffffu, a1, o);
    }
    if (lane == 0) {
        out[(size_t)w * 2 + 0] = a0 + b2[0];
        out[(size_t)w * 2 + 1] = a1 + b2[1];
    }
}

// ----------------- host launch -----------------
extern "C" void kernel_launch(void* const* d_in, const int* in_sizes, int n_in,
                              void* d_out, int out_size) {
    const int N = N_NODES, E = N_EDGES;

    const float* x_seq = nullptr;
    const int* eidx = nullptr;
    const float* Wt[18];
    int wi = 0;
    for (int i = 0; i < n_in; i++) {
        if (in_sizes[i] == 2 * E) eidx = (const int*)d_in[i];
        else if (in_sizes[i] == T_STEPS * N * 64) x_seq = (const float*)d_in[i];
        else if (wi < 18) Wt[wi++] = (const float*)d_in[i];
    }
    const float *Wn0 = Wt[0], *Ws0 = Wt[1], *b0 = Wt[2], *g0 = Wt[3], *be0 = Wt[4];
    const float *Wn1 = Wt[5], *Ws1 = Wt[6], *b1 = Wt[7], *g1 = Wt[8], *be1 = Wt[9];
    const float *gWih = Wt[10], *gWhh = Wt[11], *gbih = Wt[12], *gbhh = Wt[13];
    const float *cW1 = Wt[14], *cb1 = Wt[15], *cW2 = Wt[16], *cb2 = Wt[17];

    float *agg, *h0, *h1, *hA, *hB, *zc, *Wc0t, *Wc1t, *Wqt, *cW1t, *bq;
    int *cnt, *rp, *cur, *ci;
    cudaGetSymbolAddress((void**)&agg, g_agg);
    cudaGetSymbolAddress((void**)&h0, g_h0);
    cudaGetSymbolAddress((void**)&h1, g_h1);
    cudaGetSymbolAddress((void**)&hA, g_hA);
    cudaGetSymbolAddress((void**)&hB, g_hB);
    cudaGetSymbolAddress((void**)&zc, g_zc);
    cudaGetSymbolAddress((void**)&Wc0t, g_Wc0t);
    cudaGetSymbolAddress((void**)&Wc1t, g_Wc1t);
    cudaGetSymbolAddress((void**)&Wqt, g_Wqt);
    cudaGetSymbolAddress((void**)&cW1t, g_cW1t);
    cudaGetSymbolAddress((void**)&bq, g_bq);
    cudaGetSymbolAddress((void**)&cnt, g_cnt);
    cudaGetSymbolAddress((void**)&rp, g_rowptr);
    cudaGetSymbolAddress((void**)&cur, g_cur);
    cudaGetSymbolAddress((void**)&ci, g_colidx);

    const int* src = eidx;
    const int* dst = eidx + E;

    // dynamic smem: max(double-buffered stage, epilogue C tile), bytes
    // EPI0/1/2 (BM=64,BN=128): stage = 2*(64*40 + 128*40)*4 = 61440 ; Cs = 64*136*4 = 34816
    // EPI3     (BM=128,BN=64): stage = 2*(128*40 + 64*40)*4 = 61440 ; Cs = 128*72*4 = 36864
    const int SM_A = 61440;
    const int SM_B = 61440;
    cudaFuncSetAttribute((const void*)k_wmma<64, 128, 2, 4, 0>, cudaFuncAttributeMaxDynamicSharedMemorySize, SM_A);
    cudaFuncSetAttribute((const void*)k_wmma<64, 128, 2, 4, 1>, cudaFuncAttributeMaxDynamicSharedMemorySize, SM_A);
    cudaFuncSetAttribute((const void*)k_wmma<64, 128, 2, 4, 2>, cudaFuncAttributeMaxDynamicSharedMemorySize, SM_A);
    cudaFuncSetAttribute((const void*)k_wmma<128, 64, 4, 2, 3>, cudaFuncAttributeMaxDynamicSharedMemorySize, SM_B);

    // ---- build CSR (deterministic after per-segment sort) ----
    k_zero_i<<<(N + 255) / 256, 256>>>(cnt, N);
    k_hist<<<(E + 255) / 256, 256>>>(dst, E, cnt);
    k_scan<<<1, 1024>>>(cnt, rp, N);
    k_copy_i<<<(N + 255) / 256, 256>>>(rp, cur, N);
    k_fill<<<(E + 255) / 256, 256>>>(src, dst, E, cur, ci);
    k_sortseg<<<(N + 255) / 256, 256>>>(rp, ci, N);

    // ---- init GRU state + pre-transposed weights ----
    k_zero_f4<<<(N * 128 / 4 + 255) / 256, 256>>>((float4*)hA, N * 128 / 4);
    k_prep_c0<<<(128 * 128 + 255) / 256, 256>>>(Wn0, Ws0, Wc0t);
    k_prep_c1<<<(128 * 256 + 255) / 256, 256>>>(Wn1, Ws1, Wc1t);
    k_prep_qt<<<(512 * 256 + 255) / 256, 256>>>(gWih, gWhh, gbih, gbhh, Wqt, bq);
    k_prep_cls<<<(64 * 128 + 255) / 256, 256>>>(cW1, cW1t);

    const int GRID64  = (N + 63) / 64;    // 1563 (BM=64 kernels)
    const int GRID128 = (N + 127) / 128;  // 782  (classifier)
    const int AGG_GRID = (N + 7) / 8;

    float* hprev = hA;
    float* hnext = hB;
    for (int t = 0; t < T_STEPS; t++) {
        const float* xt = x_seq + (size_t)t * N * 64;
        // SAGE layer 0: LN+ReLU
        k_agg64<<<AGG_GRID, 256>>>(xt, agg, rp, ci, N);
        k_wmma<64, 128, 2, 4, 0><<<dim3(GRID64, 1), 256, SM_A>>>(
            agg, 64, xt, 64, Wc0t, 128, b0, g0, be0, nullptr, h0, N);
        // SAGE layer 1: LN+ReLU + residual(h0)
        k_agg128<<<AGG_GRID, 256>>>(h0, agg, rp, ci, N);
        k_wmma<64, 128, 2, 4, 1><<<dim3(GRID64, 1), 256, SM_A>>>(
            agg, 128, h0, 128, Wc1t, 256, b1, g1, be1, h0, h1, N);
        // GRU step (gate-quad epilogue), Ntot=512 in 4 col-blocks
        k_wmma<64, 128, 2, 4, 2><<<dim3(GRID64, 4), 256, SM_A>>>(
            h1, 128, hprev, 128, Wqt, 256, bq, nullptr, nullptr, hprev, hnext, N);
        float* tmp = hprev; hprev = hnext; hnext = tmp;
    }
    // classifier
    k_wmma<128, 64, 4, 2, 3><<<dim3(GRID128, 1), 256, SM_B>>>(
        hprev, 128, nullptr, 0, cW1t, 128, cb1, nullptr, nullptr, nullptr, zc, N);
    k_logits<<<AGG_GRID, 256>>>(zc, cW2, cb2, (float*)d_out, N);
}

// round 8
// speedup vs baseline: 1.7374x; 1.4698x over previous
#include <cuda_runtime.h>
#include <cuda_bf16.h>
#include <cuda_fp16.h>
#include <mma.h>
#include <cstdint>

using namespace nvcuda;

#define N_NODES 100000
#define N_EDGES 1600000
#define T_STEPS 12

// ----------------- static device scratch -----------------
__device__ float g_agg[(size_t)N_NODES * 128];
__device__ float g_h0 [(size_t)N_NODES * 128];
__device__ float g_h1 [(size_t)N_NODES * 128];
__device__ float g_hA [(size_t)N_NODES * 128];
__device__ float g_hB [(size_t)N_NODES * 128];
__device__ float g_zc [(size_t)N_NODES * 64];
__device__ float g_Wc0t[128 * 128];   // [N=128, K=128] = [Wn0 | Ws0]^T  (K-major)
__device__ float g_Wc1t[128 * 256];   // [N=128, K=256] = [Wn1 | Ws1]^T
__device__ float g_Wqt [512 * 256];   // [N=512 gate-quads, K=256]
__device__ float g_cW1t[64 * 128];    // [N=64, K=128]
__device__ float g_bq [512];
__device__ int   g_cnt   [N_NODES];
__device__ int   g_rowptr[N_NODES + 1];
__device__ int   g_cur   [N_NODES];
__device__ int   g_colidx[N_EDGES];

__device__ __forceinline__ float sigf(float x) { return 1.f / (1.f + expf(-x)); }

// store float4 as 4 fp16 values (8 bytes), RN conversion
__device__ __forceinline__ void sts4_f16(__half* p, float4 v) {
    __half2 a = __floats2half2_rn(v.x, v.y);
    __half2 b = __floats2half2_rn(v.z, v.w);
    uint2 u;
    u.x = *(uint32_t*)&a;
    u.y = *(uint32_t*)&b;
    *(uint2*)p = u;
}

// ----------------- wmma fp16 GEMM (fp32 accum), pipelined, fused epilogues -----------------
// D[row, jbase+c] = epi( A1[row,:K1]@Bt[jbase+c,:K1]^T + A2[row,:K2]@Bt[...,K1:]^T )
// Bt is [Ntot x Ktot] K-major. K in chunks of 32 (2x k16 MMA), ping-pong smem buffers.
// EPI 0: bias+LayerNorm+ReLU            (BM=64, BN=128, out stride 128)
// EPI 1: bias+LayerNorm+ReLU+residual   (BM=64, BN=128)
// EPI 2: GRU gate-quad update           (BM=64, BN=128, grid.y=4, res=h_prev)
// EPI 3: bias+ReLU                      (BM=128, BN=64, out stride 64)
template <int BM, int BN, int WR, int WC, int EPI>
__global__ void __launch_bounds__(256) k_wmma(
    const float* __restrict__ A1, int K1,
    const float* __restrict__ A2, int K2,
    const float* __restrict__ Bt, int Ktot,
    const float* __restrict__ bias,
    const float* __restrict__ gamma, const float* __restrict__ beta,
    const float* __restrict__ res,
    float* __restrict__ out, int n)
{
    constexpr int LDH = 80;            // halfs per row = 160B (32B-aligned frag ptrs)
    constexpr int LDC = BN + 8;
    constexpr int ASZ = BM * LDH;      // halfs per A buffer
    constexpr int BSZ = BN * LDH;
    constexpr int MI = BM / WR / 16;   // 2
    constexpr int NI = BN / WC / 16;   // 2
    constexpr int AIT = BM * 8 / 256;  // float4 stage iters (A)
    constexpr int BIT = BN * 8 / 256;  // float4 stage iters (B)
    extern __shared__ __align__(256) char smem_raw[];
    __half* Hs = (__half*)smem_raw;
    float* Cs = (float*)smem_raw;

    const int tid = threadIdx.x;
    const int wid = tid >> 5;
    const int wr = wid / WC, wc = wid % WC;
    const int row0 = blockIdx.x * BM;
    const int jbase = blockIdx.y * BN;

    wmma::fragment<wmma::accumulator, 16, 16, 16, float> acc[MI][NI];
#pragma unroll
    for (int mi = 0; mi < MI; mi++)
#pragma unroll
        for (int ni = 0; ni < NI; ni++) wmma::fill_fragment(acc[mi][ni], 0.f);

    const int nc = Ktot / 32;
    float4 pa[AIT], pb[BIT];

    auto ldg_chunk = [&](int c) {
        int kg = c * 32;
        const float* Asrc; int Kph, koff;
        if (kg < K1) { Asrc = A1; Kph = K1; koff = kg; }
        else         { Asrc = A2; Kph = K2; koff = kg - K1; }
#pragma unroll
        for (int it = 0; it < AIT; it++) {
            int idx = it * 256 + tid;
            int r = idx >> 3, q = idx & 7;
            int grow = row0 + r;
            pa[it] = (grow < n) ? *(const float4*)(Asrc + (size_t)grow * Kph + koff + q * 4)
                                : make_float4(0.f, 0.f, 0.f, 0.f);
        }
#pragma unroll
        for (int it = 0; it < BIT; it++) {
            int idx = it * 256 + tid;
            int r = idx >> 3, q = idx & 7;
            pb[it] = *(const float4*)(Bt + (size_t)(jbase + r) * Ktot + kg + q * 4);
        }
    };
    auto sts_chunk = [&](int s) {
        __half* As = Hs + s * ASZ;
        __half* Bs = Hs + 2 * ASZ + s * BSZ;
#pragma unroll
        for (int it = 0; it < AIT; it++) {
            int idx = it * 256 + tid;
            int r = idx >> 3, q = idx & 7;
            sts4_f16(&As[r * LDH + q * 4], pa[it]);
        }
#pragma unroll
        for (int it = 0; it < BIT; it++) {
            int idx = it * 256 + tid;
            int r = idx >> 3, q = idx & 7;
            sts4_f16(&Bs[r * LDH + q * 4], pb[it]);
        }
    };

    // prologue: stage chunk 0 into buffer 0
    ldg_chunk(0);
    sts_chunk(0);
    __syncthreads();

    for (int c = 0; c < nc; c++) {
        int s = c & 1;
        if (c + 1 < nc) ldg_chunk(c + 1);   // LDGs in flight while MMAs run
        const __half* As = Hs + s * ASZ;
        const __half* Bs = Hs + 2 * ASZ + s * BSZ;
#pragma unroll
        for (int ks = 0; ks < 2; ks++) {
            wmma::fragment<wmma::matrix_a, 16, 16, 16, __half, wmma::row_major> af[MI];
            wmma::fragment<wmma::matrix_b, 16, 16, 16, __half, wmma::col_major> bf[NI];
#pragma unroll
            for (int mi = 0; mi < MI; mi++)
                wmma::load_matrix_sync(af[mi], As + (wr * (BM / WR) + mi * 16) * LDH + ks * 16, LDH);
#pragma unroll
            for (int ni = 0; ni < NI; ni++)
                wmma::load_matrix_sync(bf[ni], Bs + (wc * (BN / WC) + ni * 16) * LDH + ks * 16, LDH);
#pragma unroll
            for (int mi = 0; mi < MI; mi++)
#pragma unroll
                for (int ni = 0; ni < NI; ni++)
                    wmma::mma_sync(acc[mi][ni], af[mi], bf[ni], acc[mi][ni]);
        }
        if (c + 1 < nc) sts_chunk(s ^ 1);
        __syncthreads();
    }

    // spill accumulators to smem C tile
#pragma unroll
    for (int mi = 0; mi < MI; mi++)
#pragma unroll
        for (int ni = 0; ni < NI; ni++)
            wmma::store_matrix_sync(Cs + (wr * (BM / WR) + mi * 16) * LDC + wc * (BN / WC) + ni * 16,
                                    acc[mi][ni], LDC, wmma::mem_row_major);
    __syncthreads();

    // ------------- epilogues (identical fp32 numerics) -------------
    if constexpr (EPI == 0 || EPI == 1) {
        // 4 threads per row, 32 cols each; LN over 128 cols
        int r = tid >> 2, seg = tid & 3;
        int grow = row0 + r;
        float v[32];
        float sum = 0.f, sq = 0.f;
#pragma unroll
        for (int q = 0; q < 8; q++) {
            float4 c4 = *(float4*)&Cs[r * LDC + seg * 32 + q * 4];
            float b0v = __ldg(&bias[seg * 32 + q * 4 + 0]);
            float b1v = __ldg(&bias[seg * 32 + q * 4 + 1]);
            float b2v = __ldg(&bias[seg * 32 + q * 4 + 2]);
            float b3v = __ldg(&bias[seg * 32 + q * 4 + 3]);
            v[q * 4 + 0] = c4.x + b0v; v[q * 4 + 1] = c4.y + b1v;
            v[q * 4 + 2] = c4.z + b2v; v[q * 4 + 3] = c4.w + b3v;
#pragma unroll
            for (int u = 0; u < 4; u++) { sum += v[q * 4 + u]; sq += v[q * 4 + u] * v[q * 4 + u]; }
        }
        sum += __shfl_xor_sync(0xffffffffu, sum, 1);
        sq  += __shfl_xor_sync(0xffffffffu, sq, 1);
        sum += __shfl_xor_sync(0xffffffffu, sum, 2);
        sq  += __shfl_xor_sync(0xffffffffu, sq, 2);
        float mean = sum * (1.f / 128.f);
        float var = sq * (1.f / 128.f) - mean * mean;
        float rs = rsqrtf(var + 1e-5f);
        if (grow < n) {
#pragma unroll
            for (int q = 0; q < 8; q++) {
                int cc = seg * 32 + q * 4;
                float4 o;
                o.x = fmaxf((v[q * 4 + 0] - mean) * rs * __ldg(&gamma[cc + 0]) + __ldg(&beta[cc + 0]), 0.f);
                o.y = fmaxf((v[q * 4 + 1] - mean) * rs * __ldg(&gamma[cc + 1]) + __ldg(&beta[cc + 1]), 0.f);
                o.z = fmaxf((v[q * 4 + 2] - mean) * rs * __ldg(&gamma[cc + 2]) + __ldg(&beta[cc + 2]), 0.f);
                o.w = fmaxf((v[q * 4 + 3] - mean) * rs * __ldg(&gamma[cc + 3]) + __ldg(&beta[cc + 3]), 0.f);
                if (EPI == 1) {
                    float4 rv = *(const float4*)(res + (size_t)grow * 128 + cc);
                    o.x += rv.x; o.y += rv.y; o.z += rv.z; o.w += rv.w;
                }
                *(float4*)(out + (size_t)grow * 128 + cc) = o;
            }
        }
    } else if constexpr (EPI == 2) {
        // GRU gate quads: 128 gemm cols -> 32 h cols; 4 threads/row, 8 quads each
        int r = tid >> 2, seg = tid & 3;
        int grow = row0 + r;
        if (grow < n) {
            int lc0 = seg * 32;
            float hv[8];
#pragma unroll
            for (int q = 0; q < 8; q++) {
                int lc = lc0 + q * 4;
                int gcol = jbase + lc;
                float cr = Cs[r * LDC + lc + 0] + __ldg(&bias[gcol + 0]);
                float cz = Cs[r * LDC + lc + 1] + __ldg(&bias[gcol + 1]);
                float ci = Cs[r * LDC + lc + 2] + __ldg(&bias[gcol + 2]);
                float ch = Cs[r * LDC + lc + 3] + __ldg(&bias[gcol + 3]);
                float rg = sigf(cr);
                float z = sigf(cz);
                float ng = tanhf(ci + rg * ch);
                float hp = res[(size_t)grow * 128 + ((jbase + lc0) >> 2) + q];
                hv[q] = (1.f - z) * ng + z * hp;
            }
            int j0 = ((jbase + lc0) >> 2);
            *(float4*)(out + (size_t)grow * 128 + j0) = make_float4(hv[0], hv[1], hv[2], hv[3]);
            *(float4*)(out + (size_t)grow * 128 + j0 + 4) = make_float4(hv[4], hv[5], hv[6], hv[7]);
        }
    } else {  // EPI == 3: bias+relu, BN=64, out stride 64
        int r = tid >> 1, seg = tid & 1;
        int grow = row0 + r;
        if (grow < n) {
#pragma unroll
            for (int q = 0; q < 8; q++) {
                int cc = seg * 32 + q * 4;
                float4 c4 = *(float4*)&Cs[r * LDC + cc];
                float4 o;
                o.x = fmaxf(c4.x + __ldg(&bias[cc + 0]), 0.f);
                o.y = fmaxf(c4.y + __ldg(&bias[cc + 1]), 0.f);
                o.z = fmaxf(c4.z + __ldg(&bias[cc + 2]), 0.f);
                o.w = fmaxf(c4.w + __ldg(&bias[cc + 3]), 0.f);
                *(float4*)(out + (size_t)grow * 64 + cc) = o;
            }
        }
    }
}

// ----------------- CSR build + misc -----------------
__global__ void k_zero_f4(float4* p, int c4) {
    int i = blockIdx.x * blockDim.x + threadIdx.x;
    if (i < c4) p[i] = make_float4(0.f, 0.f, 0.f, 0.f);
}
__global__ void k_zero_i(int* p, int c) {
    int i = blockIdx.x * blockDim.x + threadIdx.x;
    if (i < c) p[i] = 0;
}
__global__ void k_hist(const int* __restrict__ dst, int e, int* __restrict__ cnt) {
    int i = blockIdx.x * blockDim.x + threadIdx.x;
    if (i < e) atomicAdd(&cnt[dst[i]], 1);
}
__global__ void k_copy_i(const int* __restrict__ a, int* __restrict__ b, int c) {
    int i = blockIdx.x * blockDim.x + threadIdx.x;
    if (i < c) b[i] = a[i];
}
__global__ void k_fill(const int* __restrict__ src, const int* __restrict__ dst, int e,
                       int* __restrict__ cur, int* __restrict__ colidx) {
    int i = blockIdx.x * blockDim.x + threadIdx.x;
    if (i < e) {
        int p = atomicAdd(&cur[dst[i]], 1);
        colidx[p] = src[i];
    }
}
__global__ void k_sortseg(const int* __restrict__ rp, int* __restrict__ ci, int n) {
    int v = blockIdx.x * blockDim.x + threadIdx.x;
    if (v >= n) return;
    int s = rp[v], e = rp[v + 1];
    for (int i = s + 1; i < e; i++) {
        int key = ci[i];
        int j = i - 1;
        while (j >= s && ci[j] > key) { ci[j + 1] = ci[j]; j--; }
        ci[j + 1] = key;
    }
}
__global__ void k_scan(const int* __restrict__ cnt, int* __restrict__ rowptr, int n) {
    __shared__ int wsums[32];
    __shared__ int s_carry;
    int tid = threadIdx.x;
    int lane = tid & 31, wid = tid >> 5;
    if (tid == 0) s_carry = 0;
    __syncthreads();
    for (int base = 0; base < n; base += 1024) {
        int i = base + tid;
        int v = (i < n) ? cnt[i] : 0;
        int x = v;
#pragma unroll
        for (int o = 1; o < 32; o <<= 1) {
            int t = __shfl_up_sync(0xffffffffu, x, o);
            if (lane >= o) x += t;
        }
        if (lane == 31) wsums[wid] = x;
        __syncthreads();
        if (tid < 32) {
            int s = wsums[tid];
#pragma unroll
            for (int o = 1; o < 32; o <<= 1) {
                int t = __shfl_up_sync(0xffffffffu, s, o);
                if (tid >= o) s += t;
            }
            wsums[tid] = s;
        }
        __syncthreads();
        int incl = x + ((wid > 0) ? wsums[wid - 1] : 0);
        int excl = s_carry + incl - v;
        if (i < n) rowptr[i] = excl;
        int blocktot = wsums[31];
        __syncthreads();
        if (tid == 0) s_carry += blocktot;
        __syncthreads();
    }
    if (tid == 0) rowptr[n] = s_carry;
}

// ----------------- weight pre-transpose kernels -----------------
__global__ void k_prep_c0(const float* __restrict__ Wn, const float* __restrict__ Ws,
                          float* __restrict__ o) {
    int idx = blockIdx.x * blockDim.x + threadIdx.x;
    if (idx >= 128 * 128) return;
    int nn = idx >> 7, k = idx & 127;
    o[idx] = (k < 64) ? Wn[k * 128 + nn] : Ws[(k - 64) * 128 + nn];
}
__global__ void k_prep_c1(const float* __restrict__ Wn, const float* __restrict__ Ws,
                          float* __restrict__ o) {
    int idx = blockIdx.x * blockDim.x + threadIdx.x;
    if (idx >= 128 * 256) return;
    int nn = idx >> 8, k = idx & 255;
    o[idx] = (k < 128) ? Wn[k * 128 + nn] : Ws[(k - 128) * 128 + nn];
}
__global__ void k_prep_qt(const float* __restrict__ Wih, const float* __restrict__ Whh,
                          const float* __restrict__ bih, const float* __restrict__ bhh,
                          float* __restrict__ o, float* __restrict__ bq) {
    int idx = blockIdx.x * blockDim.x + threadIdx.x;
    if (idx >= 512 * 256) return;
    int c = idx >> 8, k = idx & 255;
    int j = c >> 2, g = c & 3;
    float w = 0.f;
    if (k < 128) {
        if (g == 0)      w = Wih[j * 128 + k];
        else if (g == 1) w = Wih[(128 + j) * 128 + k];
        else if (g == 2) w = Wih[(256 + j) * 128 + k];
    } else {
        int kk = k - 128;
        if (g == 0)      w = Whh[j * 128 + kk];
        else if (g == 1) w = Whh[(128 + j) * 128 + kk];
        else if (g == 3) w = Whh[(256 + j) * 128 + kk];
    }
    o[idx] = w;
    if (idx < 512) {
        int jj = idx >> 2, gg = idx & 3;
        bq[idx] = (gg == 0) ? bih[jj] + bhh[jj]
                : (gg == 1) ? bih[128 + jj] + bhh[128 + jj]
                : (gg == 2) ? bih[256 + jj]
                            : bhh[256 + jj];
    }
}
__global__ void k_prep_cls(const float* __restrict__ W, float* __restrict__ o) {
    int idx = blockIdx.x * blockDim.x + threadIdx.x;
    if (idx >= 64 * 128) return;
    int oo = idx >> 7, k = idx & 127;
    o[idx] = W[k * 64 + oo];
}

// ----------------- mean aggregation (warp per node) -----------------
__global__ void __launch_bounds__(256) k_agg64(const float* __restrict__ x, float* __restrict__ out,
                                               const int* __restrict__ rp, const int* __restrict__ ci, int n) {
    int w = (blockIdx.x * blockDim.x + threadIdx.x) >> 5;
    if (w >= n) return;
    int lane = threadIdx.x & 31;
    int s0 = rp[w], s1 = rp[w + 1];
    float ax = 0.f, ay = 0.f;
    int e = s0;
    for (; e + 4 <= s1; e += 4) {
        int i0 = ci[e], i1 = ci[e + 1], i2 = ci[e + 2], i3 = ci[e + 3];
        float2 v0 = *(const float2*)(x + (size_t)i0 * 64 + lane * 2);
        float2 v1 = *(const float2*)(x + (size_t)i1 * 64 + lane * 2);
        float2 v2 = *(const float2*)(x + (size_t)i2 * 64 + lane * 2);
        float2 v3 = *(const float2*)(x + (size_t)i3 * 64 + lane * 2);
        ax += (v0.x + v1.x) + (v2.x + v3.x);
        ay += (v0.y + v1.y) + (v2.y + v3.y);
    }
    for (; e < s1; e++) {
        int i0 = ci[e];
        float2 v0 = *(const float2*)(x + (size_t)i0 * 64 + lane * 2);
        ax += v0.x; ay += v0.y;
    }
    int d = s1 - s0; if (d < 1) d = 1;
    float inv = 1.f / (float)d;
    *(float2*)(out + (size_t)w * 64 + lane * 2) = make_float2(ax * inv, ay * inv);
}
__global__ void __launch_bounds__(256) k_agg128(const float* __restrict__ x, float* __restrict__ out,
                                                const int* __restrict__ rp, const int* __restrict__ ci, int n) {
    int w = (blockIdx.x * blockDim.x + threadIdx.x) >> 5;
    if (w >= n) return;
    int lane = threadIdx.x & 31;
    int s0 = rp[w], s1 = rp[w + 1];
    float4 acc = make_float4(0.f, 0.f, 0.f, 0.f);
    int e = s0;
    for (; e + 4 <= s1; e += 4) {
        int i0 = ci[e], i1 = ci[e + 1], i2 = ci[e + 2], i3 = ci[e + 3];
        float4 v0 = *(const float4*)(x + (size_t)i0 * 128 + lane * 4);
        float4 v1 = *(const float4*)(x + (size_t)i1 * 128 + lane * 4);
        float4 v2 = *(const float4*)(x + (size_t)i2 * 128 + lane * 4);
        float4 v3 = *(const float4*)(x + (size_t)i3 * 128 + lane * 4);
        acc.x += (v0.x + v1.x) + (v2.x + v3.x);
        acc.y += (v0.y + v1.y) + (v2.y + v3.y);
        acc.z += (v0.z + v1.z) + (v2.z + v3.z);
        acc.w += (v0.w + v1.w) + (v2.w + v3.w);
    }
    for (; e < s1; e++) {
        int i0 = ci[e];
        float4 v0 = *(const float4*)(x + (size_t)i0 * 128 + lane * 4);
        acc.x += v0.x; acc.y += v0.y; acc.z += v0.z; acc.w += v0.w;
    }
    int d = s1 - s0; if (d < 1) d = 1;
    float inv = 1.f / (float)d;
    *(float4*)(out + (size_t)w * 128 + lane * 4) =
        make_float4(acc.x * inv, acc.y * inv, acc.z * inv, acc.w * inv);
}

// final logits: warp per row, zc[64] @ W2[64,2] + b2
__global__ void __launch_bounds__(256) k_logits(const float* __restrict__ zc,
                                                const float* __restrict__ W2,
                                                const float* __restrict__ b2,
                                                float* __restrict__ out, int n) {
    int w = (blockIdx.x * blockDim.x + threadIdx.x) >> 5;
    if (w >= n) return;
    int lane = threadIdx.x & 31;
    float z0 = zc[(size_t)w * 64 + lane];
    float z1 = zc[(size_t)w * 64 + 32 + lane];
    float a0 = z0 * W2[lane * 2 + 0] + z1 * W2[(lane + 32) * 2 + 0];
    float a1 = z0 * W2[lane * 2 + 1] + z1 * W2[(lane + 32) * 2 + 1];
#pragma unroll
    for (int o = 16; o > 0; o >>= 1) {
        a0 += __shfl_xor_sync(0xffffffffu, a0, o);
        a1 += __shfl_xor_sync(0xffffffffu, a1, o);
    }
    if (lane == 0) {
        out[(size_t)w * 2 + 0] = a0 + b2[0];
        out[(size_t)w * 2 + 1] = a1 + b2[1];
    }
}

// ----------------- host launch -----------------
extern "C" void kernel_launch(void* const* d_in, const int* in_sizes, int n_in,
                              void* d_out, int out_size) {
    const int N = N_NODES, E = N_EDGES;

    const float* x_seq = nullptr;
    const int* eidx = nullptr;
    const float* Wt[18];
    int wi = 0;
    for (int i = 0; i < n_in; i++) {
        if (in_sizes[i] == 2 * E) eidx = (const int*)d_in[i];
        else if (in_sizes[i] == T_STEPS * N * 64) x_seq = (const float*)d_in[i];
        else if (wi < 18) Wt[wi++] = (const float*)d_in[i];
    }
    const float *Wn0 = Wt[0], *Ws0 = Wt[1], *b0 = Wt[2], *g0 = Wt[3], *be0 = Wt[4];
    const float *Wn1 = Wt[5], *Ws1 = Wt[6], *b1 = Wt[7], *g1 = Wt[8], *be1 = Wt[9];
    const float *gWih = Wt[10], *gWhh = Wt[11], *gbih = Wt[12], *gbhh = Wt[13];
    const float *cW1 = Wt[14], *cb1 = Wt[15], *cW2 = Wt[16], *cb2 = Wt[17];

    float *agg, *h0, *h1, *hA, *hB, *zc, *Wc0t, *Wc1t, *Wqt, *cW1t, *bq;
    int *cnt, *rp, *cur, *ci;
    cudaGetSymbolAddress((void**)&agg, g_agg);
    cudaGetSymbolAddress((void**)&h0, g_h0);
    cudaGetSymbolAddress((void**)&h1, g_h1);
    cudaGetSymbolAddress((void**)&hA, g_hA);
    cudaGetSymbolAddress((void**)&hB, g_hB);
    cudaGetSymbolAddress((void**)&zc, g_zc);
    cudaGetSymbolAddress((void**)&Wc0t, g_Wc0t);
    cudaGetSymbolAddress((void**)&Wc1t, g_Wc1t);
    cudaGetSymbolAddress((void**)&Wqt, g_Wqt);
    cudaGetSymbolAddress((void**)&cW1t, g_cW1t);
    cudaGetSymbolAddress((void**)&bq, g_bq);
    cudaGetSymbolAddress((void**)&cnt, g_cnt);
    cudaGetSymbolAddress((void**)&rp, g_rowptr);
    cudaGetSymbolAddress((void**)&cur, g_cur);
    cudaGetSymbolAddress((void**)&ci, g_colidx);

    const int* src = eidx;
    const int* dst = eidx + E;

    // dynamic smem: max(double-buffered fp16 stage, fp32 epilogue C tile), bytes
    // EPI0/1/2 (BM=64,BN=128): stage = 2*(64*80 + 128*80)*2 = 61440 ; Cs = 64*136*4 = 34816
    // EPI3     (BM=128,BN=64): stage = 2*(128*80 + 64*80)*2 = 61440 ; Cs = 128*72*4 = 36864
    const int SM_A = 61440;
    const int SM_B = 61440;
    cudaFuncSetAttribute((const void*)k_wmma<64, 128, 2, 4, 0>, cudaFuncAttributeMaxDynamicSharedMemorySize, SM_A);
    cudaFuncSetAttribute((const void*)k_wmma<64, 128, 2, 4, 1>, cudaFuncAttributeMaxDynamicSharedMemorySize, SM_A);
    cudaFuncSetAttribute((const void*)k_wmma<64, 128, 2, 4, 2>, cudaFuncAttributeMaxDynamicSharedMemorySize, SM_A);
    cudaFuncSetAttribute((const void*)k_wmma<128, 64, 4, 2, 3>, cudaFuncAttributeMaxDynamicSharedMemorySize, SM_B);

    // ---- build CSR (deterministic after per-segment sort) ----
    k_zero_i<<<(N + 255) / 256, 256>>>(cnt, N);
    k_hist<<<(E + 255) / 256, 256>>>(dst, E, cnt);
    k_scan<<<1, 1024>>>(cnt, rp, N);
    k_copy_i<<<(N + 255) / 256, 256>>>(rp, cur, N);
    k_fill<<<(E + 255) / 256, 256>>>(src, dst, E, cur, ci);
    k_sortseg<<<(N + 255) / 256, 256>>>(rp, ci, N);

    // ---- init GRU state + pre-transposed weights ----
    k_zero_f4<<<(N * 128 / 4 + 255) / 256, 256>>>((float4*)hA, N * 128 / 4);
    k_prep_c0<<<(128 * 128 + 255) / 256, 256>>>(Wn0, Ws0, Wc0t);
    k_prep_c1<<<(128 * 256 + 255) / 256, 256>>>(Wn1, Ws1, Wc1t);
    k_prep_qt<<<(512 * 256 + 255) / 256, 256>>>(gWih, gWhh, gbih, gbhh, Wqt, bq);
    k_prep_cls<<<(64 * 128 + 255) / 256, 256>>>(cW1, cW1t);

    const int GRID64  = (N + 63) / 64;    // 1563 (BM=64 kernels)
    const int GRID128 = (N + 127) / 128;  // 782  (classifier)
    const int AGG_GRID = (N + 7) / 8;

    float* hprev = hA;
    float* hnext = hB;
    for (int t = 0; t < T_STEPS; t++) {
        const float* xt = x_seq + (size_t)t * N * 64;
        // SAGE layer 0: LN+ReLU
        k_agg64<<<AGG_GRID, 256>>>(xt, agg, rp, ci, N);
        k_wmma<64, 128, 2, 4, 0><<<dim3(GRID64, 1), 256, SM_A>>>(
            agg, 64, xt, 64, Wc0t, 128, b0, g0, be0, nullptr, h0, N);
        // SAGE layer 1: LN+ReLU + residual(h0)
        k_agg128<<<AGG_GRID, 256>>>(h0, agg, rp, ci, N);
        k_wmma<64, 128, 2, 4, 1><<<dim3(GRID64, 1), 256, SM_A>>>(
            agg, 128, h0, 128, Wc1t, 256, b1, g1, be1, h0, h1, N);
        // GRU step (gate-quad epilogue), Ntot=512 in 4 col-blocks
        k_wmma<64, 128, 2, 4, 2><<<dim3(GRID64, 4), 256, SM_A>>>(
            h1, 128, hprev, 128, Wqt, 256, bq, nullptr, nullptr, hprev, hnext, N);
        float* tmp = hprev; hprev = hnext; hnext = tmp;
    }
    // classifier
    k_wmma<128, 64, 4, 2, 3><<<dim3(GRID128, 1), 256, SM_B>>>(
        hprev, 128, nullptr, 0, cW1t, 128, cb1, nullptr, nullptr, nullptr, zc, N);
    k_logits<<<AGG_GRID, 256>>>(zc, cW2, cb2, (float*)d_out, N);
}

// round 9
// speedup vs baseline: 2.2316x; 1.2844x over previous
#include <cuda_runtime.h>
#include <cuda_bf16.h>
#include <cuda_fp16.h>
#include <mma.h>
#include <cstdint>

using namespace nvcuda;

#define N_NODES 100000
#define N_EDGES 1600000
#define T_STEPS 12

// ----------------- static device scratch -----------------
// fp16 arrays declared as uint4 for 16B alignment (cast to __half*)
__device__ uint4 g_x16 [(size_t)T_STEPS * N_NODES * 64 / 8];  // fp16 copy of x_seq
__device__ uint4 g_agg16[(size_t)N_NODES * 128 / 8];
__device__ uint4 g_h016 [(size_t)N_NODES * 128 / 8];
__device__ uint4 g_h116 [(size_t)N_NODES * 128 / 8];
__device__ uint4 g_hA16 [(size_t)N_NODES * 128 / 8];
__device__ uint4 g_hB16 [(size_t)N_NODES * 128 / 8];
__device__ uint4 g_Wc0t16[128 * 128 / 8];   // [N=128, K=128] = [Wn0 | Ws0]^T  (K-major)
__device__ uint4 g_Wc1t16[128 * 256 / 8];   // [N=128, K=256] = [Wn1 | Ws1]^T
__device__ uint4 g_Wqt16 [512 * 256 / 8];   // [N=512 gate-quads, K=256]
__device__ uint4 g_cW1t16[64 * 128 / 8];    // [N=64, K=128]
// fp32 arrays (residual / gather / state / epilogue use)
__device__ float g_h0f[(size_t)N_NODES * 128];
__device__ float g_hAf[(size_t)N_NODES * 128];
__device__ float g_hBf[(size_t)N_NODES * 128];
__device__ float g_zc [(size_t)N_NODES * 64];
__device__ float g_bq [512];
__device__ int   g_cnt   [N_NODES];
__device__ int   g_rowptr[N_NODES + 1];
__device__ int   g_cur   [N_NODES];
__device__ int   g_colidx[N_EDGES];

__device__ __forceinline__ float sigf(float x) { return 1.f / (1.f + expf(-x)); }

__device__ __forceinline__ uint2 pack4_f16(float a, float b, float c, float d) {
    __half2 lo = __floats2half2_rn(a, b);
    __half2 hi = __floats2half2_rn(c, d);
    uint2 u;
    u.x = *(uint32_t*)&lo;
    u.y = *(uint32_t*)&hi;
    return u;
}

// ----------------- wmma fp16 GEMM (fp32 accum), all-fp16 operands, K-chunk 64 -----------------
// D[row, jbase+c] = epi( A1[row,:K1]@Bt[jbase+c,:K1]^T + A2[row,:K2]@Bt[...,K1:]^T )
// A1/A2/Bt are fp16, K-major. K in chunks of 64 (4x k16 MMA), ping-pong smem buffers.
// EPI 0: bias+LayerNorm+ReLU            (BM=64, BN=128) -> out fp32 + out16 fp16
// EPI 1: bias+LayerNorm+ReLU+residual   (BM=64, BN=128) -> out16 fp16 only
// EPI 2: GRU gate-quad update           (BM=64, BN=128, grid.y=4, res=h_prev) -> out fp32 + out16 fp16
// EPI 3: bias+ReLU                      (BM=128, BN=64) -> out fp32 (stride 64)
template <int BM, int BN, int WR, int WC, int EPI>
__global__ void __launch_bounds__(256) k_wmma(
    const __half* __restrict__ A1, int K1,
    const __half* __restrict__ A2, int K2,
    const __half* __restrict__ Bt, int Ktot,
    const float* __restrict__ bias,
    const float* __restrict__ gamma, const float* __restrict__ beta,
    const float* __restrict__ res,
    float* __restrict__ out, __half* __restrict__ out16, int n)
{
    constexpr int LDH = 72;            // halfs per row = 144B (16B-aligned frag ptrs, ldm%8==0)
    constexpr int LDC = BN + 8;
    constexpr int ASZ = BM * LDH;      // halfs per A buffer
    constexpr int BSZ = BN * LDH;
    constexpr int MI = BM / WR / 16;   // 2
    constexpr int NI = BN / WC / 16;   // 2
    constexpr int AIT = BM / 32;       // uint4 (8-half) stage iters for A (BM*8 slots / 256)
    constexpr int BIT = BN / 32;
    extern __shared__ __align__(256) char smem_raw[];
    __half* Hs = (__half*)smem_raw;
    float* Cs = (float*)smem_raw;

    const int tid = threadIdx.x;
    const int wid = tid >> 5;
    const int wr = wid / WC, wc = wid % WC;
    const int row0 = blockIdx.x * BM;
    const int jbase = blockIdx.y * BN;

    wmma::fragment<wmma::accumulator, 16, 16, 16, float> acc[MI][NI];
#pragma unroll
    for (int mi = 0; mi < MI; mi++)
#pragma unroll
        for (int ni = 0; ni < NI; ni++) wmma::fill_fragment(acc[mi][ni], 0.f);

    const int nc = Ktot / 64;
    uint4 pa[AIT], pb[BIT];

    auto ldg_chunk = [&](int c) {
        int kg = c * 64;
        const __half* Asrc; int Kph, koff;
        if (kg < K1) { Asrc = A1; Kph = K1; koff = kg; }
        else         { Asrc = A2; Kph = K2; koff = kg - K1; }
#pragma unroll
        for (int it = 0; it < AIT; it++) {
            int idx = it * 256 + tid;
            int r = idx >> 3, q = idx & 7;          // q: 8 uint4 per 64-half row
            int grow = row0 + r;
            pa[it] = (grow < n) ? *(const uint4*)(Asrc + (size_t)grow * Kph + koff + q * 8)
                                : make_uint4(0u, 0u, 0u, 0u);
        }
#pragma unroll
        for (int it = 0; it < BIT; it++) {
            int idx = it * 256 + tid;
            int r = idx >> 3, q = idx & 7;
            pb[it] = *(const uint4*)(Bt + (size_t)(jbase + r) * Ktot + kg + q * 8);
        }
    };
    auto sts_chunk = [&](int s) {
        __half* As = Hs + s * ASZ;
        __half* Bs = Hs + 2 * ASZ + s * BSZ;
#pragma unroll
        for (int it = 0; it < AIT; it++) {
            int idx = it * 256 + tid;
            int r = idx >> 3, q = idx & 7;
            *(uint4*)(&As[r * LDH + q * 8]) = pa[it];
        }
#pragma unroll
        for (int it = 0; it < BIT; it++) {
            int idx = it * 256 + tid;
            int r = idx >> 3, q = idx & 7;
            *(uint4*)(&Bs[r * LDH + q * 8]) = pb[it];
        }
    };

    // prologue: stage chunk 0 into buffer 0
    ldg_chunk(0);
    sts_chunk(0);
    __syncthreads();

    for (int c = 0; c < nc; c++) {
        int s = c & 1;
        if (c + 1 < nc) ldg_chunk(c + 1);   // LDGs in flight while MMAs run
        const __half* As = Hs + s * ASZ;
        const __half* Bs = Hs + 2 * ASZ + s * BSZ;
#pragma unroll
        for (int ks = 0; ks < 4; ks++) {
            wmma::fragment<wmma::matrix_a, 16, 16, 16, __half, wmma::row_major> af[MI];
            wmma::fragment<wmma::matrix_b, 16, 16, 16, __half, wmma::col_major> bf[NI];
#pragma unroll
            for (int mi = 0; mi < MI; mi++)
                wmma::load_matrix_sync(af[mi], As + (wr * (BM / WR) + mi * 16) * LDH + ks * 16, LDH);
#pragma unroll
            for (int ni = 0; ni < NI; ni++)
                wmma::load_matrix_sync(bf[ni], Bs + (wc * (BN / WC) + ni * 16) * LDH + ks * 16, LDH);
#pragma unroll
            for (int mi = 0; mi < MI; mi++)
#pragma unroll
                for (int ni = 0; ni < NI; ni++)
                    wmma::mma_sync(acc[mi][ni], af[mi], bf[ni], acc[mi][ni]);
        }
        if (c + 1 < nc) sts_chunk(s ^ 1);
        __syncthreads();
    }

    // spill accumulators to smem C tile
#pragma unroll
    for (int mi = 0; mi < MI; mi++)
#pragma unroll
        for (int ni = 0; ni < NI; ni++)
            wmma::store_matrix_sync(Cs + (wr * (BM / WR) + mi * 16) * LDC + wc * (BN / WC) + ni * 16,
                                    acc[mi][ni], LDC, wmma::mem_row_major);
    __syncthreads();

    // ------------- epilogues (fp32 math identical to prior rounds) -------------
    if constexpr (EPI == 0 || EPI == 1) {
        // 4 threads per row, 32 cols each; LN over 128 cols
        int r = tid >> 2, seg = tid & 3;
        int grow = row0 + r;
        float v[32];
        float sum = 0.f, sq = 0.f;
#pragma unroll
        for (int q = 0; q < 8; q++) {
            float4 c4 = *(float4*)&Cs[r * LDC + seg * 32 + q * 4];
            float b0v = __ldg(&bias[seg * 32 + q * 4 + 0]);
            float b1v = __ldg(&bias[seg * 32 + q * 4 + 1]);
            float b2v = __ldg(&bias[seg * 32 + q * 4 + 2]);
            float b3v = __ldg(&bias[seg * 32 + q * 4 + 3]);
            v[q * 4 + 0] = c4.x + b0v; v[q * 4 + 1] = c4.y + b1v;
            v[q * 4 + 2] = c4.z + b2v; v[q * 4 + 3] = c4.w + b3v;
#pragma unroll
            for (int u = 0; u < 4; u++) { sum += v[q * 4 + u]; sq += v[q * 4 + u] * v[q * 4 + u]; }
        }
        sum += __shfl_xor_sync(0xffffffffu, sum, 1);
        sq  += __shfl_xor_sync(0xffffffffu, sq, 1);
        sum += __shfl_xor_sync(0xffffffffu, sum, 2);
        sq  += __shfl_xor_sync(0xffffffffu, sq, 2);
        float mean = sum * (1.f / 128.f);
        float var = sq * (1.f / 128.f) - mean * mean;
        float rs = rsqrtf(var + 1e-5f);
        if (grow < n) {
#pragma unroll
            for (int q = 0; q < 8; q++) {
                int cc = seg * 32 + q * 4;
                float4 o;
                o.x = fmaxf((v[q * 4 + 0] - mean) * rs * __ldg(&gamma[cc + 0]) + __ldg(&beta[cc + 0]), 0.f);
                o.y = fmaxf((v[q * 4 + 1] - mean) * rs * __ldg(&gamma[cc + 1]) + __ldg(&beta[cc + 1]), 0.f);
                o.z = fmaxf((v[q * 4 + 2] - mean) * rs * __ldg(&gamma[cc + 2]) + __ldg(&beta[cc + 2]), 0.f);
                o.w = fmaxf((v[q * 4 + 3] - mean) * rs * __ldg(&gamma[cc + 3]) + __ldg(&beta[cc + 3]), 0.f);
                if (EPI == 1) {
                    float4 rv = *(const float4*)(res + (size_t)grow * 128 + cc);
                    o.x += rv.x; o.y += rv.y; o.z += rv.z; o.w += rv.w;
                }
                if (EPI == 0) {
                    *(float4*)(out + (size_t)grow * 128 + cc) = o;
                }
                *(uint2*)(out16 + (size_t)grow * 128 + cc) = pack4_f16(o.x, o.y, o.z, o.w);
            }
        }
    } else if constexpr (EPI == 2) {
        // GRU gate quads: 128 gemm cols -> 32 h cols; 4 threads/row, 8 quads each
        int r = tid >> 2, seg = tid & 3;
        int grow = row0 + r;
        if (grow < n) {
            int lc0 = seg * 32;
            float hv[8];
#pragma unroll
            for (int q = 0; q < 8; q++) {
                int lc = lc0 + q * 4;
                int gcol = jbase + lc;
                float cr = Cs[r * LDC + lc + 0] + __ldg(&bias[gcol + 0]);
                float cz = Cs[r * LDC + lc + 1] + __ldg(&bias[gcol + 1]);
                float ci = Cs[r * LDC + lc + 2] + __ldg(&bias[gcol + 2]);
                float ch = Cs[r * LDC + lc + 3] + __ldg(&bias[gcol + 3]);
                float rg = sigf(cr);
                float z = sigf(cz);
                float ng = tanhf(ci + rg * ch);
                float hp = res[(size_t)grow * 128 + ((jbase + lc0) >> 2) + q];
                hv[q] = (1.f - z) * ng + z * hp;
            }
            int j0 = ((jbase + lc0) >> 2);
            *(float4*)(out + (size_t)grow * 128 + j0) = make_float4(hv[0], hv[1], hv[2], hv[3]);
            *(float4*)(out + (size_t)grow * 128 + j0 + 4) = make_float4(hv[4], hv[5], hv[6], hv[7]);
            *(uint2*)(out16 + (size_t)grow * 128 + j0) = pack4_f16(hv[0], hv[1], hv[2], hv[3]);
            *(uint2*)(out16 + (size_t)grow * 128 + j0 + 4) = pack4_f16(hv[4], hv[5], hv[6], hv[7]);
        }
    } else {  // EPI == 3: bias+relu, BN=64, out stride 64 (fp32)
        int r = tid >> 1, seg = tid & 1;
        int grow = row0 + r;
        if (grow < n) {
#pragma unroll
            for (int q = 0; q < 8; q++) {
                int cc = seg * 32 + q * 4;
                float4 c4 = *(float4*)&Cs[r * LDC + cc];
                float4 o;
                o.x = fmaxf(c4.x + __ldg(&bias[cc + 0]), 0.f);
                o.y = fmaxf(c4.y + __ldg(&bias[cc + 1]), 0.f);
                o.z = fmaxf(c4.z + __ldg(&bias[cc + 2]), 0.f);
                o.w = fmaxf(c4.w + __ldg(&bias[cc + 3]), 0.f);
                *(float4*)(out + (size_t)grow * 64 + cc) = o;
            }
        }
    }
}

// ----------------- CSR build + misc -----------------
__global__ void k_zero_f4(float4* p, int c4) {
    int i = blockIdx.x * blockDim.x + threadIdx.x;
    if (i < c4) p[i] = make_float4(0.f, 0.f, 0.f, 0.f);
}
__global__ void k_zero_u4(uint4* p, int c4) {
    int i = blockIdx.x * blockDim.x + threadIdx.x;
    if (i < c4) p[i] = make_uint4(0u, 0u, 0u, 0u);
}
__global__ void k_zero_i(int* p, int c) {
    int i = blockIdx.x * blockDim.x + threadIdx.x;
    if (i < c) p[i] = 0;
}
__global__ void k_hist(const int* __restrict__ dst, int e, int* __restrict__ cnt) {
    int i = blockIdx.x * blockDim.x + threadIdx.x;
    if (i < e) atomicAdd(&cnt[dst[i]], 1);
}
__global__ void k_copy_i(const int* __restrict__ a, int* __restrict__ b, int c) {
    int i = blockIdx.x * blockDim.x + threadIdx.x;
    if (i < c) b[i] = a[i];
}
__global__ void k_fill(const int* __restrict__ src, const int* __restrict__ dst, int e,
                       int* __restrict__ cur, int* __restrict__ colidx) {
    int i = blockIdx.x * blockDim.x + threadIdx.x;
    if (i < e) {
        int p = atomicAdd(&cur[dst[i]], 1);
        colidx[p] = src[i];
    }
}
__global__ void k_sortseg(const int* __restrict__ rp, int* __restrict__ ci, int n) {
    int v = blockIdx.x * blockDim.x + threadIdx.x;
    if (v >= n) return;
    int s = rp[v], e = rp[v + 1];
    for (int i = s + 1; i < e; i++) {
        int key = ci[i];
        int j = i - 1;
        while (j >= s && ci[j] > key) { ci[j + 1] = ci[j]; j--; }
        ci[j + 1] = key;
    }
}
__global__ void k_scan(const int* __restrict__ cnt, int* __restrict__ rowptr, int n) {
    __shared__ int wsums[32];
    __shared__ int s_carry;
    int tid = threadIdx.x;
    int lane = tid & 31, wid = tid >> 5;
    if (tid == 0) s_carry = 0;
    __syncthreads();
    for (int base = 0; base < n; base += 1024) {
        int i = base + tid;
        int v = (i < n) ? cnt[i] : 0;
        int x = v;
#pragma unroll
        for (int o = 1; o < 32; o <<= 1) {
            int t = __shfl_up_sync(0xffffffffu, x, o);
            if (lane >= o) x += t;
        }
        if (lane == 31) wsums[wid] = x;
        __syncthreads();
        if (tid < 32) {
            int s = wsums[tid];
#pragma unroll
            for (int o = 1; o < 32; o <<= 1) {
                int t = __shfl_up_sync(0xffffffffu, s, o);
                if (tid >= o) s += t;
            }
            wsums[tid] = s;
        }
        __syncthreads();
        int incl = x + ((wid > 0) ? wsums[wid - 1] : 0);
        int excl = s_carry + incl - v;
        if (i < n) rowptr[i] = excl;
        int blocktot = wsums[31];
        __syncthreads();
        if (tid == 0) s_carry += blocktot;
        __syncthreads();
    }
    if (tid == 0) rowptr[n] = s_carry;
}

// ----------------- weight / input prep (write fp16 directly; RN = same bits as cvt-at-stage) ---
__global__ void k_cvt_x16(const float4* __restrict__ in, uint2* __restrict__ out, int c4) {
    int i = blockIdx.x * blockDim.x + threadIdx.x;
    if (i >= c4) return;
    float4 v = in[i];
    out[i] = pack4_f16(v.x, v.y, v.z, v.w);
}
__global__ void k_prep_c0(const float* __restrict__ Wn, const float* __restrict__ Ws,
                          __half* __restrict__ o) {
    int idx = blockIdx.x * blockDim.x + threadIdx.x;
    if (idx >= 128 * 128) return;
    int nn = idx >> 7, k = idx & 127;
    float w = (k < 64) ? Wn[k * 128 + nn] : Ws[(k - 64) * 128 + nn];
    o[idx] = __float2half_rn(w);
}
__global__ void k_prep_c1(const float* __restrict__ Wn, const float* __restrict__ Ws,
                          __half* __restrict__ o) {
    int idx = blockIdx.x * blockDim.x + threadIdx.x;
    if (idx >= 128 * 256) return;
    int nn = idx >> 8, k = idx & 255;
    float w = (k < 128) ? Wn[k * 128 + nn] : Ws[(k - 128) * 128 + nn];
    o[idx] = __float2half_rn(w);
}
__global__ void k_prep_qt(const float* __restrict__ Wih, const float* __restrict__ Whh,
                          const float* __restrict__ bih, const float* __restrict__ bhh,
                          __half* __restrict__ o, float* __restrict__ bq) {
    int idx = blockIdx.x * blockDim.x + threadIdx.x;
    if (idx >= 512 * 256) return;
    int c = idx >> 8, k = idx & 255;
    int j = c >> 2, g = c & 3;
    float w = 0.f;
    if (k < 128) {
        if (g == 0)      w = Wih[j * 128 + k];
        else if (g == 1) w = Wih[(128 + j) * 128 + k];
        else if (g == 2) w = Wih[(256 + j) * 128 + k];
    } else {
        int kk = k - 128;
        if (g == 0)      w = Whh[j * 128 + kk];
        else if (g == 1) w = Whh[(128 + j) * 128 + kk];
        else if (g == 3) w = Whh[(256 + j) * 128 + kk];
    }
    o[idx] = __float2half_rn(w);
    if (idx < 512) {
        int jj = idx >> 2, gg = idx & 3;
        bq[idx] = (gg == 0) ? bih[jj] + bhh[jj]
                : (gg == 1) ? bih[128 + jj] + bhh[128 + jj]
                : (gg == 2) ? bih[256 + jj]
                            : bhh[256 + jj];
    }
}
__global__ void k_prep_cls(const float* __restrict__ W, __half* __restrict__ o) {
    int idx = blockIdx.x * blockDim.x + threadIdx.x;
    if (idx >= 64 * 128) return;
    int oo = idx >> 7, k = idx & 127;
    o[idx] = __float2half_rn(W[k * 64 + oo]);
}

// ----------------- mean aggregation (warp per node, fp32 gather -> fp16 store) -----------------
__global__ void __launch_bounds__(256) k_agg64(const float* __restrict__ x, __half* __restrict__ out,
                                               const int* __restrict__ rp, const int* __restrict__ ci, int n) {
    int w = (blockIdx.x * blockDim.x + threadIdx.x) >> 5;
    if (w >= n) return;
    int lane = threadIdx.x & 31;
    int s0 = rp[w], s1 = rp[w + 1];
    float ax = 0.f, ay = 0.f;
    int e = s0;
    for (; e + 4 <= s1; e += 4) {
        int i0 = ci[e], i1 = ci[e + 1], i2 = ci[e + 2], i3 = ci[e + 3];
        float2 v0 = *(const float2*)(x + (size_t)i0 * 64 + lane * 2);
        float2 v1 = *(const float2*)(x + (size_t)i1 * 64 + lane * 2);
        float2 v2 = *(const float2*)(x + (size_t)i2 * 64 + lane * 2);
        float2 v3 = *(const float2*)(x + (size_t)i3 * 64 + lane * 2);
        ax += (v0.x + v1.x) + (v2.x + v3.x);
        ay += (v0.y + v1.y) + (v2.y + v3.y);
    }
    for (; e < s1; e++) {
        int i0 = ci[e];
        float2 v0 = *(const float2*)(x + (size_t)i0 * 64 + lane * 2);
        ax += v0.x; ay += v0.y;
    }
    int d = s1 - s0; if (d < 1) d = 1;
    float inv = 1.f / (float)d;
    __half2 h = __floats2half2_rn(ax * inv, ay * inv);
    *(__half2*)(out + (size_t)w * 64 + lane * 2) = h;
}
__global__ void __launch_bounds__(256) k_agg128(const float* __restrict__ x, __half* __restrict__ out,
                                                const int* __restrict__ rp, const int* __restrict__ ci, int n) {
    int w = (blockIdx.x * blockDim.x + threadIdx.x) >> 5;
    if (w >= n) return;
    int lane = threadIdx.x & 31;
    int s0 = rp[w], s1 = rp[w + 1];
    float4 acc = make_float4(0.f, 0.f, 0.f, 0.f);
    int e = s0;
    for (; e + 4 <= s1; e += 4) {
        int i0 = ci[e], i1 = ci[e + 1], i2 = ci[e + 2], i3 = ci[e + 3];
        float4 v0 = *(const float4*)(x + (size_t)i0 * 128 + lane * 4);
        float4 v1 = *(const float4*)(x + (size_t)i1 * 128 + lane * 4);
        float4 v2 = *(const float4*)(x + (size_t)i2 * 128 + lane * 4);
        float4 v3 = *(const float4*)(x + (size_t)i3 * 128 + lane * 4);
        acc.x += (v0.x + v1.x) + (v2.x + v3.x);
        acc.y += (v0.y + v1.y) + (v2.y + v3.y);
        acc.z += (v0.z + v1.z) + (v2.z + v3.z);
        acc.w += (v0.w + v1.w) + (v2.w + v3.w);
    }
    for (; e < s1; e++) {
        int i0 = ci[e];
        float4 v0 = *(const float4*)(x + (size_t)i0 * 128 + lane * 4);
        acc.x += v0.x; acc.y += v0.y; acc.z += v0.z; acc.w += v0.w;
    }
    int d = s1 - s0; if (d < 1) d = 1;
    float inv = 1.f / (float)d;
    *(uint2*)(out + (size_t)w * 128 + lane * 4) =
        pack4_f16(acc.x * inv, acc.y * inv, acc.z * inv, acc.w * inv);
}

// final logits: warp per row, zc[64] @ W2[64,2] + b2
__global__ void __launch_bounds__(256) k_logits(const float* __restrict__ zc,
                                                const float* __restrict__ W2,
                                                const float* __restrict__ b2,
                                                float* __restrict__ out, int n) {
    int w = (blockIdx.x * blockDim.x + threadIdx.x) >> 5;
    if (w >= n) return;
    int lane = threadIdx.x & 31;
    float z0 = zc[(size_t)w * 64 + lane];
    float z1 = zc[(size_t)w * 64 + 32 + lane];
    float a0 = z0 * W2[lane * 2 + 0] + z1 * W2[(lane + 32) * 2 + 0];
    float a1 = z0 * W2[lane * 2 + 1] + z1 * W2[(lane + 32) * 2 + 1];
#pragma unroll
    for (int o = 16; o > 0; o >>= 1) {
        a0 += __shfl_xor_sync(0xffffffffu, a0, o);
        a1 += __shfl_xor_sync(0xffffffffu, a1, o);
    }
    if (lane == 0) {
        out[(size_t)w * 2 + 0] = a0 + b2[0];
        out[(size_t)w * 2 + 1] = a1 + b2[1];
    }
}

// ----------------- host launch -----------------
extern "C" void kernel_launch(void* const* d_in, const int* in_sizes, int n_in,
                              void* d_out, int out_size) {
    const int N = N_NODES, E = N_EDGES;

    const float* x_seq = nullptr;
    const int* eidx = nullptr;
    const float* Wt[18];
    int wi = 0;
    for (int i = 0; i < n_in; i++) {
        if (in_sizes[i] == 2 * E) eidx = (const int*)d_in[i];
        else if (in_sizes[i] == T_STEPS * N * 64) x_seq = (const float*)d_in[i];
        else if (wi < 18) Wt[wi++] = (const float*)d_in[i];
    }
    const float *Wn0 = Wt[0], *Ws0 = Wt[1], *b0 = Wt[2], *g0 = Wt[3], *be0 = Wt[4];
    const float *Wn1 = Wt[5], *Ws1 = Wt[6], *b1 = Wt[7], *g1 = Wt[8], *be1 = Wt[9];
    const float *gWih = Wt[10], *gWhh = Wt[11], *gbih = Wt[12], *gbhh = Wt[13];
    const float *cW1 = Wt[14], *cb1 = Wt[15], *cW2 = Wt[16], *cb2 = Wt[17];

    __half *x16, *agg16, *h016, *h116, *hA16, *hB16, *Wc0t16, *Wc1t16, *Wqt16, *cW1t16;
    float *h0f, *hAf, *hBf, *zc, *bq;
    int *cnt, *rp, *cur, *ci;
    cudaGetSymbolAddress((void**)&x16, g_x16);
    cudaGetSymbolAddress((void**)&agg16, g_agg16);
    cudaGetSymbolAddress((void**)&h016, g_h016);
    cudaGetSymbolAddress((void**)&h116, g_h116);
    cudaGetSymbolAddress((void**)&hA16, g_hA16);
    cudaGetSymbolAddress((void**)&hB16, g_hB16);
    cudaGetSymbolAddress((void**)&Wc0t16, g_Wc0t16);
    cudaGetSymbolAddress((void**)&Wc1t16, g_Wc1t16);
    cudaGetSymbolAddress((void**)&Wqt16, g_Wqt16);
    cudaGetSymbolAddress((void**)&cW1t16, g_cW1t16);
    cudaGetSymbolAddress((void**)&h0f, g_h0f);
    cudaGetSymbolAddress((void**)&hAf, g_hAf);
    cudaGetSymbolAddress((void**)&hBf, g_hBf);
    cudaGetSymbolAddress((void**)&zc, g_zc);
    cudaGetSymbolAddress((void**)&bq, g_bq);
    cudaGetSymbolAddress((void**)&cnt, g_cnt);
    cudaGetSymbolAddress((void**)&rp, g_rowptr);
    cudaGetSymbolAddress((void**)&cur, g_cur);
    cudaGetSymbolAddress((void**)&ci, g_colidx);

    const int* src = eidx;
    const int* dst = eidx + E;

    // dynamic smem: max(double-buffered fp16 stage, fp32 epilogue C tile), bytes
    // stage = 2*(BM+BN)*72*2 = 2*192*144 = 55296 for both tile shapes
    // Cs: EPI0/1/2 = 64*136*4 = 34816 ; EPI3 = 128*72*4 = 36864
    const int SM_A = 55296;
    const int SM_B = 55296;
    cudaFuncSetAttribute((const void*)k_wmma<64, 128, 2, 4, 0>, cudaFuncAttributeMaxDynamicSharedMemorySize, SM_A);
    cudaFuncSetAttribute((const void*)k_wmma<64, 128, 2, 4, 1>, cudaFuncAttributeMaxDynamicSharedMemorySize, SM_A);
    cudaFuncSetAttribute((const void*)k_wmma<64, 128, 2, 4, 2>, cudaFuncAttributeMaxDynamicSharedMemorySize, SM_A);
    cudaFuncSetAttribute((const void*)k_wmma<128, 64, 4, 2, 3>, cudaFuncAttributeMaxDynamicSharedMemorySize, SM_B);

    // ---- build CSR (deterministic after per-segment sort) ----
    k_zero_i<<<(N + 255) / 256, 256>>>(cnt, N);
    k_hist<<<(E + 255) / 256, 256>>>(dst, E, cnt);
    k_scan<<<1, 1024>>>(cnt, rp, N);
    k_copy_i<<<(N + 255) / 256, 256>>>(rp, cur, N);
    k_fill<<<(E + 255) / 256, 256>>>(src, dst, E, cur, ci);
    k_sortseg<<<(N + 255) / 256, 256>>>(rp, ci, N);

    // ---- init GRU state (both copies) + fp16 weight/input prep ----
    k_zero_f4<<<(N * 128 / 4 + 255) / 256, 256>>>((float4*)hAf, N * 128 / 4);
    k_zero_u4<<<(N * 128 / 8 + 255) / 256, 256>>>((uint4*)hA16, N * 128 / 8);
    k_cvt_x16<<<((T_STEPS * N * 64 / 4) + 255) / 256, 256>>>(
        (const float4*)x_seq, (uint2*)x16, T_STEPS * N * 64 / 4);
    k_prep_c0<<<(128 * 128 + 255) / 256, 256>>>(Wn0, Ws0, Wc0t16);
    k_prep_c1<<<(128 * 256 + 255) / 256, 256>>>(Wn1, Ws1, Wc1t16);
    k_prep_qt<<<(512 * 256 + 255) / 256, 256>>>(gWih, gWhh, gbih, gbhh, Wqt16, bq);
    k_prep_cls<<<(64 * 128 + 255) / 256, 256>>>(cW1, cW1t16);

    const int GRID64  = (N + 63) / 64;    // 1563 (BM=64 kernels)
    const int GRID128 = (N + 127) / 128;  // 782  (classifier)
    const int AGG_GRID = (N + 7) / 8;

    float* hprevf = hAf;
    float* hnextf = hBf;
    __half* hprev16 = hA16;
    __half* hnext16 = hB16;
    for (int t = 0; t < T_STEPS; t++) {
        const float* xt = x_seq + (size_t)t * N * 64;
        const __half* xt16 = x16 + (size_t)t * N * 64;
        // SAGE layer 0: LN+ReLU -> h0 (fp32 + fp16)
        k_agg64<<<AGG_GRID, 256>>>(xt, agg16, rp, ci, N);
        k_wmma<64, 128, 2, 4, 0><<<dim3(GRID64, 1), 256, SM_A>>>(
            agg16, 64, xt16, 64, Wc0t16, 128, b0, g0, be0, nullptr, h0f, h016, N);
        // SAGE layer 1: LN+ReLU + residual(h0) -> h1 (fp16 only)
        k_agg128<<<AGG_GRID, 256>>>(h0f, agg16, rp, ci, N);
        k_wmma<64, 128, 2, 4, 1><<<dim3(GRID64, 1), 256, SM_A>>>(
            agg16, 128, h016, 128, Wc1t16, 256, b1, g1, be1, h0f, nullptr, h116, N);
        // GRU step (gate-quad epilogue) -> hnext (fp32 + fp16)
        k_wmma<64, 128, 2, 4, 2><<<dim3(GRID64, 4), 256, SM_A>>>(
            h116, 128, hprev16, 128, Wqt16, 256, bq, nullptr, nullptr, hprevf, hnextf, hnext16, N);
        float* tf = hprevf; hprevf = hnextf; hnextf = tf;
        __half* th = hprev16; hprev16 = hnext16; hnext16 = th;
    }
    // classifier (A1 = final hidden, fp16)
    k_wmma<128, 64, 4, 2, 3><<<dim3(GRID128, 1), 256, SM_B>>>(
        hprev16, 128, nullptr, 0, cW1t16, 128, cb1, nullptr, nullptr, nullptr, zc, nullptr, N);
    k_logits<<<AGG_GRID, 256>>>(zc, cW2, cb2, (float*)d_out, N);
}

// round 10
// speedup vs baseline: 2.4095x; 1.0797x over previous
#include <cuda_runtime.h>
#include <cuda_bf16.h>
#include <cuda_fp16.h>
#include <mma.h>
#include <cstdint>

using namespace nvcuda;

#define N_NODES 100000
#define N_EDGES 1600000
#define T_STEPS 12

// ----------------- static device scratch -----------------
// fp16 arrays declared as uint4 for 16B alignment (cast to __half*)
__device__ uint4 g_x16 [(size_t)T_STEPS * N_NODES * 64 / 8];  // fp16 copy of x_seq
__device__ uint4 g_agg16[(size_t)N_NODES * 128 / 8];
__device__ uint4 g_h016 [(size_t)N_NODES * 128 / 8];
__device__ uint4 g_h116 [(size_t)N_NODES * 128 / 8];
__device__ uint4 g_hA16 [(size_t)N_NODES * 128 / 8];
__device__ uint4 g_hB16 [(size_t)N_NODES * 128 / 8];
__device__ uint4 g_Wc0t16[128 * 128 / 8];   // [N=128, K=128] = [Wn0 | Ws0]^T  (K-major)
__device__ uint4 g_Wc1t16[128 * 256 / 8];   // [N=128, K=256] = [Wn1 | Ws1]^T
__device__ uint4 g_Wqt16 [512 * 256 / 8];   // [N=512 gate-quads, K=256]
__device__ uint4 g_cW1t16[64 * 128 / 8];    // [N=64, K=128]
// fp32 arrays (GRU state / classifier / epilogue use)
__device__ float g_hAf[(size_t)N_NODES * 128];
__device__ float g_hBf[(size_t)N_NODES * 128];
__device__ float g_zc [(size_t)N_NODES * 64];
__device__ float g_bq [512];
__device__ int   g_cnt   [N_NODES];
__device__ int   g_rowptr[N_NODES + 1];
__device__ int   g_cur   [N_NODES];
__device__ int   g_colidx[N_EDGES];

__device__ __forceinline__ float sigf(float x) { return 1.f / (1.f + expf(-x)); }

__device__ __forceinline__ uint2 pack4_f16(float a, float b, float c, float d) {
    __half2 lo = __floats2half2_rn(a, b);
    __half2 hi = __floats2half2_rn(c, d);
    uint2 u;
    u.x = *(uint32_t*)&lo;
    u.y = *(uint32_t*)&hi;
    return u;
}
__device__ __forceinline__ void unpack4_f16(uint2 u, float* o) {
    __half2 lo = *(__half2*)&u.x;
    __half2 hi = *(__half2*)&u.y;
    float2 a = __half22float2(lo);
    float2 b = __half22float2(hi);
    o[0] = a.x; o[1] = a.y; o[2] = b.x; o[3] = b.y;
}

// ----------------- wmma fp16 GEMM (fp32 accum), all-fp16 operands, K-chunk 64 -----------------
// D[row, jbase+c] = epi( A1[row,:K1]@Bt[jbase+c,:K1]^T + A2[row,:K2]@Bt[...,K1:]^T )
// A1/A2/Bt are fp16, K-major. K in chunks of 64 (4x k16 MMA), ping-pong smem buffers.
// EPI 0: bias+LayerNorm+ReLU            (BM=64, BN=128) -> out16 fp16
// EPI 1: bias+LayerNorm+ReLU+residual16 (BM=64, BN=128) -> out16 fp16 (res16 = fp16 residual)
// EPI 2: GRU gate-quad update           (BM=64, BN=128, grid.y=4; res = fp32 h_prev) -> out fp32 + out16 fp16
// EPI 3: bias+ReLU                      (BM=128, BN=64) -> out fp32 (stride 64)
template <int BM, int BN, int WR, int WC, int EPI>
__global__ void __launch_bounds__(256) k_wmma(
    const __half* __restrict__ A1, int K1,
    const __half* __restrict__ A2, int K2,
    const __half* __restrict__ Bt, int Ktot,
    const float* __restrict__ bias,
    const float* __restrict__ gamma, const float* __restrict__ beta,
    const float* __restrict__ res, const __half* __restrict__ res16,
    float* __restrict__ out, __half* __restrict__ out16, int n)
{
    constexpr int LDH = 72;            // halfs per row = 144B (16B-aligned frag ptrs, ldm%8==0)
    constexpr int LDC = BN + 8;
    constexpr int ASZ = BM * LDH;
    constexpr int BSZ = BN * LDH;
    constexpr int MI = BM / WR / 16;   // 2
    constexpr int NI = BN / WC / 16;   // 2
    constexpr int AIT = BM / 32;
    constexpr int BIT = BN / 32;
    extern __shared__ __align__(256) char smem_raw[];
    __half* Hs = (__half*)smem_raw;
    float* Cs = (float*)smem_raw;

    const int tid = threadIdx.x;
    const int wid = tid >> 5;
    const int wr = wid / WC, wc = wid % WC;
    const int row0 = blockIdx.x * BM;
    const int jbase = blockIdx.y * BN;

    wmma::fragment<wmma::accumulator, 16, 16, 16, float> acc[MI][NI];
#pragma unroll
    for (int mi = 0; mi < MI; mi++)
#pragma unroll
        for (int ni = 0; ni < NI; ni++) wmma::fill_fragment(acc[mi][ni], 0.f);

    const int nc = Ktot / 64;
    uint4 pa[AIT], pb[BIT];

    auto ldg_chunk = [&](int c) {
        int kg = c * 64;
        const __half* Asrc; int Kph, koff;
        if (kg < K1) { Asrc = A1; Kph = K1; koff = kg; }
        else         { Asrc = A2; Kph = K2; koff = kg - K1; }
#pragma unroll
        for (int it = 0; it < AIT; it++) {
            int idx = it * 256 + tid;
            int r = idx >> 3, q = idx & 7;
            int grow = row0 + r;
            pa[it] = (grow < n) ? *(const uint4*)(Asrc + (size_t)grow * Kph + koff + q * 8)
                                : make_uint4(0u, 0u, 0u, 0u);
        }
#pragma unroll
        for (int it = 0; it < BIT; it++) {
            int idx = it * 256 + tid;
            int r = idx >> 3, q = idx & 7;
            pb[it] = *(const uint4*)(Bt + (size_t)(jbase + r) * Ktot + kg + q * 8);
        }
    };
    auto sts_chunk = [&](int s) {
        __half* As = Hs + s * ASZ;
        __half* Bs = Hs + 2 * ASZ + s * BSZ;
#pragma unroll
        for (int it = 0; it < AIT; it++) {
            int idx = it * 256 + tid;
            int r = idx >> 3, q = idx & 7;
            *(uint4*)(&As[r * LDH + q * 8]) = pa[it];
        }
#pragma unroll
        for (int it = 0; it < BIT; it++) {
            int idx = it * 256 + tid;
            int r = idx >> 3, q = idx & 7;
            *(uint4*)(&Bs[r * LDH + q * 8]) = pb[it];
        }
    };

    ldg_chunk(0);
    sts_chunk(0);
    __syncthreads();

    for (int c = 0; c < nc; c++) {
        int s = c & 1;
        if (c + 1 < nc) ldg_chunk(c + 1);
        const __half* As = Hs + s * ASZ;
        const __half* Bs = Hs + 2 * ASZ + s * BSZ;
#pragma unroll
        for (int ks = 0; ks < 4; ks++) {
            wmma::fragment<wmma::matrix_a, 16, 16, 16, __half, wmma::row_major> af[MI];
            wmma::fragment<wmma::matrix_b, 16, 16, 16, __half, wmma::col_major> bf[NI];
#pragma unroll
            for (int mi = 0; mi < MI; mi++)
                wmma::load_matrix_sync(af[mi], As + (wr * (BM / WR) + mi * 16) * LDH + ks * 16, LDH);
#pragma unroll
            for (int ni = 0; ni < NI; ni++)
                wmma::load_matrix_sync(bf[ni], Bs + (wc * (BN / WC) + ni * 16) * LDH + ks * 16, LDH);
#pragma unroll
            for (int mi = 0; mi < MI; mi++)
#pragma unroll
                for (int ni = 0; ni < NI; ni++)
                    wmma::mma_sync(acc[mi][ni], af[mi], bf[ni], acc[mi][ni]);
        }
        if (c + 1 < nc) sts_chunk(s ^ 1);
        __syncthreads();
    }

#pragma unroll
    for (int mi = 0; mi < MI; mi++)
#pragma unroll
        for (int ni = 0; ni < NI; ni++)
            wmma::store_matrix_sync(Cs + (wr * (BM / WR) + mi * 16) * LDC + wc * (BN / WC) + ni * 16,
                                    acc[mi][ni], LDC, wmma::mem_row_major);
    __syncthreads();

    // ------------- epilogues (fp32 math identical to prior rounds) -------------
    if constexpr (EPI == 0 || EPI == 1) {
        int r = tid >> 2, seg = tid & 3;
        int grow = row0 + r;
        float v[32];
        float sum = 0.f, sq = 0.f;
#pragma unroll
        for (int q = 0; q < 8; q++) {
            float4 c4 = *(float4*)&Cs[r * LDC + seg * 32 + q * 4];
            float b0v = __ldg(&bias[seg * 32 + q * 4 + 0]);
            float b1v = __ldg(&bias[seg * 32 + q * 4 + 1]);
            float b2v = __ldg(&bias[seg * 32 + q * 4 + 2]);
            float b3v = __ldg(&bias[seg * 32 + q * 4 + 3]);
            v[q * 4 + 0] = c4.x + b0v; v[q * 4 + 1] = c4.y + b1v;
            v[q * 4 + 2] = c4.z + b2v; v[q * 4 + 3] = c4.w + b3v;
#pragma unroll
            for (int u = 0; u < 4; u++) { sum += v[q * 4 + u]; sq += v[q * 4 + u] * v[q * 4 + u]; }
        }
        sum += __shfl_xor_sync(0xffffffffu, sum, 1);
        sq  += __shfl_xor_sync(0xffffffffu, sq, 1);
        sum += __shfl_xor_sync(0xffffffffu, sum, 2);
        sq  += __shfl_xor_sync(0xffffffffu, sq, 2);
        float mean = sum * (1.f / 128.f);
        float var = sq * (1.f / 128.f) - mean * mean;
        float rs = rsqrtf(var + 1e-5f);
        if (grow < n) {
#pragma unroll
            for (int q = 0; q < 8; q++) {
                int cc = seg * 32 + q * 4;
                float4 o;
                o.x = fmaxf((v[q * 4 + 0] - mean) * rs * __ldg(&gamma[cc + 0]) + __ldg(&beta[cc + 0]), 0.f);
                o.y = fmaxf((v[q * 4 + 1] - mean) * rs * __ldg(&gamma[cc + 1]) + __ldg(&beta[cc + 1]), 0.f);
                o.z = fmaxf((v[q * 4 + 2] - mean) * rs * __ldg(&gamma[cc + 2]) + __ldg(&beta[cc + 2]), 0.f);
                o.w = fmaxf((v[q * 4 + 3] - mean) * rs * __ldg(&gamma[cc + 3]) + __ldg(&beta[cc + 3]), 0.f);
                if (EPI == 1) {
                    uint2 r16 = *(const uint2*)(res16 + (size_t)grow * 128 + cc);
                    float rv[4];
                    unpack4_f16(r16, rv);
                    o.x += rv[0]; o.y += rv[1]; o.z += rv[2]; o.w += rv[3];
                }
                *(uint2*)(out16 + (size_t)grow * 128 + cc) = pack4_f16(o.x, o.y, o.z, o.w);
            }
        }
    } else if constexpr (EPI == 2) {
        int r = tid >> 2, seg = tid & 3;
        int grow = row0 + r;
        if (grow < n) {
            int lc0 = seg * 32;
            float hv[8];
#pragma unroll
            for (int q = 0; q < 8; q++) {
                int lc = lc0 + q * 4;
                int gcol = jbase + lc;
                float cr = Cs[r * LDC + lc + 0] + __ldg(&bias[gcol + 0]);
                float cz = Cs[r * LDC + lc + 1] + __ldg(&bias[gcol + 1]);
                float ci = Cs[r * LDC + lc + 2] + __ldg(&bias[gcol + 2]);
                float ch = Cs[r * LDC + lc + 3] + __ldg(&bias[gcol + 3]);
                float rg = sigf(cr);
                float z = sigf(cz);
                float ng = tanhf(ci + rg * ch);
                float hp = res[(size_t)grow * 128 + ((jbase + lc0) >> 2) + q];
                hv[q] = (1.f - z) * ng + z * hp;
            }
            int j0 = ((jbase + lc0) >> 2);
            *(float4*)(out + (size_t)grow * 128 + j0) = make_float4(hv[0], hv[1], hv[2], hv[3]);
            *(float4*)(out + (size_t)grow * 128 + j0 + 4) = make_float4(hv[4], hv[5], hv[6], hv[7]);
            *(uint2*)(out16 + (size_t)grow * 128 + j0) = pack4_f16(hv[0], hv[1], hv[2], hv[3]);
            *(uint2*)(out16 + (size_t)grow * 128 + j0 + 4) = pack4_f16(hv[4], hv[5], hv[6], hv[7]);
        }
    } else {  // EPI == 3: bias+relu, BN=64, out stride 64 (fp32)
        int r = tid >> 1, seg = tid & 1;
        int grow = row0 + r;
        if (grow < n) {
#pragma unroll
            for (int q = 0; q < 8; q++) {
                int cc = seg * 32 + q * 4;
                float4 c4 = *(float4*)&Cs[r * LDC + cc];
                float4 o;
                o.x = fmaxf(c4.x + __ldg(&bias[cc + 0]), 0.f);
                o.y = fmaxf(c4.y + __ldg(&bias[cc + 1]), 0.f);
                o.z = fmaxf(c4.z + __ldg(&bias[cc + 2]), 0.f);
                o.w = fmaxf(c4.w + __ldg(&bias[cc + 3]), 0.f);
                *(float4*)(out + (size_t)grow * 64 + cc) = o;
            }
        }
    }
}

// ----------------- CSR build + misc -----------------
__global__ void k_zero_f4(float4* p, int c4) {
    int i = blockIdx.x * blockDim.x + threadIdx.x;
    if (i < c4) p[i] = make_float4(0.f, 0.f, 0.f, 0.f);
}
__global__ void k_zero_u4(uint4* p, int c4) {
    int i = blockIdx.x * blockDim.x + threadIdx.x;
    if (i < c4) p[i] = make_uint4(0u, 0u, 0u, 0u);
}
__global__ void k_zero_i(int* p, int c) {
    int i = blockIdx.x * blockDim.x + threadIdx.x;
    if (i < c) p[i] = 0;
}
__global__ void k_hist(const int* __restrict__ dst, int e, int* __restrict__ cnt) {
    int i = blockIdx.x * blockDim.x + threadIdx.x;
    if (i < e) atomicAdd(&cnt[dst[i]], 1);
}
__global__ void k_copy_i(const int* __restrict__ a, int* __restrict__ b, int c) {
    int i = blockIdx.x * blockDim.x + threadIdx.x;
    if (i < c) b[i] = a[i];
}
__global__ void k_fill(const int* __restrict__ src, const int* __restrict__ dst, int e,
                       int* __restrict__ cur, int* __restrict__ colidx) {
    int i = blockIdx.x * blockDim.x + threadIdx.x;
    if (i < e) {
        int p = atomicAdd(&cur[dst[i]], 1);
        colidx[p] = src[i];
    }
}
__global__ void k_sortseg(const int* __restrict__ rp, int* __restrict__ ci, int n) {
    int v = blockIdx.x * blockDim.x + threadIdx.x;
    if (v >= n) return;
    int s = rp[v], e = rp[v + 1];
    for (int i = s + 1; i < e; i++) {
        int key = ci[i];
        int j = i - 1;
        while (j >= s && ci[j] > key) { ci[j + 1] = ci[j]; j--; }
        ci[j + 1] = key;
    }
}
__global__ void k_scan(const int* __restrict__ cnt, int* __restrict__ rowptr, int n) {
    __shared__ int wsums[32];
    __shared__ int s_carry;
    int tid = threadIdx.x;
    int lane = tid & 31, wid = tid >> 5;
    if (tid == 0) s_carry = 0;
    __syncthreads();
    for (int base = 0; base < n; base += 1024) {
        int i = base + tid;
        int v = (i < n) ? cnt[i] : 0;
        int x = v;
#pragma unroll
        for (int o = 1; o < 32; o <<= 1) {
            int t = __shfl_up_sync(0xffffffffu, x, o);
            if (lane >= o) x += t;
        }
        if (lane == 31) wsums[wid] = x;
        __syncthreads();
        if (tid < 32) {
            int s = wsums[tid];
#pragma unroll
            for (int o = 1; o < 32; o <<= 1) {
                int t = __shfl_up_sync(0xffffffffu, s, o);
                if (tid >= o) s += t;
            }
            wsums[tid] = s;
        }
        __syncthreads();
        int incl = x + ((wid > 0) ? wsums[wid - 1] : 0);
        int excl = s_carry + incl - v;
        if (i < n) rowptr[i] = excl;
        int blocktot = wsums[31];
        __syncthreads();
        if (tid == 0) s_carry += blocktot;
        __syncthreads();
    }
    if (tid == 0) rowptr[n] = s_carry;
}

// ----------------- weight / input prep -----------------
__global__ void k_cvt_x16(const float4* __restrict__ in, uint2* __restrict__ out, int c4) {
    int i = blockIdx.x * blockDim.x + threadIdx.x;
    if (i >= c4) return;
    float4 v = in[i];
    out[i] = pack4_f16(v.x, v.y, v.z, v.w);
}
__global__ void k_prep_c0(const float* __restrict__ Wn, const float* __restrict__ Ws,
                          __half* __restrict__ o) {
    int idx = blockIdx.x * blockDim.x + threadIdx.x;
    if (idx >= 128 * 128) return;
    int nn = idx >> 7, k = idx & 127;
    float w = (k < 64) ? Wn[k * 128 + nn] : Ws[(k - 64) * 128 + nn];
    o[idx] = __float2half_rn(w);
}
__global__ void k_prep_c1(const float* __restrict__ Wn, const float* __restrict__ Ws,
                          __half* __restrict__ o) {
    int idx = blockIdx.x * blockDim.x + threadIdx.x;
    if (idx >= 128 * 256) return;
    int nn = idx >> 8, k = idx & 255;
    float w = (k < 128) ? Wn[k * 128 + nn] : Ws[(k - 128) * 128 + nn];
    o[idx] = __float2half_rn(w);
}
__global__ void k_prep_qt(const float* __restrict__ Wih, const float* __restrict__ Whh,
                          const float* __restrict__ bih, const float* __restrict__ bhh,
                          __half* __restrict__ o, float* __restrict__ bq) {
    int idx = blockIdx.x * blockDim.x + threadIdx.x;
    if (idx >= 512 * 256) return;
    int c = idx >> 8, k = idx & 255;
    int j = c >> 2, g = c & 3;
    float w = 0.f;
    if (k < 128) {
        if (g == 0)      w = Wih[j * 128 + k];
        else if (g == 1) w = Wih[(128 + j) * 128 + k];
        else if (g == 2) w = Wih[(256 + j) * 128 + k];
    } else {
        int kk = k - 128;
        if (g == 0)      w = Whh[j * 128 + kk];
        else if (g == 1) w = Whh[(128 + j) * 128 + kk];
        else if (g == 3) w = Whh[(256 + j) * 128 + kk];
    }
    o[idx] = __float2half_rn(w);
    if (idx < 512) {
        int jj = idx >> 2, gg = idx & 3;
        bq[idx] = (gg == 0) ? bih[jj] + bhh[jj]
                : (gg == 1) ? bih[128 + jj] + bhh[128 + jj]
                : (gg == 2) ? bih[256 + jj]
                            : bhh[256 + jj];
    }
}
__global__ void k_prep_cls(const float* __restrict__ W, __half* __restrict__ o) {
    int idx = blockIdx.x * blockDim.x + threadIdx.x;
    if (idx >= 64 * 128) return;
    int oo = idx >> 7, k = idx & 127;
    o[idx] = __float2half_rn(W[k * 64 + oo]);
}

// ----------------- mean aggregation (warp per node, fp16 gather, fp32 accum) -----------------
__global__ void __launch_bounds__(256) k_agg64h(const __half* __restrict__ x, __half* __restrict__ out,
                                                const int* __restrict__ rp, const int* __restrict__ ci, int n) {
    int w = (blockIdx.x * blockDim.x + threadIdx.x) >> 5;
    if (w >= n) return;
    int lane = threadIdx.x & 31;
    int s0 = rp[w], s1 = rp[w + 1];
    float ax = 0.f, ay = 0.f;
    int e = s0;
    for (; e + 4 <= s1; e += 4) {
        int i0 = ci[e], i1 = ci[e + 1], i2 = ci[e + 2], i3 = ci[e + 3];
        float2 v0 = __half22float2(*(const __half2*)(x + (size_t)i0 * 64 + lane * 2));
        float2 v1 = __half22float2(*(const __half2*)(x + (size_t)i1 * 64 + lane * 2));
        float2 v2 = __half22float2(*(const __half2*)(x + (size_t)i2 * 64 + lane * 2));
        float2 v3 = __half22float2(*(const __half2*)(x + (size_t)i3 * 64 + lane * 2));
        ax += (v0.x + v1.x) + (v2.x + v3.x);
        ay += (v0.y + v1.y) + (v2.y + v3.y);
    }
    for (; e < s1; e++) {
        int i0 = ci[e];
        float2 v0 = __half22float2(*(const __half2*)(x + (size_t)i0 * 64 + lane * 2));
        ax += v0.x; ay += v0.y;
    }
    int d = s1 - s0; if (d < 1) d = 1;
    float inv = 1.f / (float)d;
    *(__half2*)(out + (size_t)w * 64 + lane * 2) = __floats2half2_rn(ax * inv, ay * inv);
}
__global__ void __launch_bounds__(256) k_agg128h(const __half* __restrict__ x, __half* __restrict__ out,
                                                 const int* __restrict__ rp, const int* __restrict__ ci, int n) {
    int w = (blockIdx.x * blockDim.x + threadIdx.x) >> 5;
    if (w >= n) return;
    int lane = threadIdx.x & 31;
    int s0 = rp[w], s1 = rp[w + 1];
    float a0 = 0.f, a1 = 0.f, a2 = 0.f, a3 = 0.f;
    int e = s0;
    for (; e + 4 <= s1; e += 4) {
        int i0 = ci[e], i1 = ci[e + 1], i2 = ci[e + 2], i3 = ci[e + 3];
        float v[4][4];
        unpack4_f16(*(const uint2*)(x + (size_t)i0 * 128 + lane * 4), v[0]);
        unpack4_f16(*(const uint2*)(x + (size_t)i1 * 128 + lane * 4), v[1]);
        unpack4_f16(*(const uint2*)(x + (size_t)i2 * 128 + lane * 4), v[2]);
        unpack4_f16(*(const uint2*)(x + (size_t)i3 * 128 + lane * 4), v[3]);
        a0 += (v[0][0] + v[1][0]) + (v[2][0] + v[3][0]);
        a1 += (v[0][1] + v[1][1]) + (v[2][1] + v[3][1]);
        a2 += (v[0][2] + v[1][2]) + (v[2][2] + v[3][2]);
        a3 += (v[0][3] + v[1][3]) + (v[2][3] + v[3][3]);
    }
    for (; e < s1; e++) {
        int i0 = ci[e];
        float v[4];
        unpack4_f16(*(const uint2*)(x + (size_t)i0 * 128 + lane * 4), v);
        a0 += v[0]; a1 += v[1]; a2 += v[2]; a3 += v[3];
    }
    int d = s1 - s0; if (d < 1) d = 1;
    float inv = 1.f / (float)d;
    *(uint2*)(out + (size_t)w * 128 + lane * 4) =
        pack4_f16(a0 * inv, a1 * inv, a2 * inv, a3 * inv);
}

// final logits: warp per row, zc[64] @ W2[64,2] + b2
__global__ void __launch_bounds__(256) k_logits(const float* __restrict__ zc,
                                                const float* __restrict__ W2,
                                                const float* __restrict__ b2,
                                                float* __restrict__ out, int n) {
    int w = (blockIdx.x * blockDim.x + threadIdx.x) >> 5;
    if (w >= n) return;
    int lane = threadIdx.x & 31;
    float z0 = zc[(size_t)w * 64 + lane];
    float z1 = zc[(size_t)w * 64 + 32 + lane];
    float a0 = z0 * W2[lane * 2 + 0] + z1 * W2[(lane + 32) * 2 + 0];
    float a1 = z0 * W2[lane * 2 + 1] + z1 * W2[(lane + 32) * 2 + 1];
#pragma unroll
    for (int o = 16; o > 0; o >>= 1) {
        a0 += __shfl_xor_sync(0xffffffffu, a0, o);
        a1 += __shfl_xor_sync(0xffffffffu, a1, o);
    }
    if (lane == 0) {
        out[(size_t)w * 2 + 0] = a0 + b2[0];
        out[(size_t)w * 2 + 1] = a1 + b2[1];
    }
}

// ----------------- host launch -----------------
extern "C" void kernel_launch(void* const* d_in, const int* in_sizes, int n_in,
                              void* d_out, int out_size) {
    const int N = N_NODES, E = N_EDGES;

    const float* x_seq = nullptr;
    const int* eidx = nullptr;
    const float* Wt[18];
    int wi = 0;
    for (int i = 0; i < n_in; i++) {
        if (in_sizes[i] == 2 * E) eidx = (const int*)d_in[i];
        else if (in_sizes[i] == T_STEPS * N * 64) x_seq = (const float*)d_in[i];
        else if (wi < 18) Wt[wi++] = (const float*)d_in[i];
    }
    const float *Wn0 = Wt[0], *Ws0 = Wt[1], *b0 = Wt[2], *g0 = Wt[3], *be0 = Wt[4];
    const float *Wn1 = Wt[5], *Ws1 = Wt[6], *b1 = Wt[7], *g1 = Wt[8], *be1 = Wt[9];
    const float *gWih = Wt[10], *gWhh = Wt[11], *gbih = Wt[12], *gbhh = Wt[13];
    const float *cW1 = Wt[14], *cb1 = Wt[15], *cW2 = Wt[16], *cb2 = Wt[17];

    __half *x16, *agg16, *h016, *h116, *hA16, *hB16, *Wc0t16, *Wc1t16, *Wqt16, *cW1t16;
    float *hAf, *hBf, *zc, *bq;
    int *cnt, *rp, *cur, *ci;
    cudaGetSymbolAddress((void**)&x16, g_x16);
    cudaGetSymbolAddress((void**)&agg16, g_agg16);
    cudaGetSymbolAddress((void**)&h016, g_h016);
    cudaGetSymbolAddress((void**)&h116, g_h116);
    cudaGetSymbolAddress((void**)&hA16, g_hA16);
    cudaGetSymbolAddress((void**)&hB16, g_hB16);
    cudaGetSymbolAddress((void**)&Wc0t16, g_Wc0t16);
    cudaGetSymbolAddress((void**)&Wc1t16, g_Wc1t16);
    cudaGetSymbolAddress((void**)&Wqt16, g_Wqt16);
    cudaGetSymbolAddress((void**)&cW1t16, g_cW1t16);
    cudaGetSymbolAddress((void**)&hAf, g_hAf);
    cudaGetSymbolAddress((void**)&hBf, g_hBf);
    cudaGetSymbolAddress((void**)&zc, g_zc);
    cudaGetSymbolAddress((void**)&bq, g_bq);
    cudaGetSymbolAddress((void**)&cnt, g_cnt);
    cudaGetSymbolAddress((void**)&rp, g_rowptr);
    cudaGetSymbolAddress((void**)&cur, g_cur);
    cudaGetSymbolAddress((void**)&ci, g_colidx);

    const int* src = eidx;
    const int* dst = eidx + E;

    const int SM_A = 55296;
    const int SM_B = 55296;
    cudaFuncSetAttribute((const void*)k_wmma<64, 128, 2, 4, 0>, cudaFuncAttributeMaxDynamicSharedMemorySize, SM_A);
    cudaFuncSetAttribute((const void*)k_wmma<64, 128, 2, 4, 1>, cudaFuncAttributeMaxDynamicSharedMemorySize, SM_A);
    cudaFuncSetAttribute((const void*)k_wmma<64, 128, 2, 4, 2>, cudaFuncAttributeMaxDynamicSharedMemorySize, SM_A);
    cudaFuncSetAttribute((const void*)k_wmma<128, 64, 4, 2, 3>, cudaFuncAttributeMaxDynamicSharedMemorySize, SM_B);

    // ---- build CSR (deterministic after per-segment sort) ----
    k_zero_i<<<(N + 255) / 256, 256>>>(cnt, N);
    k_hist<<<(E + 255) / 256, 256>>>(dst, E, cnt);
    k_scan<<<1, 1024>>>(cnt, rp, N);
    k_copy_i<<<(N + 255) / 256, 256>>>(rp, cur, N);
    k_fill<<<(E + 255) / 256, 256>>>(src, dst, E, cur, ci);
    k_sortseg<<<(N + 255) / 256, 256>>>(rp, ci, N);

    // ---- init GRU state + fp16 weight/input prep ----
    k_zero_f4<<<(N * 128 / 4 + 255) / 256, 256>>>((float4*)hAf, N * 128 / 4);
    k_zero_u4<<<(N * 128 / 8 + 255) / 256, 256>>>((uint4*)hA16, N * 128 / 8);
    k_cvt_x16<<<((T_STEPS * N * 64 / 4) + 255) / 256, 256>>>(
        (const float4*)x_seq, (uint2*)x16, T_STEPS * N * 64 / 4);
    k_prep_c0<<<(128 * 128 + 255) / 256, 256>>>(Wn0, Ws0, Wc0t16);
    k_prep_c1<<<(128 * 256 + 255) / 256, 256>>>(Wn1, Ws1, Wc1t16);
    k_prep_qt<<<(512 * 256 + 255) / 256, 256>>>(gWih, gWhh, gbih, gbhh, Wqt16, bq);
    k_prep_cls<<<(64 * 128 + 255) / 256, 256>>>(cW1, cW1t16);

    const int GRID64  = (N + 63) / 64;
    const int GRID128 = (N + 127) / 128;
    const int AGG_GRID = (N + 7) / 8;

    float* hprevf = hAf;
    float* hnextf = hBf;
    __half* hprev16 = hA16;
    __half* hnext16 = hB16;
    for (int t = 0; t < T_STEPS; t++) {
        const __half* xt16 = x16 + (size_t)t * N * 64;
        // SAGE layer 0: LN+ReLU -> h016 (fp16)
        k_agg64h<<<AGG_GRID, 256>>>(xt16, agg16, rp, ci, N);
        k_wmma<64, 128, 2, 4, 0><<<dim3(GRID64, 1), 256, SM_A>>>(
            agg16, 64, xt16, 64, Wc0t16, 128, b0, g0, be0, nullptr, nullptr, nullptr, h016, N);
        // SAGE layer 1: LN+ReLU + residual(h016) -> h116 (fp16)
        k_agg128h<<<AGG_GRID, 256>>>(h016, agg16, rp, ci, N);
        k_wmma<64, 128, 2, 4, 1><<<dim3(GRID64, 1), 256, SM_A>>>(
            agg16, 128, h016, 128, Wc1t16, 256, b1, g1, be1, nullptr, h016, nullptr, h116, N);
        // GRU step (gate-quad epilogue) -> hnext (fp32 + fp16)
        k_wmma<64, 128, 2, 4, 2><<<dim3(GRID64, 4), 256, SM_A>>>(
            h116, 128, hprev16, 128, Wqt16, 256, bq, nullptr, nullptr, hprevf, nullptr, hnextf, hnext16, N);
        float* tf = hprevf; hprevf = hnextf; hnextf = tf;
        __half* th = hprev16; hprev16 = hnext16; hnext16 = th;
    }
    // classifier (A1 = final hidden, fp16)
    k_wmma<128, 64, 4, 2, 3><<<dim3(GRID128, 1), 256, SM_B>>>(
        hprev16, 128, nullptr, 0, cW1t16, 128, cb1, nullptr, nullptr, nullptr, nullptr, zc, nullptr, N);
    k_logits<<<AGG_GRID, 256>>>(zc, cW2, cb2, (float*)d_out, N);
}

// round 11
// speedup vs baseline: 2.4339x; 1.0101x over previous
#include <cuda_runtime.h>
#include <cuda_bf16.h>
#include <cuda_fp16.h>
#include <mma.h>
#include <cstdint>

using namespace nvcuda;

#define N_NODES 100000
#define N_EDGES 1600000
#define T_STEPS 12

// ----------------- static device scratch -----------------
// fp16 arrays declared as uint4 for 16B alignment (cast to __half*)
__device__ uint4 g_x16      [(size_t)T_STEPS * N_NODES * 64 / 8];   // fp16 x_seq
__device__ uint4 g_agg64a   [(size_t)T_STEPS * N_NODES * 64 / 8];   // agg(x) all t
__device__ uint4 g_h016a    [(size_t)T_STEPS * N_NODES * 128 / 8];  // h0 all t
__device__ uint4 g_agg128a  [(size_t)T_STEPS * N_NODES * 128 / 8];  // agg(h0) all t
__device__ uint4 g_h116a    [(size_t)T_STEPS * N_NODES * 128 / 8];  // h1 all t
__device__ uint4 g_hA16 [(size_t)N_NODES * 128 / 8];
__device__ uint4 g_hB16 [(size_t)N_NODES * 128 / 8];
__device__ uint4 g_Wc0t16[128 * 128 / 8];
__device__ uint4 g_Wc1t16[128 * 256 / 8];
__device__ uint4 g_Wqt16 [512 * 256 / 8];
__device__ uint4 g_cW1t16[64 * 128 / 8];
// fp32 arrays
__device__ float g_hAf[(size_t)N_NODES * 128];
__device__ float g_hBf[(size_t)N_NODES * 128];
__device__ float g_zc [(size_t)N_NODES * 64];
__device__ float g_bq [512];
__device__ int   g_cnt   [N_NODES];
__device__ int   g_rowptr[N_NODES + 1];
__device__ int   g_cur   [N_NODES];
__device__ int   g_colidx[N_EDGES];

__device__ __forceinline__ float sigf(float x) { return 1.f / (1.f + expf(-x)); }

__device__ __forceinline__ uint2 pack4_f16(float a, float b, float c, float d) {
    __half2 lo = __floats2half2_rn(a, b);
    __half2 hi = __floats2half2_rn(c, d);
    uint2 u;
    u.x = *(uint32_t*)&lo;
    u.y = *(uint32_t*)&hi;
    return u;
}
__device__ __forceinline__ void unpack4_f16(uint2 u, float* o) {
    __half2 lo = *(__half2*)&u.x;
    __half2 hi = *(__half2*)&u.y;
    float2 a = __half22float2(lo);
    float2 b = __half22float2(hi);
    o[0] = a.x; o[1] = a.y; o[2] = b.x; o[3] = b.y;
}

// ----------------- wmma fp16 GEMM (fp32 accum), time-batched -----------------
// 1D grid: bid = t * nRowTiles + rowTile (t slow => L2 locality per wave).
// D[row, jbase+c] = epi( A1[row,:K1]@Bt^T + A2[row,:K2]@Bt^T )
// EPI 0: bias+LN+ReLU -> out16                 (BM=64,BN=128)
// EPI 1: bias+LN+ReLU+res16 -> out16           (BM=64,BN=128)
// EPI 2: GRU gate-quad (grid.y=4; res fp32) -> out fp32 + out16
// EPI 3: bias+ReLU -> out fp32 (stride 64)     (BM=128,BN=64)
template <int BM, int BN, int WR, int WC, int EPI>
__global__ void __launch_bounds__(256) k_wmma(
    const __half* __restrict__ A1, int K1,
    const __half* __restrict__ A2, int K2,
    const __half* __restrict__ Bt, int Ktot,
    const float* __restrict__ bias,
    const float* __restrict__ gamma, const float* __restrict__ beta,
    const float* __restrict__ res, const __half* __restrict__ res16,
    float* __restrict__ out, __half* __restrict__ out16, int n,
    int nRowTiles, size_t sA1, size_t sA2, size_t sRes16, size_t sOut16)
{
    constexpr int LDH = 72;
    constexpr int LDC = BN + 8;
    constexpr int ASZ = BM * LDH;
    constexpr int BSZ = BN * LDH;
    constexpr int MI = BM / WR / 16;
    constexpr int NI = BN / WC / 16;
    constexpr int AIT = BM / 32;
    constexpr int BIT = BN / 32;
    extern __shared__ __align__(256) char smem_raw[];
    __half* Hs = (__half*)smem_raw;
    float* Cs = (float*)smem_raw;

    const int tid = threadIdx.x;
    const int wid = tid >> 5;
    const int wr = wid / WC, wc = wid % WC;
    const int tt = blockIdx.x / nRowTiles;
    const int rt = blockIdx.x - tt * nRowTiles;
    const int row0 = rt * BM;
    const int jbase = blockIdx.y * BN;
    A1 += (size_t)tt * sA1;
    A2 += (size_t)tt * sA2;
    res16 += (size_t)tt * sRes16;
    out16 += (size_t)tt * sOut16;

    wmma::fragment<wmma::accumulator, 16, 16, 16, float> acc[MI][NI];
#pragma unroll
    for (int mi = 0; mi < MI; mi++)
#pragma unroll
        for (int ni = 0; ni < NI; ni++) wmma::fill_fragment(acc[mi][ni], 0.f);

    const int nc = Ktot / 64;
    uint4 pa[AIT], pb[BIT];

    auto ldg_chunk = [&](int c) {
        int kg = c * 64;
        const __half* Asrc; int Kph, koff;
        if (kg < K1) { Asrc = A1; Kph = K1; koff = kg; }
        else         { Asrc = A2; Kph = K2; koff = kg - K1; }
#pragma unroll
        for (int it = 0; it < AIT; it++) {
            int idx = it * 256 + tid;
            int r = idx >> 3, q = idx & 7;
            int grow = row0 + r;
            pa[it] = (grow < n) ? *(const uint4*)(Asrc + (size_t)grow * Kph + koff + q * 8)
                                : make_uint4(0u, 0u, 0u, 0u);
        }
#pragma unroll
        for (int it = 0; it < BIT; it++) {
            int idx = it * 256 + tid;
            int r = idx >> 3, q = idx & 7;
            pb[it] = *(const uint4*)(Bt + (size_t)(jbase + r) * Ktot + kg + q * 8);
        }
    };
    auto sts_chunk = [&](int s) {
        __half* As = Hs + s * ASZ;
        __half* Bs = Hs + 2 * ASZ + s * BSZ;
#pragma unroll
        for (int it = 0; it < AIT; it++) {
            int idx = it * 256 + tid;
            int r = idx >> 3, q = idx & 7;
            *(uint4*)(&As[r * LDH + q * 8]) = pa[it];
        }
#pragma unroll
        for (int it = 0; it < BIT; it++) {
            int idx = it * 256 + tid;
            int r = idx >> 3, q = idx & 7;
            *(uint4*)(&Bs[r * LDH + q * 8]) = pb[it];
        }
    };

    ldg_chunk(0);
    sts_chunk(0);
    __syncthreads();

    for (int c = 0; c < nc; c++) {
        int s = c & 1;
        if (c + 1 < nc) ldg_chunk(c + 1);
        const __half* As = Hs + s * ASZ;
        const __half* Bs = Hs + 2 * ASZ + s * BSZ;
#pragma unroll
        for (int ks = 0; ks < 4; ks++) {
            wmma::fragment<wmma::matrix_a, 16, 16, 16, __half, wmma::row_major> af[MI];
            wmma::fragment<wmma::matrix_b, 16, 16, 16, __half, wmma::col_major> bf[NI];
#pragma unroll
            for (int mi = 0; mi < MI; mi++)
                wmma::load_matrix_sync(af[mi], As + (wr * (BM / WR) + mi * 16) * LDH + ks * 16, LDH);
#pragma unroll
            for (int ni = 0; ni < NI; ni++)
                wmma::load_matrix_sync(bf[ni], Bs + (wc * (BN / WC) + ni * 16) * LDH + ks * 16, LDH);
#pragma unroll
            for (int mi = 0; mi < MI; mi++)
#pragma unroll
                for (int ni = 0; ni < NI; ni++)
                    wmma::mma_sync(acc[mi][ni], af[mi], bf[ni], acc[mi][ni]);
        }
        if (c + 1 < nc) sts_chunk(s ^ 1);
        __syncthreads();
    }

#pragma unroll
    for (int mi = 0; mi < MI; mi++)
#pragma unroll
        for (int ni = 0; ni < NI; ni++)
            wmma::store_matrix_sync(Cs + (wr * (BM / WR) + mi * 16) * LDC + wc * (BN / WC) + ni * 16,
                                    acc[mi][ni], LDC, wmma::mem_row_major);
    __syncthreads();

    if constexpr (EPI == 0 || EPI == 1) {
        int r = tid >> 2, seg = tid & 3;
        int grow = row0 + r;
        float v[32];
        float sum = 0.f, sq = 0.f;
#pragma unroll
        for (int q = 0; q < 8; q++) {
            float4 c4 = *(float4*)&Cs[r * LDC + seg * 32 + q * 4];
            float b0v = __ldg(&bias[seg * 32 + q * 4 + 0]);
            float b1v = __ldg(&bias[seg * 32 + q * 4 + 1]);
            float b2v = __ldg(&bias[seg * 32 + q * 4 + 2]);
            float b3v = __ldg(&bias[seg * 32 + q * 4 + 3]);
            v[q * 4 + 0] = c4.x + b0v; v[q * 4 + 1] = c4.y + b1v;
            v[q * 4 + 2] = c4.z + b2v; v[q * 4 + 3] = c4.w + b3v;
#pragma unroll
            for (int u = 0; u < 4; u++) { sum += v[q * 4 + u]; sq += v[q * 4 + u] * v[q * 4 + u]; }
        }
        sum += __shfl_xor_sync(0xffffffffu, sum, 1);
        sq  += __shfl_xor_sync(0xffffffffu, sq, 1);
        sum += __shfl_xor_sync(0xffffffffu, sum, 2);
        sq  += __shfl_xor_sync(0xffffffffu, sq, 2);
        float mean = sum * (1.f / 128.f);
        float var = sq * (1.f / 128.f) - mean * mean;
        float rs = rsqrtf(var + 1e-5f);
        if (grow < n) {
#pragma unroll
            for (int q = 0; q < 8; q++) {
                int cc = seg * 32 + q * 4;
                float4 o;
                o.x = fmaxf((v[q * 4 + 0] - mean) * rs * __ldg(&gamma[cc + 0]) + __ldg(&beta[cc + 0]), 0.f);
                o.y = fmaxf((v[q * 4 + 1] - mean) * rs * __ldg(&gamma[cc + 1]) + __ldg(&beta[cc + 1]), 0.f);
                o.z = fmaxf((v[q * 4 + 2] - mean) * rs * __ldg(&gamma[cc + 2]) + __ldg(&beta[cc + 2]), 0.f);
                o.w = fmaxf((v[q * 4 + 3] - mean) * rs * __ldg(&gamma[cc + 3]) + __ldg(&beta[cc + 3]), 0.f);
                if (EPI == 1) {
                    uint2 r16 = *(const uint2*)(res16 + (size_t)grow * 128 + cc);
                    float rv[4];
                    unpack4_f16(r16, rv);
                    o.x += rv[0]; o.y += rv[1]; o.z += rv[2]; o.w += rv[3];
                }
                *(uint2*)(out16 + (size_t)grow * 128 + cc) = pack4_f16(o.x, o.y, o.z, o.w);
            }
        }
    } else if constexpr (EPI == 2) {
        int r = tid >> 2, seg = tid & 3;
        int grow = row0 + r;
        if (grow < n) {
            int lc0 = seg * 32;
            float hv[8];
#pragma unroll
            for (int q = 0; q < 8; q++) {
                int lc = lc0 + q * 4;
                int gcol = jbase + lc;
                float cr = Cs[r * LDC + lc + 0] + __ldg(&bias[gcol + 0]);
                float cz = Cs[r * LDC + lc + 1] + __ldg(&bias[gcol + 1]);
                float ci = Cs[r * LDC + lc + 2] + __ldg(&bias[gcol + 2]);
                float ch = Cs[r * LDC + lc + 3] + __ldg(&bias[gcol + 3]);
                float rg = sigf(cr);
                float z = sigf(cz);
                float ng = tanhf(ci + rg * ch);
                float hp = res[(size_t)grow * 128 + ((jbase + lc0) >> 2) + q];
                hv[q] = (1.f - z) * ng + z * hp;
            }
            int j0 = ((jbase + lc0) >> 2);
            *(float4*)(out + (size_t)grow * 128 + j0) = make_float4(hv[0], hv[1], hv[2], hv[3]);
            *(float4*)(out + (size_t)grow * 128 + j0 + 4) = make_float4(hv[4], hv[5], hv[6], hv[7]);
            *(uint2*)(out16 + (size_t)grow * 128 + j0) = pack4_f16(hv[0], hv[1], hv[2], hv[3]);
            *(uint2*)(out16 + (size_t)grow * 128 + j0 + 4) = pack4_f16(hv[4], hv[5], hv[6], hv[7]);
        }
    } else {
        int r = tid >> 1, seg = tid & 1;
        int grow = row0 + r;
        if (grow < n) {
#pragma unroll
            for (int q = 0; q < 8; q++) {
                int cc = seg * 32 + q * 4;
                float4 c4 = *(float4*)&Cs[r * LDC + cc];
                float4 o;
                o.x = fmaxf(c4.x + __ldg(&bias[cc + 0]), 0.f);
                o.y = fmaxf(c4.y + __ldg(&bias[cc + 1]), 0.f);
                o.z = fmaxf(c4.z + __ldg(&bias[cc + 2]), 0.f);
                o.w = fmaxf(c4.w + __ldg(&bias[cc + 3]), 0.f);
                *(float4*)(out + (size_t)grow * 64 + cc) = o;
            }
        }
    }
}

// ----------------- CSR build + misc -----------------
__global__ void k_zero_f4(float4* p, int c4) {
    int i = blockIdx.x * blockDim.x + threadIdx.x;
    if (i < c4) p[i] = make_float4(0.f, 0.f, 0.f, 0.f);
}
__global__ void k_zero_u4(uint4* p, int c4) {
    int i = blockIdx.x * blockDim.x + threadIdx.x;
    if (i < c4) p[i] = make_uint4(0u, 0u, 0u, 0u);
}
__global__ void k_zero_i(int* p, int c) {
    int i = blockIdx.x * blockDim.x + threadIdx.x;
    if (i < c) p[i] = 0;
}
__global__ void k_hist(const int* __restrict__ dst, int e, int* __restrict__ cnt) {
    int i = blockIdx.x * blockDim.x + threadIdx.x;
    if (i < e) atomicAdd(&cnt[dst[i]], 1);
}
__global__ void k_fill(const int* __restrict__ src, const int* __restrict__ dst, int e,
                       int* __restrict__ cur, int* __restrict__ colidx) {
    int i = blockIdx.x * blockDim.x + threadIdx.x;
    if (i < e) {
        int p = atomicAdd(&cur[dst[i]], 1);
        colidx[p] = src[i];
    }
}
__global__ void k_sortseg(const int* __restrict__ rp, int* __restrict__ ci, int n) {
    int v = blockIdx.x * blockDim.x + threadIdx.x;
    if (v >= n) return;
    int s = rp[v], e = rp[v + 1];
    for (int i = s + 1; i < e; i++) {
        int key = ci[i];
        int j = i - 1;
        while (j >= s && ci[j] > key) { ci[j + 1] = ci[j]; j--; }
        ci[j + 1] = key;
    }
}
// exclusive scan; also writes cur[] (fill cursor copy)
__global__ void k_scan(const int* __restrict__ cnt, int* __restrict__ rowptr,
                       int* __restrict__ cur, int n) {
    __shared__ int wsums[32];
    __shared__ int s_carry;
    int tid = threadIdx.x;
    int lane = tid & 31, wid = tid >> 5;
    if (tid == 0) s_carry = 0;
    __syncthreads();
    for (int base = 0; base < n; base += 1024) {
        int i = base + tid;
        int v = (i < n) ? cnt[i] : 0;
        int x = v;
#pragma unroll
        for (int o = 1; o < 32; o <<= 1) {
            int t = __shfl_up_sync(0xffffffffu, x, o);
            if (lane >= o) x += t;
        }
        if (lane == 31) wsums[wid] = x;
        __syncthreads();
        if (tid < 32) {
            int s = wsums[tid];
#pragma unroll
            for (int o = 1; o < 32; o <<= 1) {
                int t = __shfl_up_sync(0xffffffffu, s, o);
                if (tid >= o) s += t;
            }
            wsums[tid] = s;
        }
        __syncthreads();
        int incl = x + ((wid > 0) ? wsums[wid - 1] : 0);
        int excl = s_carry + incl - v;
        if (i < n) { rowptr[i] = excl; cur[i] = excl; }
        int blocktot = wsums[31];
        __syncthreads();
        if (tid == 0) s_carry += blocktot;
        __syncthreads();
    }
    if (tid == 0) rowptr[n] = s_carry;
}

// ----------------- weight / input prep -----------------
__global__ void k_cvt_x16(const float4* __restrict__ in, uint2* __restrict__ out, int c4) {
    int i = blockIdx.x * blockDim.x + threadIdx.x;
    if (i >= c4) return;
    float4 v = in[i];
    out[i] = pack4_f16(v.x, v.y, v.z, v.w);
}
__global__ void k_prep_c0(const float* __restrict__ Wn, const float* __restrict__ Ws,
                          __half* __restrict__ o) {
    int idx = blockIdx.x * blockDim.x + threadIdx.x;
    if (idx >= 128 * 128) return;
    int nn = idx >> 7, k = idx & 127;
    float w = (k < 64) ? Wn[k * 128 + nn] : Ws[(k - 64) * 128 + nn];
    o[idx] = __float2half_rn(w);
}
__global__ void k_prep_c1(const float* __restrict__ Wn, const float* __restrict__ Ws,
                          __half* __restrict__ o) {
    int idx = blockIdx.x * blockDim.x + threadIdx.x;
    if (idx >= 128 * 256) return;
    int nn = idx >> 8, k = idx & 255;
    float w = (k < 128) ? Wn[k * 128 + nn] : Ws[(k - 128) * 128 + nn];
    o[idx] = __float2half_rn(w);
}
__global__ void k_prep_qt(const float* __restrict__ Wih, const float* __restrict__ Whh,
                          const float* __restrict__ bih, const float* __restrict__ bhh,
                          __half* __restrict__ o, float* __restrict__ bq) {
    int idx = blockIdx.x * blockDim.x + threadIdx.x;
    if (idx >= 512 * 256) return;
    int c = idx >> 8, k = idx & 255;
    int j = c >> 2, g = c & 3;
    float w = 0.f;
    if (k < 128) {
        if (g == 0)      w = Wih[j * 128 + k];
        else if (g == 1) w = Wih[(128 + j) * 128 + k];
        else if (g == 2) w = Wih[(256 + j) * 128 + k];
    } else {
        int kk = k - 128;
        if (g == 0)      w = Whh[j * 128 + kk];
        else if (g == 1) w = Whh[(128 + j) * 128 + kk];
        else if (g == 3) w = Whh[(256 + j) * 128 + kk];
    }
    o[idx] = __float2half_rn(w);
    if (idx < 512) {
        int jj = idx >> 2, gg = idx & 3;
        bq[idx] = (gg == 0) ? bih[jj] + bhh[jj]
                : (gg == 1) ? bih[128 + jj] + bhh[128 + jj]
                : (gg == 2) ? bih[256 + jj]
                            : bhh[256 + jj];
    }
}
__global__ void k_prep_cls(const float* __restrict__ W, __half* __restrict__ o) {
    int idx = blockIdx.x * blockDim.x + threadIdx.x;
    if (idx >= 64 * 128) return;
    int oo = idx >> 7, k = idx & 127;
    o[idx] = __float2half_rn(W[k * 64 + oo]);
}

// ----------------- mean aggregation (warp/node, fp16 gather, fp32 accum, time-batched) -----------
__global__ void __launch_bounds__(256) k_agg64h(const __half* __restrict__ x, __half* __restrict__ out,
                                                const int* __restrict__ rp, const int* __restrict__ ci,
                                                int n, int blocksPerT) {
    int tt = blockIdx.x / blocksPerT;
    int lb = blockIdx.x - tt * blocksPerT;
    int w = (lb * 256 + threadIdx.x) >> 5;
    if (w >= n) return;
    x += (size_t)tt * n * 64;
    out += (size_t)tt * n * 64;
    int lane = threadIdx.x & 31;
    int s0 = rp[w], s1 = rp[w + 1];
    float ax = 0.f, ay = 0.f;
    int e = s0;
    for (; e + 4 <= s1; e += 4) {
        int i0 = ci[e], i1 = ci[e + 1], i2 = ci[e + 2], i3 = ci[e + 3];
        float2 v0 = __half22float2(*(const __half2*)(x + (size_t)i0 * 64 + lane * 2));
        float2 v1 = __half22float2(*(const __half2*)(x + (size_t)i1 * 64 + lane * 2));
        float2 v2 = __half22float2(*(const __half2*)(x + (size_t)i2 * 64 + lane * 2));
        float2 v3 = __half22float2(*(const __half2*)(x + (size_t)i3 * 64 + lane * 2));
        ax += (v0.x + v1.x) + (v2.x + v3.x);
        ay += (v0.y + v1.y) + (v2.y + v3.y);
    }
    for (; e < s1; e++) {
        int i0 = ci[e];
        float2 v0 = __half22float2(*(const __half2*)(x + (size_t)i0 * 64 + lane * 2));
        ax += v0.x; ay += v0.y;
    }
    int d = s1 - s0; if (d < 1) d = 1;
    float inv = 1.f / (float)d;
    *(__half2*)(out + (size_t)w * 64 + lane * 2) = __floats2half2_rn(ax * inv, ay * inv);
}
__global__ void __launch_bounds__(256) k_agg128h(const __half* __restrict__ x, __half* __restrict__ out,
                                                 const int* __restrict__ rp, const int* __restrict__ ci,
                                                 int n, int blocksPerT) {
    int tt = blockIdx.x / blocksPerT;
    int lb = blockIdx.x - tt * blocksPerT;
    int w = (lb * 256 + threadIdx.x) >> 5;
    if (w >= n) return;
    x += (size_t)tt * n * 128;
    out += (size_t)tt * n * 128;
    int lane = threadIdx.x & 31;
    int s0 = rp[w], s1 = rp[w + 1];
    float a0 = 0.f, a1 = 0.f, a2 = 0.f, a3 = 0.f;
    int e = s0;
    for (; e + 4 <= s1; e += 4) {
        int i0 = ci[e], i1 = ci[e + 1], i2 = ci[e + 2], i3 = ci[e + 3];
        float v[4][4];
        unpack4_f16(*(const uint2*)(x + (size_t)i0 * 128 + lane * 4), v[0]);
        unpack4_f16(*(const uint2*)(x + (size_t)i1 * 128 + lane * 4), v[1]);
        unpack4_f16(*(const uint2*)(x + (size_t)i2 * 128 + lane * 4), v[2]);
        unpack4_f16(*(const uint2*)(x + (size_t)i3 * 128 + lane * 4), v[3]);
        a0 += (v[0][0] + v[1][0]) + (v[2][0] + v[3][0]);
        a1 += (v[0][1] + v[1][1]) + (v[2][1] + v[3][1]);
        a2 += (v[0][2] + v[1][2]) + (v[2][2] + v[3][2]);
        a3 += (v[0][3] + v[1][3]) + (v[2][3] + v[3][3]);
    }
    for (; e < s1; e++) {
        int i0 = ci[e];
        float v[4];
        unpack4_f16(*(const uint2*)(x + (size_t)i0 * 128 + lane * 4), v);
        a0 += v[0]; a1 += v[1]; a2 += v[2]; a3 += v[3];
    }
    int d = s1 - s0; if (d < 1) d = 1;
    float inv = 1.f / (float)d;
    *(uint2*)(out + (size_t)w * 128 + lane * 4) =
        pack4_f16(a0 * inv, a1 * inv, a2 * inv, a3 * inv);
}

// final logits: warp per row, zc[64] @ W2[64,2] + b2
__global__ void __launch_bounds__(256) k_logits(const float* __restrict__ zc,
                                                const float* __restrict__ W2,
                                                const float* __restrict__ b2,
                                                float* __restrict__ out, int n) {
    int w = (blockIdx.x * blockDim.x + threadIdx.x) >> 5;
    if (w >= n) return;
    int lane = threadIdx.x & 31;
    float z0 = zc[(size_t)w * 64 + lane];
    float z1 = zc[(size_t)w * 64 + 32 + lane];
    float a0 = z0 * W2[lane * 2 + 0] + z1 * W2[(lane + 32) * 2 + 0];
    float a1 = z0 * W2[lane * 2 + 1] + z1 * W2[(lane + 32) * 2 + 1];
#pragma unroll
    for (int o = 16; o > 0; o >>= 1) {
        a0 += __shfl_xor_sync(0xffffffffu, a0, o);
        a1 += __shfl_xor_sync(0xffffffffu, a1, o);
    }
    if (lane == 0) {
        out[(size_t)w * 2 + 0] = a0 + b2[0];
        out[(size_t)w * 2 + 1] = a1 + b2[1];
    }
}

// ----------------- host launch -----------------
extern "C" void kernel_launch(void* const* d_in, const int* in_sizes, int n_in,
                              void* d_out, int out_size) {
    const int N = N_NODES, E = N_EDGES;

    const float* x_seq = nullptr;
    const int* eidx = nullptr;
    const float* Wt[18];
    int wi = 0;
    for (int i = 0; i < n_in; i++) {
        if (in_sizes[i] == 2 * E) eidx = (const int*)d_in[i];
        else if (in_sizes[i] == T_STEPS * N * 64) x_seq = (const float*)d_in[i];
        else if (wi < 18) Wt[wi++] = (const float*)d_in[i];
    }
    const float *Wn0 = Wt[0], *Ws0 = Wt[1], *b0 = Wt[2], *g0 = Wt[3], *be0 = Wt[4];
    const float *Wn1 = Wt[5], *Ws1 = Wt[6], *b1 = Wt[7], *g1 = Wt[8], *be1 = Wt[9];
    const float *gWih = Wt[10], *gWhh = Wt[11], *gbih = Wt[12], *gbhh = Wt[13];
    const float *cW1 = Wt[14], *cb1 = Wt[15], *cW2 = Wt[16], *cb2 = Wt[17];

    __half *x16, *agg64a, *h016a, *agg128a, *h116a, *hA16, *hB16;
    __half *Wc0t16, *Wc1t16, *Wqt16, *cW1t16;
    float *hAf, *hBf, *zc, *bq;
    int *cnt, *rp, *cur, *ci;
    cudaGetSymbolAddress((void**)&x16, g_x16);
    cudaGetSymbolAddress((void**)&agg64a, g_agg64a);
    cudaGetSymbolAddress((void**)&h016a, g_h016a);
    cudaGetSymbolAddress((void**)&agg128a, g_agg128a);
    cudaGetSymbolAddress((void**)&h116a, g_h116a);
    cudaGetSymbolAddress((void**)&hA16, g_hA16);
    cudaGetSymbolAddress((void**)&hB16, g_hB16);
    cudaGetSymbolAddress((void**)&Wc0t16, g_Wc0t16);
    cudaGetSymbolAddress((void**)&Wc1t16, g_Wc1t16);
    cudaGetSymbolAddress((void**)&Wqt16, g_Wqt16);
    cudaGetSymbolAddress((void**)&cW1t16, g_cW1t16);
    cudaGetSymbolAddress((void**)&hAf, g_hAf);
    cudaGetSymbolAddress((void**)&hBf, g_hBf);
    cudaGetSymbolAddress((void**)&zc, g_zc);
    cudaGetSymbolAddress((void**)&bq, g_bq);
    cudaGetSymbolAddress((void**)&cnt, g_cnt);
    cudaGetSymbolAddress((void**)&rp, g_rowptr);
    cudaGetSymbolAddress((void**)&cur, g_cur);
    cudaGetSymbolAddress((void**)&ci, g_colidx);

    const int* src = eidx;
    const int* dst = eidx + E;

    const int SM_A = 55296;
    cudaFuncSetAttribute((const void*)k_wmma<64, 128, 2, 4, 0>, cudaFuncAttributeMaxDynamicSharedMemorySize, SM_A);
    cudaFuncSetAttribute((const void*)k_wmma<64, 128, 2, 4, 1>, cudaFuncAttributeMaxDynamicSharedMemorySize, SM_A);
    cudaFuncSetAttribute((const void*)k_wmma<64, 128, 2, 4, 2>, cudaFuncAttributeMaxDynamicSharedMemorySize, SM_A);
    cudaFuncSetAttribute((const void*)k_wmma<128, 64, 4, 2, 3>, cudaFuncAttributeMaxDynamicSharedMemorySize, SM_A);

    // ---- build CSR ----
    k_zero_i<<<(N + 255) / 256, 256>>>(cnt, N);
    k_hist<<<(E + 255) / 256, 256>>>(dst, E, cnt);
    k_scan<<<1, 1024>>>(cnt, rp, cur, N);
    k_fill<<<(E + 255) / 256, 256>>>(src, dst, E, cur, ci);
    k_sortseg<<<(N + 255) / 256, 256>>>(rp, ci, N);

    // ---- init GRU state + fp16 prep ----
    k_zero_f4<<<(N * 128 / 4 + 255) / 256, 256>>>((float4*)hAf, N * 128 / 4);
    k_zero_u4<<<(N * 128 / 8 + 255) / 256, 256>>>((uint4*)hA16, N * 128 / 8);
    k_cvt_x16<<<((T_STEPS * N * 64 / 4) + 255) / 256, 256>>>(
        (const float4*)x_seq, (uint2*)x16, T_STEPS * N * 64 / 4);
    k_prep_c0<<<(128 * 128 + 255) / 256, 256>>>(Wn0, Ws0, Wc0t16);
    k_prep_c1<<<(128 * 256 + 255) / 256, 256>>>(Wn1, Ws1, Wc1t16);
    k_prep_qt<<<(512 * 256 + 255) / 256, 256>>>(gWih, gWhh, gbih, gbhh, Wqt16, bq);
    k_prep_cls<<<(64 * 128 + 255) / 256, 256>>>(cW1, cW1t16);

    const int GRID64  = (N + 63) / 64;    // 1563
    const int GRID128 = (N + 127) / 128;  // 782
    const int AGG_GRID = (N + 7) / 8;     // 12500
    const size_t S64  = (size_t)N * 64;
    const size_t S128 = (size_t)N * 128;

    // ---- phase 1: all-t agg(x) + SAGE layer 0 ----
    k_agg64h<<<AGG_GRID * T_STEPS, 256>>>(x16, agg64a, rp, ci, N, AGG_GRID);
    k_wmma<64, 128, 2, 4, 0><<<dim3(GRID64 * T_STEPS, 1), 256, SM_A>>>(
        agg64a, 64, x16, 64, Wc0t16, 128, b0, g0, be0, nullptr, nullptr,
        nullptr, h016a, N, GRID64, S64, S64, 0, S128);

    // ---- phase 2: all-t agg(h0) + SAGE layer 1 (+residual h0) ----
    k_agg128h<<<AGG_GRID * T_STEPS, 256>>>(h016a, agg128a, rp, ci, N, AGG_GRID);
    k_wmma<64, 128, 2, 4, 1><<<dim3(GRID64 * T_STEPS, 1), 256, SM_A>>>(
        agg128a, 128, h016a, 128, Wc1t16, 256, b1, g1, be1, nullptr, h016a,
        nullptr, h116a, N, GRID64, S128, S128, S128, S128);

    // ---- phase 3: sequential GRU ----
    float* hprevf = hAf;
    float* hnextf = hBf;
    __half* hprev16 = hA16;
    __half* hnext16 = hB16;
    for (int t = 0; t < T_STEPS; t++) {
        const __half* h1t = h116a + (size_t)t * S128;
        k_wmma<64, 128, 2, 4, 2><<<dim3(GRID64, 4), 256, SM_A>>>(
            h1t, 128, hprev16, 128, Wqt16, 256, bq, nullptr, nullptr, hprevf, nullptr,
            hnextf, hnext16, N, GRID64, 0, 0, 0, 0);
        float* tf = hprevf; hprevf = hnextf; hnextf = tf;
        __half* th = hprev16; hprev16 = hnext16; hnext16 = th;
    }
    // classifier + logits
    k_wmma<128, 64, 4, 2, 3><<<dim3(GRID128, 1), 256, SM_A>>>(
        hprev16, 128, nullptr, 0, cW1t16, 128, cb1, nullptr, nullptr, nullptr, nullptr,
        zc, nullptr, N, GRID128, 0, 0, 0, 0);
    k_logits<<<AGG_GRID, 256>>>(zc, cW2, cb2, (float*)d_out, N);
}

// round 12
// speedup vs baseline: 2.6844x; 1.1029x over previous
#include <cuda_runtime.h>
#include <cuda_bf16.h>
#include <cuda_fp16.h>
#include <mma.h>
#include <cstdint>

using namespace nvcuda;

#define N_NODES 100000
#define N_EDGES 1600000
#define T_STEPS 12

// ----------------- static device scratch -----------------
__device__ uint4 g_x16      [(size_t)T_STEPS * N_NODES * 64 / 8];
__device__ uint4 g_agg64a   [(size_t)T_STEPS * N_NODES * 64 / 8];
__device__ uint4 g_h016a    [(size_t)T_STEPS * N_NODES * 128 / 8];
__device__ uint4 g_agg128a  [(size_t)T_STEPS * N_NODES * 128 / 8];
__device__ uint4 g_h116a    [(size_t)T_STEPS * N_NODES * 128 / 8];
__device__ uint4 g_hA16 [(size_t)N_NODES * 128 / 8];
__device__ uint4 g_hB16 [(size_t)N_NODES * 128 / 8];
__device__ uint4 g_Wc0t16[128 * 128 / 8];
__device__ uint4 g_Wc1t16[128 * 256 / 8];
__device__ uint4 g_Wqt16 [512 * 256 / 8];
__device__ uint4 g_cW1t16[64 * 128 / 8];
__device__ float g_hAf[(size_t)N_NODES * 128];
__device__ float g_hBf[(size_t)N_NODES * 128];
__device__ float g_zc [(size_t)N_NODES * 64];
__device__ float g_bq [512];
__device__ int   g_cnt   [N_NODES];
__device__ int   g_rowptr[N_NODES + 1];
__device__ int   g_cur   [N_NODES];
__device__ int   g_colidx[N_EDGES];

__device__ __forceinline__ float sigf(float x) { return 1.f / (1.f + expf(-x)); }

__device__ __forceinline__ uint2 pack4_f16(float a, float b, float c, float d) {
    __half2 lo = __floats2half2_rn(a, b);
    __half2 hi = __floats2half2_rn(c, d);
    uint2 u;
    u.x = *(uint32_t*)&lo;
    u.y = *(uint32_t*)&hi;
    return u;
}
__device__ __forceinline__ void unpack4_f16(uint2 u, float* o) {
    __half2 lo = *(__half2*)&u.x;
    __half2 hi = *(__half2*)&u.y;
    float2 a = __half22float2(lo);
    float2 b = __half22float2(hi);
    o[0] = a.x; o[1] = a.y; o[2] = b.x; o[3] = b.y;
}

// ----------------- cp.async helpers -----------------
__device__ __forceinline__ void cp16(uint32_t dst, const void* src) {
    asm volatile("cp.async.cg.shared.global [%0], [%1], 16;\n" :: "r"(dst), "l"(src));
}
__device__ __forceinline__ void cp_commit() {
    asm volatile("cp.async.commit_group;\n" ::: "memory");
}
template <int NG>
__device__ __forceinline__ void cp_wait() {
    asm volatile("cp.async.wait_group %0;\n" :: "n"(NG) : "memory");
}

// ----------------- wmma fp16 GEMM (fp32 accum), cp.async pipelined, time-batched ---------------
// BM=128 tiles, warp tile 32x64 (WR=4, WC=2, MI=2, NI=4). K in chunks of 64, ping-pong smem.
// 1D grid: bid = t * nRowTiles + rowTile.
// EPI 0: bias+LN+ReLU -> out16
// EPI 1: bias+LN+ReLU+res16 -> out16
// EPI 2: GRU gate-quad (grid.y=4; res fp32 h_prev) -> out fp32 + out16
// EPI 3: bias+ReLU -> out fp32 (stride 64), BN=64
template <int BM, int BN, int WR, int WC, int EPI>
__global__ void __launch_bounds__(256) k_wmma(
    const __half* __restrict__ A1, int K1,
    const __half* __restrict__ A2, int K2,
    const __half* __restrict__ Bt, int Ktot,
    const float* __restrict__ bias,
    const float* __restrict__ gamma, const float* __restrict__ beta,
    const float* __restrict__ res, const __half* __restrict__ res16,
    float* __restrict__ out, __half* __restrict__ out16, int n,
    int nRowTiles, size_t sA1, size_t sA2, size_t sRes16, size_t sOut16)
{
    constexpr int LDH = 72;
    constexpr int LDC = BN + 8;
    constexpr int ASZ = BM * LDH;   // halfs
    constexpr int BSZ = BN * LDH;
    constexpr int MI = BM / WR / 16;     // 2
    constexpr int NI = BN / WC / 16;     // 4 (BN=128) / 2 (BN=64)
    constexpr int AIT = BM * 8 / 256;    // 4
    constexpr int BIT = BN * 8 / 256;    // 4 / 2
    extern __shared__ __align__(256) char smem_raw[];
    __half* Hs = (__half*)smem_raw;
    float* Cs = (float*)smem_raw;
    uint32_t smem_u = (uint32_t)__cvta_generic_to_shared(smem_raw);

    const int tid = threadIdx.x;
    const int wid = tid >> 5;
    const int wr = wid / WC, wc = wid % WC;
    const int tt = blockIdx.x / nRowTiles;
    const int rt = blockIdx.x - tt * nRowTiles;
    const int row0 = rt * BM;
    const int jbase = blockIdx.y * BN;
    A1 += (size_t)tt * sA1;
    A2 += (size_t)tt * sA2;
    res16 += (size_t)tt * sRes16;
    out16 += (size_t)tt * sOut16;

    wmma::fragment<wmma::accumulator, 16, 16, 16, float> acc[MI][NI];
#pragma unroll
    for (int mi = 0; mi < MI; mi++)
#pragma unroll
        for (int ni = 0; ni < NI; ni++) wmma::fill_fragment(acc[mi][ni], 0.f);

    const int nc = Ktot / 64;

    auto stage = [&](int c, int s) {
        int kg = c * 64;
        const __half* Asrc; int Kph, koff;
        if (kg < K1) { Asrc = A1; Kph = K1; koff = kg; }
        else         { Asrc = A2; Kph = K2; koff = kg - K1; }
        uint32_t Asm = smem_u + (uint32_t)(s * ASZ) * 2;
        uint32_t Bsm = smem_u + (uint32_t)(2 * ASZ + s * BSZ) * 2;
#pragma unroll
        for (int it = 0; it < AIT; it++) {
            int idx = it * 256 + tid;
            int r = idx >> 3, q = idx & 7;
            int grow = row0 + r;
            if (grow > n - 1) grow = n - 1;   // clamped rows are never stored
            cp16(Asm + (uint32_t)(r * LDH + q * 8) * 2,
                 Asrc + (size_t)grow * Kph + koff + q * 8);
        }
#pragma unroll
        for (int it = 0; it < BIT; it++) {
            int idx = it * 256 + tid;
            int r = idx >> 3, q = idx & 7;
            cp16(Bsm + (uint32_t)(r * LDH + q * 8) * 2,
                 Bt + (size_t)(jbase + r) * Ktot + kg + q * 8);
        }
        cp_commit();
    };

    stage(0, 0);
    for (int c = 0; c < nc; c++) {
        int s = c & 1;
        if (c + 1 < nc) { stage(c + 1, s ^ 1); cp_wait<1>(); }
        else            { cp_wait<0>(); }
        __syncthreads();
        const __half* As = Hs + s * ASZ;
        const __half* Bs = Hs + 2 * ASZ + s * BSZ;
#pragma unroll
        for (int ks = 0; ks < 4; ks++) {
            wmma::fragment<wmma::matrix_a, 16, 16, 16, __half, wmma::row_major> af[MI];
            wmma::fragment<wmma::matrix_b, 16, 16, 16, __half, wmma::col_major> bf[NI];
#pragma unroll
            for (int mi = 0; mi < MI; mi++)
                wmma::load_matrix_sync(af[mi], As + (wr * (BM / WR) + mi * 16) * LDH + ks * 16, LDH);
#pragma unroll
            for (int ni = 0; ni < NI; ni++)
                wmma::load_matrix_sync(bf[ni], Bs + (wc * (BN / WC) + ni * 16) * LDH + ks * 16, LDH);
#pragma unroll
            for (int mi = 0; mi < MI; mi++)
#pragma unroll
                for (int ni = 0; ni < NI; ni++)
                    wmma::mma_sync(acc[mi][ni], af[mi], bf[ni], acc[mi][ni]);
        }
        __syncthreads();
    }

#pragma unroll
    for (int mi = 0; mi < MI; mi++)
#pragma unroll
        for (int ni = 0; ni < NI; ni++)
            wmma::store_matrix_sync(Cs + (wr * (BM / WR) + mi * 16) * LDC + wc * (BN / WC) + ni * 16,
                                    acc[mi][ni], LDC, wmma::mem_row_major);
    __syncthreads();

    // ------------- epilogues -------------
    if constexpr (EPI == 0 || EPI == 1) {
        constexpr int TPR = 256 / BM;      // 2
        constexpr int CP = BN / TPR;       // 64
        int r = tid / TPR, seg = tid % TPR;
        int grow = row0 + r;
        float sum = 0.f, sq = 0.f;
#pragma unroll
        for (int q = 0; q < CP / 4; q++) {
            int cc = seg * CP + q * 4;
            float4 c4 = *(float4*)&Cs[r * LDC + cc];
            c4.x += __ldg(&bias[cc + 0]); c4.y += __ldg(&bias[cc + 1]);
            c4.z += __ldg(&bias[cc + 2]); c4.w += __ldg(&bias[cc + 3]);
            sum += (c4.x + c4.y) + (c4.z + c4.w);
            sq += c4.x * c4.x + c4.y * c4.y + c4.z * c4.z + c4.w * c4.w;
        }
#pragma unroll
        for (int o = 1; o < TPR; o <<= 1) {
            sum += __shfl_xor_sync(0xffffffffu, sum, o);
            sq  += __shfl_xor_sync(0xffffffffu, sq, o);
        }
        float mean = sum * (1.f / 128.f);
        float var = sq * (1.f / 128.f) - mean * mean;
        float rs = rsqrtf(var + 1e-5f);
        if (grow < n) {
#pragma unroll
            for (int q = 0; q < CP / 4; q++) {
                int cc = seg * CP + q * 4;
                float4 c4 = *(float4*)&Cs[r * LDC + cc];
                float4 o;
                o.x = fmaxf((c4.x + __ldg(&bias[cc + 0]) - mean) * rs * __ldg(&gamma[cc + 0]) + __ldg(&beta[cc + 0]), 0.f);
                o.y = fmaxf((c4.y + __ldg(&bias[cc + 1]) - mean) * rs * __ldg(&gamma[cc + 1]) + __ldg(&beta[cc + 1]), 0.f);
                o.z = fmaxf((c4.z + __ldg(&bias[cc + 2]) - mean) * rs * __ldg(&gamma[cc + 2]) + __ldg(&beta[cc + 2]), 0.f);
                o.w = fmaxf((c4.w + __ldg(&bias[cc + 3]) - mean) * rs * __ldg(&gamma[cc + 3]) + __ldg(&beta[cc + 3]), 0.f);
                if (EPI == 1) {
                    uint2 r16 = *(const uint2*)(res16 + (size_t)grow * 128 + cc);
                    float rv[4];
                    unpack4_f16(r16, rv);
                    o.x += rv[0]; o.y += rv[1]; o.z += rv[2]; o.w += rv[3];
                }
                *(uint2*)(out16 + (size_t)grow * 128 + cc) = pack4_f16(o.x, o.y, o.z, o.w);
            }
        }
    } else if constexpr (EPI == 2) {
        constexpr int TPR = 256 / BM;      // 2
        int r = tid / TPR, seg = tid % TPR;
        int grow = row0 + r;
        if (grow < n) {
            int lc0 = seg * (BN / TPR);    // 0 or 64
#pragma unroll
            for (int g4 = 0; g4 < (BN / TPR) / 16; g4++) {   // 4 groups of 4 quads
                int j0 = (jbase >> 2) + seg * 16 + g4 * 4;
                float4 hp = *(const float4*)(res + (size_t)grow * 128 + j0);
                float hpv[4] = {hp.x, hp.y, hp.z, hp.w};
                float hv[4];
#pragma unroll
                for (int q = 0; q < 4; q++) {
                    int lc = lc0 + (g4 * 4 + q) * 4;
                    int gcol = jbase + lc;
                    float cr = Cs[r * LDC + lc + 0] + __ldg(&bias[gcol + 0]);
                    float cz = Cs[r * LDC + lc + 1] + __ldg(&bias[gcol + 1]);
                    float ci = Cs[r * LDC + lc + 2] + __ldg(&bias[gcol + 2]);
                    float ch = Cs[r * LDC + lc + 3] + __ldg(&bias[gcol + 3]);
                    float rg = sigf(cr);
                    float z = sigf(cz);
                    float ng = tanhf(ci + rg * ch);
                    hv[q] = (1.f - z) * ng + z * hpv[q];
                }
                *(float4*)(out + (size_t)grow * 128 + j0) = make_float4(hv[0], hv[1], hv[2], hv[3]);
                *(uint2*)(out16 + (size_t)grow * 128 + j0) = pack4_f16(hv[0], hv[1], hv[2], hv[3]);
            }
        }
    } else {  // EPI == 3: bias+relu, BN=64, out stride 64 (fp32)
        int r = tid >> 1, seg = tid & 1;
        int grow = row0 + r;
        if (grow < n) {
#pragma unroll
            for (int q = 0; q < 8; q++) {
                int cc = seg * 32 + q * 4;
                float4 c4 = *(float4*)&Cs[r * LDC + cc];
                float4 o;
                o.x = fmaxf(c4.x + __ldg(&bias[cc + 0]), 0.f);
                o.y = fmaxf(c4.y + __ldg(&bias[cc + 1]), 0.f);
                o.z = fmaxf(c4.z + __ldg(&bias[cc + 2]), 0.f);
                o.w = fmaxf(c4.w + __ldg(&bias[cc + 3]), 0.f);
                *(float4*)(out + (size_t)grow * 64 + cc) = o;
            }
        }
    }
}

// ----------------- CSR build + misc -----------------
__global__ void k_zero_f4(float4* p, int c4) {
    int i = blockIdx.x * blockDim.x + threadIdx.x;
    if (i < c4) p[i] = make_float4(0.f, 0.f, 0.f, 0.f);
}
__global__ void k_zero_u4(uint4* p, int c4) {
    int i = blockIdx.x * blockDim.x + threadIdx.x;
    if (i < c4) p[i] = make_uint4(0u, 0u, 0u, 0u);
}
__global__ void k_zero_i(int* p, int c) {
    int i = blockIdx.x * blockDim.x + threadIdx.x;
    if (i < c) p[i] = 0;
}
__global__ void k_hist(const int* __restrict__ dst, int e, int* __restrict__ cnt) {
    int i = blockIdx.x * blockDim.x + threadIdx.x;
    if (i < e) atomicAdd(&cnt[dst[i]], 1);
}
__global__ void k_fill(const int* __restrict__ src, const int* __restrict__ dst, int e,
                       int* __restrict__ cur, int* __restrict__ colidx) {
    int i = blockIdx.x * blockDim.x + threadIdx.x;
    if (i < e) {
        int p = atomicAdd(&cur[dst[i]], 1);
        colidx[p] = src[i];
    }
}
__global__ void k_sortseg(const int* __restrict__ rp, int* __restrict__ ci, int n) {
    int v = blockIdx.x * blockDim.x + threadIdx.x;
    if (v >= n) return;
    int s = rp[v], e = rp[v + 1];
    for (int i = s + 1; i < e; i++) {
        int key = ci[i];
        int j = i - 1;
        while (j >= s && ci[j] > key) { ci[j + 1] = ci[j]; j--; }
        ci[j + 1] = key;
    }
}
__global__ void k_scan(const int* __restrict__ cnt, int* __restrict__ rowptr,
                       int* __restrict__ cur, int n) {
    __shared__ int wsums[32];
    __shared__ int s_carry;
    int tid = threadIdx.x;
    int lane = tid & 31, wid = tid >> 5;
    if (tid == 0) s_carry = 0;
    __syncthreads();
    for (int base = 0; base < n; base += 1024) {
        int i = base + tid;
        int v = (i < n) ? cnt[i] : 0;
        int x = v;
#pragma unroll
        for (int o = 1; o < 32; o <<= 1) {
            int t = __shfl_up_sync(0xffffffffu, x, o);
            if (lane >= o) x += t;
        }
        if (lane == 31) wsums[wid] = x;
        __syncthreads();
        if (tid < 32) {
            int s = wsums[tid];
#pragma unroll
            for (int o = 1; o < 32; o <<= 1) {
                int t = __shfl_up_sync(0xffffffffu, s, o);
                if (tid >= o) s += t;
            }
            wsums[tid] = s;
        }
        __syncthreads();
        int incl = x + ((wid > 0) ? wsums[wid - 1] : 0);
        int excl = s_carry + incl - v;
        if (i < n) { rowptr[i] = excl; cur[i] = excl; }
        int blocktot = wsums[31];
        __syncthreads();
        if (tid == 0) s_carry += blocktot;
        __syncthreads();
    }
    if (tid == 0) rowptr[n] = s_carry;
}

// ----------------- weight / input prep -----------------
__global__ void k_cvt_x16(const float4* __restrict__ in, uint2* __restrict__ out, int c4) {
    int i = blockIdx.x * blockDim.x + threadIdx.x;
    if (i >= c4) return;
    float4 v = in[i];
    out[i] = pack4_f16(v.x, v.y, v.z, v.w);
}
__global__ void k_prep_c0(const float* __restrict__ Wn, const float* __restrict__ Ws,
                          __half* __restrict__ o) {
    int idx = blockIdx.x * blockDim.x + threadIdx.x;
    if (idx >= 128 * 128) return;
    int nn = idx >> 7, k = idx & 127;
    float w = (k < 64) ? Wn[k * 128 + nn] : Ws[(k - 64) * 128 + nn];
    o[idx] = __float2half_rn(w);
}
__global__ void k_prep_c1(const float* __restrict__ Wn, const float* __restrict__ Ws,
                          __half* __restrict__ o) {
    int idx = blockIdx.x * blockDim.x + threadIdx.x;
    if (idx >= 128 * 256) return;
    int nn = idx >> 8, k = idx & 255;
    float w = (k < 128) ? Wn[k * 128 + nn] : Ws[(k - 128) * 128 + nn];
    o[idx] = __float2half_rn(w);
}
__global__ void k_prep_qt(const float* __restrict__ Wih, const float* __restrict__ Whh,
                          const float* __restrict__ bih, const float* __restrict__ bhh,
                          __half* __restrict__ o, float* __restrict__ bq) {
    int idx = blockIdx.x * blockDim.x + threadIdx.x;
    if (idx >= 512 * 256) return;
    int c = idx >> 8, k = idx & 255;
    int j = c >> 2, g = c & 3;
    float w = 0.f;
    if (k < 128) {
        if (g == 0)      w = Wih[j * 128 + k];
        else if (g == 1) w = Wih[(128 + j) * 128 + k];
        else if (g == 2) w = Wih[(256 + j) * 128 + k];
    } else {
        int kk = k - 128;
        if (g == 0)      w = Whh[j * 128 + kk];
        else if (g == 1) w = Whh[(128 + j) * 128 + kk];
        else if (g == 3) w = Whh[(256 + j) * 128 + kk];
    }
    o[idx] = __float2half_rn(w);
    if (idx < 512) {
        int jj = idx >> 2, gg = idx & 3;
        bq[idx] = (gg == 0) ? bih[jj] + bhh[jj]
                : (gg == 1) ? bih[128 + jj] + bhh[128 + jj]
                : (gg == 2) ? bih[256 + jj]
                            : bhh[256 + jj];
    }
}
__global__ void k_prep_cls(const float* __restrict__ W, __half* __restrict__ o) {
    int idx = blockIdx.x * blockDim.x + threadIdx.x;
    if (idx >= 64 * 128) return;
    int oo = idx >> 7, k = idx & 127;
    o[idx] = __float2half_rn(W[k * 64 + oo]);
}

// ----------------- mean aggregation (warp/node, fp16 gather, fp32 accum, time-batched) ---------
__global__ void __launch_bounds__(256) k_agg64h(const __half* __restrict__ x, __half* __restrict__ out,
                                                const int* __restrict__ rp, const int* __restrict__ ci,
                                                int n, int blocksPerT) {
    int tt = blockIdx.x / blocksPerT;
    int lb = blockIdx.x - tt * blocksPerT;
    int w = (lb * 256 + threadIdx.x) >> 5;
    if (w >= n) return;
    x += (size_t)tt * n * 64;
    out += (size_t)tt * n * 64;
    int lane = threadIdx.x & 31;
    int s0 = rp[w], s1 = rp[w + 1];
    float ax = 0.f, ay = 0.f;
    int e = s0;
    for (; e + 4 <= s1; e += 4) {
        int i0 = ci[e], i1 = ci[e + 1], i2 = ci[e + 2], i3 = ci[e + 3];
        float2 v0 = __half22float2(*(const __half2*)(x + (size_t)i0 * 64 + lane * 2));
        float2 v1 = __half22float2(*(const __half2*)(x + (size_t)i1 * 64 + lane * 2));
        float2 v2 = __half22float2(*(const __half2*)(x + (size_t)i2 * 64 + lane * 2));
        float2 v3 = __half22float2(*(const __half2*)(x + (size_t)i3 * 64 + lane * 2));
        ax += (v0.x + v1.x) + (v2.x + v3.x);
        ay += (v0.y + v1.y) + (v2.y + v3.y);
    }
    for (; e < s1; e++) {
        int i0 = ci[e];
        float2 v0 = __half22float2(*(const __half2*)(x + (size_t)i0 * 64 + lane * 2));
        ax += v0.x; ay += v0.y;
    }
    int d = s1 - s0; if (d < 1) d = 1;
    float inv = 1.f / (float)d;
    *(__half2*)(out + (size_t)w * 64 + lane * 2) = __floats2half2_rn(ax * inv, ay * inv);
}
__global__ void __launch_bounds__(256) k_agg128h(const __half* __restrict__ x, __half* __restrict__ out,
                                                 const int* __restrict__ rp, const int* __restrict__ ci,
                                                 int n, int blocksPerT) {
    int tt = blockIdx.x / blocksPerT;
    int lb = blockIdx.x - tt * blocksPerT;
    int w = (lb * 256 + threadIdx.x) >> 5;
    if (w >= n) return;
    x += (size_t)tt * n * 128;
    out += (size_t)tt * n * 128;
    int lane = threadIdx.x & 31;
    int s0 = rp[w], s1 = rp[w + 1];
    float a0 = 0.f, a1 = 0.f, a2 = 0.f, a3 = 0.f;
    int e = s0;
    for (; e + 4 <= s1; e += 4) {
        int i0 = ci[e], i1 = ci[e + 1], i2 = ci[e + 2], i3 = ci[e + 3];
        float v[4][4];
        unpack4_f16(*(const uint2*)(x + (size_t)i0 * 128 + lane * 4), v[0]);
        unpack4_f16(*(const uint2*)(x + (size_t)i1 * 128 + lane * 4), v[1]);
        unpack4_f16(*(const uint2*)(x + (size_t)i2 * 128 + lane * 4), v[2]);
        unpack4_f16(*(const uint2*)(x + (size_t)i3 * 128 + lane * 4), v[3]);
        a0 += (v[0][0] + v[1][0]) + (v[2][0] + v[3][0]);
        a1 += (v[0][1] + v[1][1]) + (v[2][1] + v[3][1]);
        a2 += (v[0][2] + v[1][2]) + (v[2][2] + v[3][2]);
        a3 += (v[0][3] + v[1][3]) + (v[2][3] + v[3][3]);
    }
    for (; e < s1; e++) {
        int i0 = ci[e];
        float v[4];
        unpack4_f16(*(const uint2*)(x + (size_t)i0 * 128 + lane * 4), v);
        a0 += v[0]; a1 += v[1]; a2 += v[2]; a3 += v[3];
    }
    int d = s1 - s0; if (d < 1) d = 1;
    float inv = 1.f / (float)d;
    *(uint2*)(out + (size_t)w * 128 + lane * 4) =
        pack4_f16(a0 * inv, a1 * inv, a2 * inv, a3 * inv);
}

// final logits
__global__ void __launch_bounds__(256) k_logits(const float* __restrict__ zc,
                                                const float* __restrict__ W2,
                                                const float* __restrict__ b2,
                                                float* __restrict__ out, int n) {
    int w = (blockIdx.x * blockDim.x + threadIdx.x) >> 5;
    if (w >= n) return;
    int lane = threadIdx.x & 31;
    float z0 = zc[(size_t)w * 64 + lane];
    float z1 = zc[(size_t)w * 64 + 32 + lane];
    float a0 = z0 * W2[lane * 2 + 0] + z1 * W2[(lane + 32) * 2 + 0];
    float a1 = z0 * W2[lane * 2 + 1] + z1 * W2[(lane + 32) * 2 + 1];
#pragma unroll
    for (int o = 16; o > 0; o >>= 1) {
        a0 += __shfl_xor_sync(0xffffffffu, a0, o);
        a1 += __shfl_xor_sync(0xffffffffu, a1, o);
    }
    if (lane == 0) {
        out[(size_t)w * 2 + 0] = a0 + b2[0];
        out[(size_t)w * 2 + 1] = a1 + b2[1];
    }
}

// ----------------- host launch -----------------
extern "C" void kernel_launch(void* const* d_in, const int* in_sizes, int n_in,
                              void* d_out, int out_size) {
    const int N = N_NODES, E = N_EDGES;

    const float* x_seq = nullptr;
    const int* eidx = nullptr;
    const float* Wt[18];
    int wi = 0;
    for (int i = 0; i < n_in; i++) {
        if (in_sizes[i] == 2 * E) eidx = (const int*)d_in[i];
        else if (in_sizes[i] == T_STEPS * N * 64) x_seq = (const float*)d_in[i];
        else if (wi < 18) Wt[wi++] = (const float*)d_in[i];
    }
    const float *Wn0 = Wt[0], *Ws0 = Wt[1], *b0 = Wt[2], *g0 = Wt[3], *be0 = Wt[4];
    const float *Wn1 = Wt[5], *Ws1 = Wt[6], *b1 = Wt[7], *g1 = Wt[8], *be1 = Wt[9];
    const float *gWih = Wt[10], *gWhh = Wt[11], *gbih = Wt[12], *gbhh = Wt[13];
    const float *cW1 = Wt[14], *cb1 = Wt[15], *cW2 = Wt[16], *cb2 = Wt[17];

    __half *x16, *agg64a, *h016a, *agg128a, *h116a, *hA16, *hB16;
    __half *Wc0t16, *Wc1t16, *Wqt16, *cW1t16;
    float *hAf, *hBf, *zc, *bq;
    int *cnt, *rp, *cur, *ci;
    cudaGetSymbolAddress((void**)&x16, g_x16);
    cudaGetSymbolAddress((void**)&agg64a, g_agg64a);
    cudaGetSymbolAddress((void**)&h016a, g_h016a);
    cudaGetSymbolAddress((void**)&agg128a, g_agg128a);
    cudaGetSymbolAddress((void**)&h116a, g_h116a);
    cudaGetSymbolAddress((void**)&hA16, g_hA16);
    cudaGetSymbolAddress((void**)&hB16, g_hB16);
    cudaGetSymbolAddress((void**)&Wc0t16, g_Wc0t16);
    cudaGetSymbolAddress((void**)&Wc1t16, g_Wc1t16);
    cudaGetSymbolAddress((void**)&Wqt16, g_Wqt16);
    cudaGetSymbolAddress((void**)&cW1t16, g_cW1t16);
    cudaGetSymbolAddress((void**)&hAf, g_hAf);
    cudaGetSymbolAddress((void**)&hBf, g_hBf);
    cudaGetSymbolAddress((void**)&zc, g_zc);
    cudaGetSymbolAddress((void**)&bq, g_bq);
    cudaGetSymbolAddress((void**)&cnt, g_cnt);
    cudaGetSymbolAddress((void**)&rp, g_rowptr);
    cudaGetSymbolAddress((void**)&cur, g_cur);
    cudaGetSymbolAddress((void**)&ci, g_colidx);

    const int* src = eidx;
    const int* dst = eidx + E;

    // smem: stage 2*(128+128)*72*2 = 73728 B ; C tile 128*136*4 = 69632 B
    const int SM_A = 73728;
    cudaFuncSetAttribute((const void*)k_wmma<128, 128, 4, 2, 0>, cudaFuncAttributeMaxDynamicSharedMemorySize, SM_A);
    cudaFuncSetAttribute((const void*)k_wmma<128, 128, 4, 2, 1>, cudaFuncAttributeMaxDynamicSharedMemorySize, SM_A);
    cudaFuncSetAttribute((const void*)k_wmma<128, 128, 4, 2, 2>, cudaFuncAttributeMaxDynamicSharedMemorySize, SM_A);
    cudaFuncSetAttribute((const void*)k_wmma<128, 64, 4, 2, 3>,  cudaFuncAttributeMaxDynamicSharedMemorySize, SM_A);

    // ---- build CSR ----
    k_zero_i<<<(N + 255) / 256, 256>>>(cnt, N);
    k_hist<<<(E + 255) / 256, 256>>>(dst, E, cnt);
    k_scan<<<1, 1024>>>(cnt, rp, cur, N);
    k_fill<<<(E + 255) / 256, 256>>>(src, dst, E, cur, ci);
    k_sortseg<<<(N + 255) / 256, 256>>>(rp, ci, N);

    // ---- init GRU state + fp16 prep ----
    k_zero_f4<<<(N * 128 / 4 + 255) / 256, 256>>>((float4*)hAf, N * 128 / 4);
    k_zero_u4<<<(N * 128 / 8 + 255) / 256, 256>>>((uint4*)hA16, N * 128 / 8);
    k_cvt_x16<<<((T_STEPS * N * 64 / 4) + 255) / 256, 256>>>(
        (const float4*)x_seq, (uint2*)x16, T_STEPS * N * 64 / 4);
    k_prep_c0<<<(128 * 128 + 255) / 256, 256>>>(Wn0, Ws0, Wc0t16);
    k_prep_c1<<<(128 * 256 + 255) / 256, 256>>>(Wn1, Ws1, Wc1t16);
    k_prep_qt<<<(512 * 256 + 255) / 256, 256>>>(gWih, gWhh, gbih, gbhh, Wqt16, bq);
    k_prep_cls<<<(64 * 128 + 255) / 256, 256>>>(cW1, cW1t16);

    const int GRID = (N + 127) / 128;     // 782
    const int AGG_GRID = (N + 7) / 8;     // 12500
    const size_t S64  = (size_t)N * 64;
    const size_t S128 = (size_t)N * 128;

    // ---- phase 1: all-t agg(x) + SAGE layer 0 ----
    k_agg64h<<<AGG_GRID * T_STEPS, 256>>>(x16, agg64a, rp, ci, N, AGG_GRID);
    k_wmma<128, 128, 4, 2, 0><<<dim3(GRID * T_STEPS, 1), 256, SM_A>>>(
        agg64a, 64, x16, 64, Wc0t16, 128, b0, g0, be0, nullptr, nullptr,
        nullptr, h016a, N, GRID, S64, S64, 0, S128);

    // ---- phase 2: all-t agg(h0) + SAGE layer 1 (+residual h0) ----
    k_agg128h<<<AGG_GRID * T_STEPS, 256>>>(h016a, agg128a, rp, ci, N, AGG_GRID);
    k_wmma<128, 128, 4, 2, 1><<<dim3(GRID * T_STEPS, 1), 256, SM_A>>>(
        agg128a, 128, h016a, 128, Wc1t16, 256, b1, g1, be1, nullptr, h016a,
        nullptr, h116a, N, GRID, S128, S128, S128, S128);

    // ---- phase 3: sequential GRU ----
    float* hprevf = hAf;
    float* hnextf = hBf;
    __half* hprev16 = hA16;
    __half* hnext16 = hB16;
    for (int t = 0; t < T_STEPS; t++) {
        const __half* h1t = h116a + (size_t)t * S128;
        k_wmma<128, 128, 4, 2, 2><<<dim3(GRID, 4), 256, SM_A>>>(
            h1t, 128, hprev16, 128, Wqt16, 256, bq, nullptr, nullptr, hprevf, nullptr,
            hnextf, hnext16, N, GRID, 0, 0, 0, 0);
        float* tf = hprevf; hprevf = hnextf; hnextf = tf;
        __half* th = hprev16; hprev16 = hnext16; hnext16 = th;
    }
    // classifier + logits
    k_wmma<128, 64, 4, 2, 3><<<dim3(GRID, 1), 256, SM_A>>>(
        hprev16, 128, nullptr, 0, cW1t16, 128, cb1, nullptr, nullptr, nullptr, nullptr,
        zc, nullptr, N, GRID, 0, 0, 0, 0);
    k_logits<<<AGG_GRID, 256>>>(zc, cW2, cb2, (float*)d_out, N);
}